// round 4
// baseline (speedup 1.0000x reference)
#include <cuda_runtime.h>
#include <cstdint>

#define NC 200000
#define NCOMP 3
#define NN (NC*NCOMP)
#define EC 400000
#define EE (EC*NCOMP)
#define HD 96
#define NB 4096
#define SCAN_BLK 1024
#define NPART ((NN + SCAN_BLK - 1)/SCAN_BLK)

// ---------------- device scratch (static, no runtime allocation) ----------
__device__ __align__(16) float g_h[(size_t)NN*HD];
__device__ __align__(16) float g_s[(size_t)NN*HD];
__device__ int   g_deg[NN];
__device__ int   g_fill[NN];
__device__ int   g_off[NN+1];
__device__ int   g_esrc[EE];
__device__ int   g_part[SCAN_BLK];
__device__ __align__(16) float g_Wpack[18*192*384];   // [cl][k][j]
__device__ __align__(16) float g_bias[18*384];        // [cl][ brz(192) | bin(96) | bnh(96) ]
__device__ __align__(16) float g_pool[NCOMP*NB*HD];
__device__ __align__(16) float g_feat[(size_t)NB*384];
__device__ __align__(16) float g_t1[(size_t)NB*1536];
__device__ __align__(16) float g_t2[(size_t)NB*384];

// ---------------- f32x2 helpers -------------------------------------------
__device__ __forceinline__ unsigned long long dup2(float x){
    unsigned int u = __float_as_uint(x);
    unsigned long long r;
    asm("mov.b64 %0, {%1, %1};" : "=l"(r) : "r"(u));
    return r;
}
__device__ __forceinline__ unsigned long long ffma2(unsigned long long a,
                                                    unsigned long long b,
                                                    unsigned long long c){
    unsigned long long d;
    asm("fma.rn.f32x2 %0, %1, %2, %3;" : "=l"(d) : "l"(a), "l"(b), "l"(c));
    return d;
}
__device__ __forceinline__ float2 unpack2(unsigned long long v){
    unsigned int lo, hi;
    asm("mov.b64 {%0, %1}, %2;" : "=r"(lo), "=r"(hi) : "l"(v));
    float2 f; f.x = __uint_as_float(lo); f.y = __uint_as_float(hi); return f;
}
__device__ __forceinline__ float sigf(float x){ return 1.f/(1.f + expf(-x)); }

// ---------------- init: h0 = pad(x), zero counters --------------------------
__global__ void k_init(const float* __restrict__ x1, const float* __restrict__ x2,
                       const float* __restrict__ x3){
    long long idx = (long long)blockIdx.x*blockDim.x + threadIdx.x;
    if (idx < (long long)NN*HD){
        int n = (int)(idx / HD);
        int j = (int)(idx - (long long)n*HD);
        int c = n / NC;
        int ln = n - c*NC;
        const float* x = (c==0)?x1:((c==1)?x2:x3);
        g_h[idx] = (j < 32) ? x[(size_t)ln*32 + j] : 0.f;
    }
    if (idx < NN){ g_deg[idx] = 0; g_fill[idx] = 0; }
}

// ---------------- CSR build -------------------------------------------------
__global__ void k_deg(const int* __restrict__ e1, const int* __restrict__ e2,
                      const int* __restrict__ e3){
    int e = blockIdx.x*blockDim.x + threadIdx.x;
    if (e >= EE) return;
    int c = e / EC, le = e - c*EC;
    const int* ei = (c==0)?e1:((c==1)?e2:e3);
    int dst = ei[EC + le];
    atomicAdd(&g_deg[c*NC + dst], 1);
}

__global__ void k_scan1(){
    __shared__ int sm[SCAN_BLK];
    int tid = threadIdx.x;
    int i = blockIdx.x*SCAN_BLK + tid;
    int v = (i < NN) ? g_deg[i] : 0;
    sm[tid] = v;
    __syncthreads();
    for (int off = 1; off < SCAN_BLK; off <<= 1){
        int t = 0;
        if (tid >= off) t = sm[tid - off];
        __syncthreads();
        sm[tid] += t;
        __syncthreads();
    }
    if (i < NN) g_off[i] = sm[tid] - v;          // block-local exclusive
    if (tid == SCAN_BLK-1) g_part[blockIdx.x] = sm[tid];
}

__global__ void k_scan2(){
    __shared__ int sm[SCAN_BLK];
    int tid = threadIdx.x;
    int v = (tid < NPART) ? g_part[tid] : 0;
    sm[tid] = v;
    __syncthreads();
    for (int off = 1; off < SCAN_BLK; off <<= 1){
        int t = 0;
        if (tid >= off) t = sm[tid - off];
        __syncthreads();
        sm[tid] += t;
        __syncthreads();
    }
    if (tid < NPART) g_part[tid] = sm[tid] - v;  // exclusive block bases
}

__global__ void k_scan3(){
    int tid = threadIdx.x;
    int i = blockIdx.x*SCAN_BLK + tid;
    if (i < NN) g_off[i] += g_part[blockIdx.x];
    if (blockIdx.x == 0 && tid == 0) g_off[NN] = EE;
}

__global__ void k_fill(const int* __restrict__ e1, const int* __restrict__ e2,
                       const int* __restrict__ e3){
    int e = blockIdx.x*blockDim.x + threadIdx.x;
    if (e >= EE) return;
    int c = e / EC, le = e - c*EC;
    const int* ei = (c==0)?e1:((c==1)?e2:e3);
    int dst = ei[EC + le];
    int src = ei[le];
    int dg = c*NC + dst;
    int p = g_off[dg] + atomicAdd(&g_fill[dg], 1);
    g_esrc[p] = c*NC + src;
}

// ---------------- weight packing --------------------------------------------
// Wpack[cl][k][j], k in [0,192), j in [0,384):
//  k<96  (S part):   j<288 -> (W_l @ wih^T)[k][j]  ; j>=288 -> 0
//  k>=96 (h part):   j<192 -> whh[j][k-96] ; 192<=j<288 -> 0 ; j>=288 -> whh[j-96][k-96]
__global__ void k_pack(
    const float* __restrict__ W1, const float* __restrict__ wih1, const float* __restrict__ whh1,
    const float* __restrict__ W2, const float* __restrict__ wih2, const float* __restrict__ whh2,
    const float* __restrict__ W3, const float* __restrict__ wih3, const float* __restrict__ whh3)
{
    int cl = blockIdx.y;
    int c = cl / 6, l = cl % 6;
    const float* W   = (c==0)?W1:((c==1)?W2:W3);
    const float* wih = (c==0)?wih1:((c==1)?wih2:wih3);
    const float* whh = (c==0)?whh1:((c==1)?whh2:whh3);
    int id = blockIdx.x*blockDim.x + threadIdx.x;
    if (id >= 192*384) return;
    int k = id / 384, j = id % 384;
    float v = 0.f;
    if (k < 96){
        if (j < 288){
            const float* wr = W + (size_t)(l*96 + k)*96;
            const float* ir = wih + (size_t)j*96;
            float s = 0.f;
            #pragma unroll 8
            for (int t = 0; t < 96; t++) s += wr[t]*ir[t];
            v = s;
        }
    } else {
        int t = k - 96;
        if (j < 192)       v = whh[(size_t)j*96 + t];
        else if (j >= 288) v = whh[(size_t)(j-96)*96 + t];  // 192 + (j-288)
    }
    g_Wpack[(size_t)cl*192*384 + id] = v;
}

__global__ void k_packbias(
    const float* __restrict__ bih1, const float* __restrict__ bhh1,
    const float* __restrict__ bih2, const float* __restrict__ bhh2,
    const float* __restrict__ bih3, const float* __restrict__ bhh3)
{
    int cl = blockIdx.x;
    int c = cl / 6;
    const float* bih = (c==0)?bih1:((c==1)?bih2:bih3);
    const float* bhh = (c==0)?bhh1:((c==1)?bhh2:bhh3);
    int j = threadIdx.x;   // 0..383
    float v;
    if (j < 192)      v = bih[j] + bhh[j];
    else if (j < 288) v = bih[192 + (j-192)];
    else              v = bhh[192 + (j-288)];
    g_bias[cl*384 + j] = v;
}

// ---------------- per-layer aggregation: S[dst] = sum_{src} h[src] ----------
__global__ void k_scatter(){
    int gt = blockIdx.x*blockDim.x + threadIdx.x;
    int node = gt >> 5;
    int lane = gt & 31;
    if (node >= NN) return;
    int o0 = g_off[node], o1 = g_off[node+1];
    float a0 = 0.f, a1 = 0.f, a2 = 0.f;
    for (int e = o0; e < o1; e++){
        int s = __ldg(&g_esrc[e]);
        const float* hp = g_h + (size_t)s*HD;
        a0 += hp[lane];
        a1 += hp[lane+32];
        a2 += hp[lane+64];
    }
    float* sp = g_s + (size_t)node*HD;
    sp[lane]    = a0;
    sp[lane+32] = a1;
    sp[lane+64] = a2;
}

// ---------------- fused GRU layer -------------------------------------------
#define AS_STRIDE 33
#define AS_FLOATS (192*AS_STRIDE)   // 6336
#define BS_FLOATS (32*384)          // 12288 (also reused as Gbuf 32x384)
__global__ void __launch_bounds__(256, 2) k_gru(int layer){
    extern __shared__ float smf[];
    float* As = smf;                       // A_t[k][r], pad 33
    float* Bs = smf + AS_FLOATS;           // weight chunk / gate buffer
    float* sb = smf + AS_FLOATS + BS_FLOATS; // 384 biases

    const int comp = blockIdx.y;
    const int cl = comp*6 + layer;
    const int row0 = blockIdx.x*32;
    const int nodeBase = comp*NC + row0;
    const int tid = threadIdx.x;
    const int tx = tid & 31;
    const int ty = tid >> 5;          // 0..7
    const int r0 = ty*4;

    // biases to smem
    for (int i = tid; i < 384; i += 256) sb[i] = g_bias[cl*384 + i];

    // A tile (transposed): As[k*33 + r]
    for (int idx = tid; idx < 32*192; idx += 256){
        int r = idx / 192;
        int k = idx - r*192;
        size_t node = (size_t)(nodeBase + r);
        float v = (k < 96) ? g_s[node*HD + k] : g_h[node*HD + (k-96)];
        As[k*AS_STRIDE + r] = v;
    }

    unsigned long long acc[6][4];
    #pragma unroll
    for (int g = 0; g < 6; g++)
        #pragma unroll
        for (int i = 0; i < 4; i++) acc[g][i] = 0ull;

    const float* wbase = g_Wpack + (size_t)cl*192*384;
    const int jb = 2*tx;

    for (int chunk = 0; chunk < 6; chunk++){
        __syncthreads();
        const float4* src = (const float4*)(wbase + (size_t)chunk*32*384);
        float4* dstv = (float4*)Bs;
        #pragma unroll
        for (int i = 0; i < 12; i++) dstv[tid + 256*i] = src[tid + 256*i];
        __syncthreads();

        #pragma unroll 8
        for (int k = 0; k < 32; k++){
            const float* arow = &As[(chunk*32 + k)*AS_STRIDE + r0];
            unsigned long long A0 = dup2(arow[0]);
            unsigned long long A1 = dup2(arow[1]);
            unsigned long long A2 = dup2(arow[2]);
            unsigned long long A3 = dup2(arow[3]);
            const float* brow = &Bs[k*384 + jb];
            #pragma unroll
            for (int g = 0; g < 6; g++){
                unsigned long long B = *(const unsigned long long*)(brow + 64*g);
                acc[g][0] = ffma2(A0, B, acc[g][0]);
                acc[g][1] = ffma2(A1, B, acc[g][1]);
                acc[g][2] = ffma2(A2, B, acc[g][2]);
                acc[g][3] = ffma2(A3, B, acc[g][3]);
            }
        }
    }

    // park pre-activations in Gbuf (reuse Bs)
    __syncthreads();
    #pragma unroll
    for (int g = 0; g < 6; g++)
        #pragma unroll
        for (int i = 0; i < 4; i++){
            float2 v = unpack2(acc[g][i]);
            *(float2*)&Bs[(r0 + i)*384 + jb + 64*g] = v;
        }
    __syncthreads();

    // gates: 32 rows x 96 feats
    for (int idx = tid; idx < 32*96; idx += 256){
        int r = idx / 96;
        int jj = idx - r*96;
        const float* grow = &Bs[r*384];
        float pr  = grow[jj]       + sb[jj];
        float pz  = grow[96 + jj]  + sb[96 + jj];
        float gin = grow[192 + jj] + sb[192 + jj];
        float ghn = grow[288 + jj] + sb[288 + jj];
        float rr = sigf(pr);
        float zz = sigf(pz);
        float nn = tanhf(gin + rr*ghn);
        float hold = As[(96 + jj)*AS_STRIDE + r];
        g_h[(size_t)(nodeBase + r)*HD + jj] = (1.f - zz)*nn + zz*hold;
    }
}

// ---------------- pooling: mean of relu(h) over sorted batch ranges ---------
__global__ void k_pool(const int* __restrict__ b1, const int* __restrict__ b2,
                       const int* __restrict__ b3){
    int b = blockIdx.x;
    int c = blockIdx.y;
    const int* batch = (c==0)?b1:((c==1)?b2:b3);
    int lo = 0, hi = NC;
    while (lo < hi){ int m = (lo+hi) >> 1; if (batch[m] < b) lo = m+1; else hi = m; }
    int s0 = lo;
    hi = NC;
    while (lo < hi){ int m = (lo+hi) >> 1; if (batch[m] < b+1) lo = m+1; else hi = m; }
    int e0 = lo;
    float denom = fmaxf((float)(e0 - s0), 1.f);
    int f = threadIdx.x;
    float sum = 0.f;
    for (int n = s0; n < e0; n++)
        sum += fmaxf(g_h[(size_t)(c*NC + n)*HD + f], 0.f);
    g_pool[((size_t)c*NB + b)*HD + f] = sum / denom;
}

// ---------------- feature assembly ------------------------------------------
__global__ void k_feat(){
    int idx = blockIdx.x*blockDim.x + threadIdx.x;
    if (idx >= NB*384) return;
    int b = idx / 384;
    int j = idx - b*384;
    float v;
    if (j < 96)       v = g_pool[(size_t)b*HD + j];
    else if (j < 192) v = g_pool[((size_t)NB + b)*HD + (j-96)];
    else if (j < 288) v = g_pool[((size_t)2*NB + b)*HD + (j-192)];
    else {
        int jj = j - 288;
        v = g_pool[(size_t)b*HD + jj]
          * g_pool[((size_t)NB + b)*HD + jj]
          * g_pool[((size_t)2*NB + b)*HD + jj];
    }
    g_feat[idx] = v;
}

// ---------------- MLP GEMM: globals resolved in DEVICE code ------------------
// MODE 0: g_t1 = relu(g_feat @ fc1_w + fc1_b)   [4096,384]x[384,1536]
// MODE 1: g_t2 = relu(g_t1 @ fc2_w + fc2_b)     [4096,1536]x[1536,384]
template<int MODE>
__global__ void __launch_bounds__(256) k_gemm(const float* __restrict__ B,
                                              const float* __restrict__ bias){
    const float* A = (MODE == 0) ? g_feat : g_t1;
    float*       C = (MODE == 0) ? g_t1   : g_t2;
    const int N = (MODE == 0) ? 1536 : 384;
    const int K = (MODE == 0) ? 384  : 1536;

    __shared__ float As[64*33];
    __shared__ float Bs[32*68];
    int txx = threadIdx.x & 15;
    int tyy = threadIdx.x >> 4;
    int m0 = blockIdx.y*64;
    int n0 = blockIdx.x*64;
    float accv[4][4];
    #pragma unroll
    for (int i = 0; i < 4; i++)
        #pragma unroll
        for (int j = 0; j < 4; j++) accv[i][j] = 0.f;

    for (int kc = 0; kc < K; kc += 32){
        __syncthreads();
        for (int i = threadIdx.x; i < 64*32; i += 256){
            int r = i >> 5, k = i & 31;
            As[r*33 + k] = A[(size_t)(m0 + r)*K + kc + k];
        }
        for (int i = threadIdx.x; i < 32*64; i += 256){
            int k = i >> 6, cc = i & 63;
            Bs[k*68 + cc] = B[(size_t)(kc + k)*N + n0 + cc];
        }
        __syncthreads();
        #pragma unroll 8
        for (int k = 0; k < 32; k++){
            float a[4], bb[4];
            #pragma unroll
            for (int i = 0; i < 4; i++) a[i] = As[(tyy*4 + i)*33 + k];
            float4 bv = *(const float4*)&Bs[k*68 + txx*4];
            bb[0] = bv.x; bb[1] = bv.y; bb[2] = bv.z; bb[3] = bv.w;
            #pragma unroll
            for (int i = 0; i < 4; i++)
                #pragma unroll
                for (int j = 0; j < 4; j++)
                    accv[i][j] += a[i]*bb[j];
        }
    }
    #pragma unroll
    for (int i = 0; i < 4; i++){
        int row = m0 + tyy*4 + i;
        #pragma unroll
        for (int j = 0; j < 4; j++){
            int col = n0 + txx*4 + j;
            float v = accv[i][j] + bias[col];
            C[(size_t)row*N + col] = fmaxf(v, 0.f);
        }
    }
}

// ---------------- fc3: [4096,384] @ [384,3] ---------------------------------
__global__ void k_fc3(const float* __restrict__ w, const float* __restrict__ b,
                      float* __restrict__ out){
    int gt = blockIdx.x*blockDim.x + threadIdx.x;
    int row = gt >> 5;
    int lane = gt & 31;
    if (row >= NB) return;
    float a0 = 0.f, a1 = 0.f, a2 = 0.f;
    for (int k = lane; k < 384; k += 32){
        float f = g_t2[(size_t)row*384 + k];
        a0 += f*w[k*3 + 0];
        a1 += f*w[k*3 + 1];
        a2 += f*w[k*3 + 2];
    }
    #pragma unroll
    for (int o = 16; o; o >>= 1){
        a0 += __shfl_down_sync(0xffffffffu, a0, o);
        a1 += __shfl_down_sync(0xffffffffu, a1, o);
        a2 += __shfl_down_sync(0xffffffffu, a2, o);
    }
    if (lane == 0){
        out[row*3 + 0] = a0 + b[0];
        out[row*3 + 1] = a1 + b[1];
        out[row*3 + 2] = a2 + b[2];
    }
}

// ---------------- launch ----------------------------------------------------
extern "C" void kernel_launch(void* const* d_in, const int* in_sizes, int n_in,
                              void* d_out, int out_size) {
    // Size-based input classification — robust to metadata ordering.
    const float* xs[3]   = {0,0,0};
    const int*   es[3]   = {0,0,0};
    const int*   bs[3]   = {0,0,0};
    const float* Ws[3]   = {0,0,0};
    const float* wihs[3] = {0,0,0};
    const float* whhs[3] = {0,0,0};
    const float* bihs[3] = {0,0,0};
    const float* bhhs[3] = {0,0,0};
    const float* fcw[2]  = {0,0};
    const float* fc1b = 0; const float* fc2b = 0;
    const float* fc3w = 0; const float* fc3b = 0;
    int nx=0, ne=0, nb=0, nW=0, nwpair=0, nbpair=0, nfcw=0;
    for (int i = 0; i < n_in; i++){
        int s = in_sizes[i];
        const void* p = d_in[i];
        switch (s){
            case 6400000: if (nx < 3) xs[nx++] = (const float*)p; break;
            case 800000:  if (ne < 3) es[ne++] = (const int*)p;   break;
            case 200000:  if (nb < 3) bs[nb++] = (const int*)p;   break;
            case 55296:   if (nW < 3) Ws[nW++] = (const float*)p; break;
            case 27648:   { int c = nwpair/2;
                            if (c < 3){ if ((nwpair & 1) == 0) wihs[c] = (const float*)p;
                                        else                   whhs[c] = (const float*)p; }
                            nwpair++; } break;
            case 288:     { int c = nbpair/2;
                            if (c < 3){ if ((nbpair & 1) == 0) bihs[c] = (const float*)p;
                                        else                   bhhs[c] = (const float*)p; }
                            nbpair++; } break;
            case 589824:  if (nfcw < 2) fcw[nfcw++] = (const float*)p; break;
            case 1536:    fc1b = (const float*)p; break;
            case 384:     fc2b = (const float*)p; break;
            case 1152:    fc3w = (const float*)p; break;
            case 3:       fc3b = (const float*)p; break;
            default: break;
        }
    }
    const float* fc1w = fcw[0];
    const float* fc2w = fcw[1];
    float* out = (float*)d_out;

    const int gruSmem = (AS_FLOATS + BS_FLOATS + 384) * 4;  // 76032 B
    cudaFuncSetAttribute(k_gru, cudaFuncAttributeMaxDynamicSharedMemorySize, gruSmem);

    // init h0 + counters
    {
        long long tot = (long long)NN*HD;
        int blocks = (int)((tot + 255)/256);
        k_init<<<blocks, 256>>>(xs[0], xs[1], xs[2]);
    }
    // CSR
    k_deg<<<(EE + 255)/256, 256>>>(es[0], es[1], es[2]);
    k_scan1<<<NPART, SCAN_BLK>>>();
    k_scan2<<<1, SCAN_BLK>>>();
    k_scan3<<<NPART, SCAN_BLK>>>();
    k_fill<<<(EE + 255)/256, 256>>>(es[0], es[1], es[2]);
    // weight packing
    k_pack<<<dim3((192*384 + 255)/256, 18), 256>>>(Ws[0], wihs[0], whhs[0],
                                                   Ws[1], wihs[1], whhs[1],
                                                   Ws[2], wihs[2], whhs[2]);
    k_packbias<<<18, 384>>>(bihs[0], bhhs[0], bihs[1], bhhs[1], bihs[2], bhhs[2]);
    // 6 GGC layers
    for (int l = 0; l < 6; l++){
        k_scatter<<<(NN*32 + 255)/256, 256>>>();
        k_gru<<<dim3(NC/32, 3), 256, gruSmem>>>(l);
    }
    // pool + head
    k_pool<<<dim3(NB, 3), 96>>>(bs[0], bs[1], bs[2]);
    k_feat<<<(NB*384 + 255)/256, 256>>>();
    k_gemm<0><<<dim3(1536/64, NB/64), 256>>>(fc1w, fc1b);
    k_gemm<1><<<dim3(384/64,  NB/64), 256>>>(fc2w, fc2b);
    k_fc3<<<(NB*32 + 255)/256, 256>>>(fc3w, fc3b, out);
}

// round 5
// speedup vs baseline: 1.2317x; 1.2317x over previous
#include <cuda_runtime.h>
#include <cstdint>

#define NC 200000
#define NCOMP 3
#define NN (NC*NCOMP)
#define EC 400000
#define EE (EC*NCOMP)
#define HD 96
#define NB 4096
#define SCAN_BLK 1024
#define NPART ((NN + SCAN_BLK - 1)/SCAN_BLK)

// ---------------- device scratch (static, no runtime allocation) ----------
__device__ __align__(16) float g_h[(size_t)NN*HD];
__device__ __align__(16) float g_s[(size_t)NN*HD];
__device__ int   g_deg[NN];
__device__ int   g_fill[NN];
__device__ int   g_off[NN+1];
__device__ int   g_esrc[EE];
__device__ int   g_part[SCAN_BLK];
__device__ __align__(16) unsigned short g_Wbh[(size_t)18*384*192]; // bf16 hi, [cl][n][k]
__device__ __align__(16) unsigned short g_Wbl[(size_t)18*384*192]; // bf16 lo
__device__ __align__(16) float g_bias[18*384];        // [cl][ brz(192) | bin(96) | bnh(96) ]
__device__ __align__(16) float g_pool[NCOMP*NB*HD];
__device__ __align__(16) float g_feat[(size_t)NB*384];
__device__ __align__(16) float g_t1[(size_t)NB*1536];
__device__ __align__(16) float g_t2[(size_t)NB*384];

// ---------------- helpers ---------------------------------------------------
__device__ __forceinline__ unsigned f2bf(float x){
    unsigned u = __float_as_uint(x);
    return (u + 0x7fffu + ((u >> 16) & 1u)) >> 16;   // RN-even
}
__device__ __forceinline__ float bfv(unsigned bits16){ return __uint_as_float(bits16 << 16); }
__device__ __forceinline__ float bflo(unsigned w){ return __uint_as_float(w << 16); }
__device__ __forceinline__ float bfhi(unsigned w){ return __uint_as_float(w & 0xffff0000u); }
__device__ __forceinline__ float sigf(float x){ return 1.f/(1.f + expf(-x)); }

__device__ __forceinline__ void mma16816(float* d, const unsigned* a, unsigned b0, unsigned b1){
    asm volatile(
        "mma.sync.aligned.m16n8k16.row.col.f32.bf16.bf16.f32 "
        "{%0,%1,%2,%3}, {%4,%5,%6,%7}, {%8,%9}, {%0,%1,%2,%3};"
        : "+f"(d[0]), "+f"(d[1]), "+f"(d[2]), "+f"(d[3])
        : "r"(a[0]), "r"(a[1]), "r"(a[2]), "r"(a[3]), "r"(b0), "r"(b1));
}

// ---------------- init: h0 = pad(x), zero counters --------------------------
__global__ void k_init(const float* __restrict__ x1, const float* __restrict__ x2,
                       const float* __restrict__ x3){
    long long idx = (long long)blockIdx.x*blockDim.x + threadIdx.x;
    if (idx < (long long)NN*HD){
        int n = (int)(idx / HD);
        int j = (int)(idx - (long long)n*HD);
        int c = n / NC;
        int ln = n - c*NC;
        const float* x = (c==0)?x1:((c==1)?x2:x3);
        g_h[idx] = (j < 32) ? x[(size_t)ln*32 + j] : 0.f;
    }
    if (idx < NN){ g_deg[idx] = 0; g_fill[idx] = 0; }
}

// ---------------- CSR build -------------------------------------------------
__global__ void k_deg(const int* __restrict__ e1, const int* __restrict__ e2,
                      const int* __restrict__ e3){
    int e = blockIdx.x*blockDim.x + threadIdx.x;
    if (e >= EE) return;
    int c = e / EC, le = e - c*EC;
    const int* ei = (c==0)?e1:((c==1)?e2:e3);
    int dst = ei[EC + le];
    atomicAdd(&g_deg[c*NC + dst], 1);
}

__global__ void k_scan1(){
    __shared__ int sm[SCAN_BLK];
    int tid = threadIdx.x;
    int i = blockIdx.x*SCAN_BLK + tid;
    int v = (i < NN) ? g_deg[i] : 0;
    sm[tid] = v;
    __syncthreads();
    for (int off = 1; off < SCAN_BLK; off <<= 1){
        int t = 0;
        if (tid >= off) t = sm[tid - off];
        __syncthreads();
        sm[tid] += t;
        __syncthreads();
    }
    if (i < NN) g_off[i] = sm[tid] - v;
    if (tid == SCAN_BLK-1) g_part[blockIdx.x] = sm[tid];
}

__global__ void k_scan2(){
    __shared__ int sm[SCAN_BLK];
    int tid = threadIdx.x;
    int v = (tid < NPART) ? g_part[tid] : 0;
    sm[tid] = v;
    __syncthreads();
    for (int off = 1; off < SCAN_BLK; off <<= 1){
        int t = 0;
        if (tid >= off) t = sm[tid - off];
        __syncthreads();
        sm[tid] += t;
        __syncthreads();
    }
    if (tid < NPART) g_part[tid] = sm[tid] - v;
}

__global__ void k_scan3(){
    int tid = threadIdx.x;
    int i = blockIdx.x*SCAN_BLK + tid;
    if (i < NN) g_off[i] += g_part[blockIdx.x];
    if (blockIdx.x == 0 && tid == 0) g_off[NN] = EE;
}

__global__ void k_fill(const int* __restrict__ e1, const int* __restrict__ e2,
                       const int* __restrict__ e3){
    int e = blockIdx.x*blockDim.x + threadIdx.x;
    if (e >= EE) return;
    int c = e / EC, le = e - c*EC;
    const int* ei = (c==0)?e1:((c==1)?e2:e3);
    int dst = ei[EC + le];
    int src = ei[le];
    int dg = c*NC + dst;
    int p = g_off[dg] + atomicAdd(&g_fill[dg], 1);
    g_esrc[p] = c*NC + src;
}

// ---------------- weight packing --------------------------------------------
// Logical Wpack[k][j], k in [0,192), j in [0,384):
//  k<96  (S part):   j<288 -> (W_l @ wih^T)[k][j]  ; j>=288 -> 0
//  k>=96 (h part):   j<192 -> whh[j][k-96] ; 192<=j<288 -> 0 ; j>=288 -> whh[j-96][k-96]
// Stored TRANSPOSED as bf16 hi/lo planes: g_Wb*[cl][j][k]
__global__ void k_pack(
    const float* __restrict__ W1, const float* __restrict__ wih1, const float* __restrict__ whh1,
    const float* __restrict__ W2, const float* __restrict__ wih2, const float* __restrict__ whh2,
    const float* __restrict__ W3, const float* __restrict__ wih3, const float* __restrict__ whh3)
{
    int cl = blockIdx.y;
    int c = cl / 6, l = cl % 6;
    const float* W   = (c==0)?W1:((c==1)?W2:W3);
    const float* wih = (c==0)?wih1:((c==1)?wih2:wih3);
    const float* whh = (c==0)?whh1:((c==1)?whh2:whh3);
    int id = blockIdx.x*blockDim.x + threadIdx.x;
    if (id >= 192*384) return;
    int k = id / 384, j = id % 384;
    float v = 0.f;
    if (k < 96){
        if (j < 288){
            const float* wr = W + (size_t)(l*96 + k)*96;
            const float* ir = wih + (size_t)j*96;
            float s = 0.f;
            #pragma unroll 8
            for (int t = 0; t < 96; t++) s += wr[t]*ir[t];
            v = s;
        }
    } else {
        int t = k - 96;
        if (j < 192)       v = whh[(size_t)j*96 + t];
        else if (j >= 288) v = whh[(size_t)(j-96)*96 + t];
    }
    unsigned hb = f2bf(v);
    float rem = v - bfv(hb);
    size_t o = (size_t)cl*73728 + (size_t)j*192 + k;
    g_Wbh[o] = (unsigned short)hb;
    g_Wbl[o] = (unsigned short)f2bf(rem);
}

__global__ void k_packbias(
    const float* __restrict__ bih1, const float* __restrict__ bhh1,
    const float* __restrict__ bih2, const float* __restrict__ bhh2,
    const float* __restrict__ bih3, const float* __restrict__ bhh3)
{
    int cl = blockIdx.x;
    int c = cl / 6;
    const float* bih = (c==0)?bih1:((c==1)?bih2:bih3);
    const float* bhh = (c==0)?bhh1:((c==1)?bhh2:bhh3);
    int j = threadIdx.x;   // 0..383
    float v;
    if (j < 192)      v = bih[j] + bhh[j];
    else if (j < 288) v = bih[192 + (j-192)];
    else              v = bhh[192 + (j-288)];
    g_bias[cl*384 + j] = v;
}

// ---------------- per-layer aggregation: S[dst] = sum_{src} h[src] ----------
__global__ void k_scatter(){
    int gt = blockIdx.x*blockDim.x + threadIdx.x;
    int node = gt >> 5;
    int lane = gt & 31;
    if (node >= NN) return;
    int o0 = g_off[node], o1 = g_off[node+1];
    float a0 = 0.f, a1 = 0.f, a2 = 0.f;
    for (int e = o0; e < o1; e++){
        int s = __ldg(&g_esrc[e]);
        const float* hp = g_h + (size_t)s*HD;
        a0 += hp[lane];
        a1 += hp[lane+32];
        a2 += hp[lane+64];
    }
    float* sp = g_s + (size_t)node*HD;
    sp[lane]    = a0;
    sp[lane+32] = a1;
    sp[lane+64] = a2;
}

// ---------------- fused GRU layer (tensor-core, bf16 3-term split) ----------
// Block: 128 nodes. 8 warps = 4(M) x 2(N-slice). Pass p covers features
// [p*48, p*48+48): warp (wm,wn) owns rows wm*32..+31, features wn*24 + t*8.
// N-tiles per warp = (gate g, t): column = g*96 + p*48 + wn*24 + t*8.
// A = [S(96) | h(96)] bf16 hi/lo planes in smem, stride 100 words/row.
// W chunks (k16 x 192 gate-sliced cols) double-buffered, [n'][9 words].
#define SM_AH 0
#define SM_AL 12800
#define SM_WB 25600            // [2 bufs][2 planes][192][9] = 2*3456 words
#define SM_BIAS 32512
#define SM_WORDS 32896         // *4 = 131584 bytes
__global__ void __launch_bounds__(256, 1) k_gru(int layer){
    extern __shared__ unsigned smw[];
    unsigned* Ah = smw + SM_AH;
    unsigned* Al = smw + SM_AL;
    unsigned* Wbuf = smw + SM_WB;
    float* sb = (float*)(smw + SM_BIAS);

    const int comp = blockIdx.y;
    const int cl = comp*6 + layer;
    const int row0 = blockIdx.x*128;
    const int tid = threadIdx.x;
    const int lane = tid & 31;
    const int wid = tid >> 5;
    const int wm = wid & 3;          // M group: rows wm*32..
    const int wn = wid >> 2;         // 0..1
    const int lr = lane >> 2;        // 0..7
    const int lq = lane & 3;         // 0..3

    for (int i = tid; i < 384; i += 256) sb[i] = g_bias[cl*384 + i];

    // ---- stage A (S|h) as bf16 hi/lo planes ----
    #pragma unroll 1
    for (int q = 0; q < 24; q++){
        int fidx = tid + 256*q;          // 0..6143 float4s
        int row = fidx / 48;
        int c4 = fidx - row*48;          // float4 col
        float4 v = make_float4(0.f,0.f,0.f,0.f);
        int r = row0 + row;
        if (r < NC){
            size_t base = (size_t)(comp*NC + r)*96;
            v = (c4 < 24) ? *(const float4*)(g_s + base + c4*4)
                          : *(const float4*)(g_h + base + (c4-24)*4);
        }
        unsigned h0 = f2bf(v.x), h1 = f2bf(v.y), h2 = f2bf(v.z), h3 = f2bf(v.w);
        int w = row*100 + c4*2;
        Ah[w]   = h0 | (h1 << 16);
        Ah[w+1] = h2 | (h3 << 16);
        Al[w]   = f2bf(v.x - bfv(h0)) | (f2bf(v.y - bfv(h1)) << 16);
        Al[w+1] = f2bf(v.z - bfv(h2)) | (f2bf(v.w - bfv(h3)) << 16);
    }

    const unsigned* WhG = ((const unsigned*)g_Wbh) + (size_t)cl*36864;
    const unsigned* WlG = ((const unsigned*)g_Wbl) + (size_t)cl*36864;

    #pragma unroll 1
    for (int p = 0; p < 2; p++){
        float acc[2][4][3][4];
        #pragma unroll
        for (int mt = 0; mt < 2; mt++)
            #pragma unroll
            for (int g = 0; g < 4; g++)
                #pragma unroll
                for (int t = 0; t < 3; t++)
                    #pragma unroll
                    for (int i = 0; i < 4; i++) acc[mt][g][t][i] = 0.f;

        unsigned rg[12];
        // prefetch chunk ks=0
        #pragma unroll
        for (int q = 0; q < 12; q++){
            int idx = tid + 256*q;
            int plane = idx / 1536;
            int rw = idx - plane*1536;
            int nrow = rw >> 3, w = rw & 7;
            int n = (nrow/48)*96 + p*48 + (nrow%48);
            rg[q] = __ldg((plane ? WlG : WhG) + n*96 + w);
        }
        __syncthreads();
        #pragma unroll
        for (int q = 0; q < 12; q++){
            int idx = tid + 256*q;
            int plane = idx / 1536;
            int rw = idx - plane*1536;
            Wbuf[plane*1728 + (rw>>3)*9 + (rw&7)] = rg[q];
        }

        #pragma unroll 1
        for (int ks = 0; ks < 12; ks++){
            int buf = ks & 1;
            __syncthreads();
            if (ks < 11){
                #pragma unroll
                for (int q = 0; q < 12; q++){
                    int idx = tid + 256*q;
                    int plane = idx / 1536;
                    int rw = idx - plane*1536;
                    int nrow = rw >> 3, w = rw & 7;
                    int n = (nrow/48)*96 + p*48 + (nrow%48);
                    rg[q] = __ldg((plane ? WlG : WhG) + n*96 + (ks+1)*8 + w);
                }
            }
            // A fragments
            unsigned afh[2][4], afl[2][4];
            #pragma unroll
            for (int mt = 0; mt < 2; mt++){
                int base = (wm*32 + mt*16 + lr)*100 + ks*8 + lq;
                afh[mt][0] = Ah[base];     afh[mt][1] = Ah[base + 800];
                afh[mt][2] = Ah[base + 4]; afh[mt][3] = Ah[base + 804];
                afl[mt][0] = Al[base];     afl[mt][1] = Al[base + 800];
                afl[mt][2] = Al[base + 4]; afl[mt][3] = Al[base + 804];
            }
            const unsigned* WB = Wbuf + buf*3456;
            #pragma unroll
            for (int g = 0; g < 4; g++){
                #pragma unroll
                for (int t = 0; t < 3; t++){
                    int nrow = g*48 + wn*24 + t*8 + lr;
                    int wb = nrow*9 + lq;
                    unsigned bh0 = WB[wb],        bh1 = WB[wb + 4];
                    unsigned bl0 = WB[1728 + wb], bl1 = WB[1728 + wb + 4];
                    #pragma unroll
                    for (int mt = 0; mt < 2; mt++){
                        mma16816(acc[mt][g][t], afh[mt], bh0, bh1);
                        mma16816(acc[mt][g][t], afh[mt], bl0, bl1);
                        mma16816(acc[mt][g][t], afl[mt], bh0, bh1);
                    }
                }
            }
            if (ks < 11){
                #pragma unroll
                for (int q = 0; q < 12; q++){
                    int idx = tid + 256*q;
                    int plane = idx / 1536;
                    int rw = idx - plane*1536;
                    Wbuf[(buf^1)*3456 + plane*1728 + (rw>>3)*9 + (rw&7)] = rg[q];
                }
            }
        }
        __syncthreads();

        // ---- epilogue: gates in registers, write h' ----
        #pragma unroll
        for (int mt = 0; mt < 2; mt++){
            #pragma unroll
            for (int t = 0; t < 3; t++){
                int f0 = p*48 + wn*24 + t*8 + 2*lq;
                float bR0 = sb[f0],       bR1 = sb[f0+1];
                float bZ0 = sb[96+f0],    bZ1 = sb[96+f0+1];
                float bI0 = sb[192+f0],   bI1 = sb[192+f0+1];
                float bN0 = sb[288+f0],   bN1 = sb[288+f0+1];
                #pragma unroll
                for (int half = 0; half < 2; half++){
                    int row = wm*32 + mt*16 + lr + half*8;
                    int w = row*100 + 48 + (f0 >> 1);
                    unsigned hw = Ah[w], lw = Al[w];
                    float ho0 = bflo(hw) + bflo(lw);
                    float ho1 = bfhi(hw) + bfhi(lw);
                    int ci = half*2;
                    float rr0 = sigf(acc[mt][0][t][ci]   + bR0);
                    float rr1 = sigf(acc[mt][0][t][ci+1] + bR1);
                    float zz0 = sigf(acc[mt][1][t][ci]   + bZ0);
                    float zz1 = sigf(acc[mt][1][t][ci+1] + bZ1);
                    float nn0 = tanhf(acc[mt][2][t][ci]   + bI0 + rr0*(acc[mt][3][t][ci]   + bN0));
                    float nn1 = tanhf(acc[mt][2][t][ci+1] + bI1 + rr1*(acc[mt][3][t][ci+1] + bN1));
                    float o0 = (1.f - zz0)*nn0 + zz0*ho0;
                    float o1 = (1.f - zz1)*nn1 + zz1*ho1;
                    int r = row0 + row;
                    if (r < NC){
                        float2 st = make_float2(o0, o1);
                        *(float2*)(g_h + (size_t)(comp*NC + r)*96 + f0) = st;
                    }
                }
            }
        }
    }
}

// ---------------- pooling: mean of relu(h) over sorted batch ranges ---------
__global__ void k_pool(const int* __restrict__ b1, const int* __restrict__ b2,
                       const int* __restrict__ b3){
    int b = blockIdx.x;
    int c = blockIdx.y;
    const int* batch = (c==0)?b1:((c==1)?b2:b3);
    int lo = 0, hi = NC;
    while (lo < hi){ int m = (lo+hi) >> 1; if (batch[m] < b) lo = m+1; else hi = m; }
    int s0 = lo;
    hi = NC;
    while (lo < hi){ int m = (lo+hi) >> 1; if (batch[m] < b+1) lo = m+1; else hi = m; }
    int e0 = lo;
    float denom = fmaxf((float)(e0 - s0), 1.f);
    int f = threadIdx.x;
    float sum = 0.f;
    for (int n = s0; n < e0; n++)
        sum += fmaxf(g_h[(size_t)(c*NC + n)*HD + f], 0.f);
    g_pool[((size_t)c*NB + b)*HD + f] = sum / denom;
}

// ---------------- feature assembly ------------------------------------------
__global__ void k_feat(){
    int idx = blockIdx.x*blockDim.x + threadIdx.x;
    if (idx >= NB*384) return;
    int b = idx / 384;
    int j = idx - b*384;
    float v;
    if (j < 96)       v = g_pool[(size_t)b*HD + j];
    else if (j < 192) v = g_pool[((size_t)NB + b)*HD + (j-96)];
    else if (j < 288) v = g_pool[((size_t)2*NB + b)*HD + (j-192)];
    else {
        int jj = j - 288;
        v = g_pool[(size_t)b*HD + jj]
          * g_pool[((size_t)NB + b)*HD + jj]
          * g_pool[((size_t)2*NB + b)*HD + jj];
    }
    g_feat[idx] = v;
}

// ---------------- MLP GEMM (globals resolved in device code) ----------------
template<int MODE>
__global__ void __launch_bounds__(256) k_gemm(const float* __restrict__ B,
                                              const float* __restrict__ bias){
    const float* A = (MODE == 0) ? g_feat : g_t1;
    float*       C = (MODE == 0) ? g_t1   : g_t2;
    const int N = (MODE == 0) ? 1536 : 384;
    const int K = (MODE == 0) ? 384  : 1536;

    __shared__ float As[64*33];
    __shared__ float Bs[32*68];
    int txx = threadIdx.x & 15;
    int tyy = threadIdx.x >> 4;
    int m0 = blockIdx.y*64;
    int n0 = blockIdx.x*64;
    float accv[4][4];
    #pragma unroll
    for (int i = 0; i < 4; i++)
        #pragma unroll
        for (int j = 0; j < 4; j++) accv[i][j] = 0.f;

    for (int kc = 0; kc < K; kc += 32){
        __syncthreads();
        for (int i = threadIdx.x; i < 64*32; i += 256){
            int r = i >> 5, k = i & 31;
            As[r*33 + k] = A[(size_t)(m0 + r)*K + kc + k];
        }
        for (int i = threadIdx.x; i < 32*64; i += 256){
            int k = i >> 6, cc = i & 63;
            Bs[k*68 + cc] = B[(size_t)(kc + k)*N + n0 + cc];
        }
        __syncthreads();
        #pragma unroll 8
        for (int k = 0; k < 32; k++){
            float a[4], bb[4];
            #pragma unroll
            for (int i = 0; i < 4; i++) a[i] = As[(tyy*4 + i)*33 + k];
            float4 bv = *(const float4*)&Bs[k*68 + txx*4];
            bb[0] = bv.x; bb[1] = bv.y; bb[2] = bv.z; bb[3] = bv.w;
            #pragma unroll
            for (int i = 0; i < 4; i++)
                #pragma unroll
                for (int j = 0; j < 4; j++)
                    accv[i][j] += a[i]*bb[j];
        }
    }
    #pragma unroll
    for (int i = 0; i < 4; i++){
        int row = m0 + tyy*4 + i;
        #pragma unroll
        for (int j = 0; j < 4; j++){
            int col = n0 + txx*4 + j;
            float v = accv[i][j] + bias[col];
            C[(size_t)row*N + col] = fmaxf(v, 0.f);
        }
    }
}

// ---------------- fc3: [4096,384] @ [384,3] ---------------------------------
__global__ void k_fc3(const float* __restrict__ w, const float* __restrict__ b,
                      float* __restrict__ out){
    int gt = blockIdx.x*blockDim.x + threadIdx.x;
    int row = gt >> 5;
    int lane = gt & 31;
    if (row >= NB) return;
    float a0 = 0.f, a1 = 0.f, a2 = 0.f;
    for (int k = lane; k < 384; k += 32){
        float f = g_t2[(size_t)row*384 + k];
        a0 += f*w[k*3 + 0];
        a1 += f*w[k*3 + 1];
        a2 += f*w[k*3 + 2];
    }
    #pragma unroll
    for (int o = 16; o; o >>= 1){
        a0 += __shfl_down_sync(0xffffffffu, a0, o);
        a1 += __shfl_down_sync(0xffffffffu, a1, o);
        a2 += __shfl_down_sync(0xffffffffu, a2, o);
    }
    if (lane == 0){
        out[row*3 + 0] = a0 + b[0];
        out[row*3 + 1] = a1 + b[1];
        out[row*3 + 2] = a2 + b[2];
    }
}

// ---------------- launch ----------------------------------------------------
extern "C" void kernel_launch(void* const* d_in, const int* in_sizes, int n_in,
                              void* d_out, int out_size) {
    const float* xs[3]   = {0,0,0};
    const int*   es[3]   = {0,0,0};
    const int*   bs[3]   = {0,0,0};
    const float* Ws[3]   = {0,0,0};
    const float* wihs[3] = {0,0,0};
    const float* whhs[3] = {0,0,0};
    const float* bihs[3] = {0,0,0};
    const float* bhhs[3] = {0,0,0};
    const float* fcw[2]  = {0,0};
    const float* fc1b = 0; const float* fc2b = 0;
    const float* fc3w = 0; const float* fc3b = 0;
    int nx=0, ne=0, nb=0, nW=0, nwpair=0, nbpair=0, nfcw=0;
    for (int i = 0; i < n_in; i++){
        int s = in_sizes[i];
        const void* p = d_in[i];
        switch (s){
            case 6400000: if (nx < 3) xs[nx++] = (const float*)p; break;
            case 800000:  if (ne < 3) es[ne++] = (const int*)p;   break;
            case 200000:  if (nb < 3) bs[nb++] = (const int*)p;   break;
            case 55296:   if (nW < 3) Ws[nW++] = (const float*)p; break;
            case 27648:   { int c = nwpair/2;
                            if (c < 3){ if ((nwpair & 1) == 0) wihs[c] = (const float*)p;
                                        else                   whhs[c] = (const float*)p; }
                            nwpair++; } break;
            case 288:     { int c = nbpair/2;
                            if (c < 3){ if ((nbpair & 1) == 0) bihs[c] = (const float*)p;
                                        else                   bhhs[c] = (const float*)p; }
                            nbpair++; } break;
            case 589824:  if (nfcw < 2) fcw[nfcw++] = (const float*)p; break;
            case 1536:    fc1b = (const float*)p; break;
            case 384:     fc2b = (const float*)p; break;
            case 1152:    fc3w = (const float*)p; break;
            case 3:       fc3b = (const float*)p; break;
            default: break;
        }
    }
    const float* fc1w = fcw[0];
    const float* fc2w = fcw[1];
    float* out = (float*)d_out;

    const int gruSmem = SM_WORDS*4;   // 131584 B
    cudaFuncSetAttribute(k_gru, cudaFuncAttributeMaxDynamicSharedMemorySize, gruSmem);

    {
        long long tot = (long long)NN*HD;
        int blocks = (int)((tot + 255)/256);
        k_init<<<blocks, 256>>>(xs[0], xs[1], xs[2]);
    }
    k_deg<<<(EE + 255)/256, 256>>>(es[0], es[1], es[2]);
    k_scan1<<<NPART, SCAN_BLK>>>();
    k_scan2<<<1, SCAN_BLK>>>();
    k_scan3<<<NPART, SCAN_BLK>>>();
    k_fill<<<(EE + 255)/256, 256>>>(es[0], es[1], es[2]);
    k_pack<<<dim3((192*384 + 255)/256, 18), 256>>>(Ws[0], wihs[0], whhs[0],
                                                   Ws[1], wihs[1], whhs[1],
                                                   Ws[2], wihs[2], whhs[2]);
    k_packbias<<<18, 384>>>(bihs[0], bhhs[0], bihs[1], bhhs[1], bihs[2], bhhs[2]);

    const int gruBlocks = (NC + 127)/128;   // 1563
    for (int l = 0; l < 6; l++){
        k_scatter<<<(NN*32 + 255)/256, 256>>>();
        k_gru<<<dim3(gruBlocks, 3), 256, gruSmem>>>(l);
    }
    k_pool<<<dim3(NB, 3), 96>>>(bs[0], bs[1], bs[2]);
    k_feat<<<(NB*384 + 255)/256, 256>>>();
    k_gemm<0><<<dim3(1536/64, NB/64), 256>>>(fc1w, fc1b);
    k_gemm<1><<<dim3(384/64,  NB/64), 256>>>(fc2w, fc2b);
    k_fc3<<<(NB*32 + 255)/256, 256>>>(fc3w, fc3b, out);
}

// round 6
// speedup vs baseline: 1.3027x; 1.0577x over previous
#include <cuda_runtime.h>
#include <cstdint>

#define NC 200000
#define NCOMP 3
#define NN (NC*NCOMP)
#define EC 400000
#define EE (EC*NCOMP)
#define HD 96
#define NB 4096
#define SCAN_BLK 1024
#define NPART ((NN + SCAN_BLK - 1)/SCAN_BLK)

// ---------------- device scratch (static, no runtime allocation) ----------
__device__ __align__(16) float g_h[(size_t)NN*HD];
__device__ __align__(16) float g_s[(size_t)NN*HD];
__device__ int   g_deg[NN];
__device__ int   g_fill[NN];
__device__ int   g_off[NN+1];
__device__ int   g_esrc[EE];
__device__ int   g_part[SCAN_BLK];
__device__ __align__(16) unsigned short g_Wbh[(size_t)18*384*192]; // bf16 hi, [cl][n][k]
__device__ __align__(16) unsigned short g_Wbl[(size_t)18*384*192]; // bf16 lo
__device__ __align__(16) float g_bias[18*384];        // [cl][ brz(192) | bin(96) | bnh(96) ]
__device__ __align__(16) float g_pool[NCOMP*NB*HD];
__device__ __align__(16) float g_feat[(size_t)NB*384];
__device__ __align__(16) float g_t1[(size_t)NB*1536];
__device__ __align__(16) float g_t2[(size_t)NB*384];

// ---------------- helpers ---------------------------------------------------
__device__ __forceinline__ unsigned f2bf(float x){
    unsigned u = __float_as_uint(x);
    return (u + 0x7fffu + ((u >> 16) & 1u)) >> 16;   // RN-even
}
__device__ __forceinline__ float bfv(unsigned bits16){ return __uint_as_float(bits16 << 16); }
__device__ __forceinline__ float bflo(unsigned w){ return __uint_as_float(w << 16); }
__device__ __forceinline__ float bfhi(unsigned w){ return __uint_as_float(w & 0xffff0000u); }
__device__ __forceinline__ float ex2f(float x){ float y; asm("ex2.approx.f32 %0, %1;" : "=f"(y) : "f"(x)); return y; }
__device__ __forceinline__ float rcpf(float x){ float y; asm("rcp.approx.f32 %0, %1;" : "=f"(y) : "f"(x)); return y; }
#define L2E 1.4426950408889634f

__device__ __forceinline__ void mma16816(float* d, const unsigned* a, unsigned b0, unsigned b1){
    asm volatile(
        "mma.sync.aligned.m16n8k16.row.col.f32.bf16.bf16.f32 "
        "{%0,%1,%2,%3}, {%4,%5,%6,%7}, {%8,%9}, {%0,%1,%2,%3};"
        : "+f"(d[0]), "+f"(d[1]), "+f"(d[2]), "+f"(d[3])
        : "r"(a[0]), "r"(a[1]), "r"(a[2]), "r"(a[3]), "r"(b0), "r"(b1));
}

// ---------------- mega kernel: init h0 + zero counters + pack W + pack bias --
#define MEGA_IB 225000      // (NN*HD)/256
#define MEGA_PB 5184        // 18*73728/256
#define MEGA_BB 27          // ceil(18*384/256)
__global__ void k_mega(
    const float* __restrict__ x1, const float* __restrict__ x2, const float* __restrict__ x3,
    const float* __restrict__ W1, const float* __restrict__ wih1, const float* __restrict__ whh1,
    const float* __restrict__ W2, const float* __restrict__ wih2, const float* __restrict__ whh2,
    const float* __restrict__ W3, const float* __restrict__ wih3, const float* __restrict__ whh3,
    const float* __restrict__ bih1, const float* __restrict__ bhh1,
    const float* __restrict__ bih2, const float* __restrict__ bhh2,
    const float* __restrict__ bih3, const float* __restrict__ bhh3)
{
    int bid = blockIdx.x;
    int tid = threadIdx.x;
    if (bid < MEGA_IB){
        long long idx = (long long)bid*256 + tid;
        int n = (int)(idx / HD);
        int j = (int)(idx - (long long)n*HD);
        int c = n / NC;
        int ln = n - c*NC;
        const float* x = (c==0)?x1:((c==1)?x2:x3);
        g_h[idx] = (j < 32) ? x[(size_t)ln*32 + j] : 0.f;
        if (idx < NN){ g_deg[(int)idx] = 0; g_fill[(int)idx] = 0; }
    } else if (bid < MEGA_IB + MEGA_PB){
        int gid = (bid - MEGA_IB)*256 + tid;     // < 18*73728
        int cl = gid / 73728;
        int rem = gid - cl*73728;
        int c = cl / 6, l = cl % 6;
        const float* W   = (c==0)?W1:((c==1)?W2:W3);
        const float* wih = (c==0)?wih1:((c==1)?wih2:wih3);
        const float* whh = (c==0)?whh1:((c==1)?whh2:whh3);
        int k = rem / 384, j = rem % 384;
        float v = 0.f;
        if (k < 96){
            if (j < 288){
                const float* wr = W + (size_t)(l*96 + k)*96;
                const float* ir = wih + (size_t)j*96;
                float s = 0.f;
                #pragma unroll 8
                for (int t = 0; t < 96; t++) s += wr[t]*ir[t];
                v = s;
            }
        } else {
            int t = k - 96;
            if (j < 192)       v = whh[(size_t)j*96 + t];
            else if (j >= 288) v = whh[(size_t)(j-96)*96 + t];
        }
        unsigned hb = f2bf(v);
        float remv = v - bfv(hb);
        size_t o = (size_t)cl*73728 + (size_t)j*192 + k;
        g_Wbh[o] = (unsigned short)hb;
        g_Wbl[o] = (unsigned short)f2bf(remv);
    } else {
        int id = (bid - MEGA_IB - MEGA_PB)*256 + tid;
        if (id < 18*384){
            int cl = id / 384;
            int j = id - cl*384;
            int c = cl / 6;
            const float* bih = (c==0)?bih1:((c==1)?bih2:bih3);
            const float* bhh = (c==0)?bhh1:((c==1)?bhh2:bhh3);
            float v;
            if (j < 192)      v = bih[j] + bhh[j];
            else if (j < 288) v = bih[192 + (j-192)];
            else              v = bhh[192 + (j-288)];
            g_bias[cl*384 + j] = v;
        }
    }
}

// ---------------- CSR build -------------------------------------------------
__global__ void k_deg(const int* __restrict__ e1, const int* __restrict__ e2,
                      const int* __restrict__ e3){
    int e = blockIdx.x*blockDim.x + threadIdx.x;
    if (e >= EE) return;
    int c = e / EC, le = e - c*EC;
    const int* ei = (c==0)?e1:((c==1)?e2:e3);
    int dst = ei[EC + le];
    atomicAdd(&g_deg[c*NC + dst], 1);
}

__global__ void k_scan1(){
    __shared__ int sm[SCAN_BLK];
    int tid = threadIdx.x;
    int i = blockIdx.x*SCAN_BLK + tid;
    int v = (i < NN) ? g_deg[i] : 0;
    sm[tid] = v;
    __syncthreads();
    for (int off = 1; off < SCAN_BLK; off <<= 1){
        int t = 0;
        if (tid >= off) t = sm[tid - off];
        __syncthreads();
        sm[tid] += t;
        __syncthreads();
    }
    if (i < NN) g_off[i] = sm[tid] - v;
    if (tid == SCAN_BLK-1) g_part[blockIdx.x] = sm[tid];
}

__global__ void k_scan2(){
    __shared__ int sm[SCAN_BLK];
    int tid = threadIdx.x;
    int v = (tid < NPART) ? g_part[tid] : 0;
    sm[tid] = v;
    __syncthreads();
    for (int off = 1; off < SCAN_BLK; off <<= 1){
        int t = 0;
        if (tid >= off) t = sm[tid - off];
        __syncthreads();
        sm[tid] += t;
        __syncthreads();
    }
    if (tid < NPART) g_part[tid] = sm[tid] - v;
}

// fill with scan3 partial-add inlined
__global__ void k_fill(const int* __restrict__ e1, const int* __restrict__ e2,
                       const int* __restrict__ e3){
    int e = blockIdx.x*blockDim.x + threadIdx.x;
    if (e >= EE) return;
    int c = e / EC, le = e - c*EC;
    const int* ei = (c==0)?e1:((c==1)?e2:e3);
    int dst = ei[EC + le];
    int src = ei[le];
    int dg = c*NC + dst;
    int p = g_off[dg] + g_part[dg >> 10] + atomicAdd(&g_fill[dg], 1);
    g_esrc[p] = c*NC + src;
}

// ---------------- per-layer aggregation: S[dst] = sum_{src} h[src] ----------
__global__ void k_scatter(){
    int gt = blockIdx.x*blockDim.x + threadIdx.x;
    int node = gt >> 5;
    int lane = gt & 31;
    if (node >= NN) return;
    int o0 = g_off[node] + g_part[node >> 10];
    int n1 = node + 1;
    int o1 = (n1 == NN) ? EE : (g_off[n1] + g_part[n1 >> 10]);
    float a0 = 0.f, a1 = 0.f, a2 = 0.f;
    for (int e = o0; e < o1; e++){
        int s = __ldg(&g_esrc[e]);
        const float* hp = g_h + (size_t)s*HD;
        a0 += hp[lane];
        a1 += hp[lane+32];
        a2 += hp[lane+64];
    }
    float* sp = g_s + (size_t)node*HD;
    sp[lane]    = a0;
    sp[lane+32] = a1;
    sp[lane+64] = a2;
}

// ---------------- fused GRU layer (tensor-core, bf16 3-term split) ----------
// WARM=1: telemetry pass, writes g_s (overwritten by scatter later).
#define SM_AH 0
#define SM_AL 12800
#define SM_WB 25600            // [2 bufs][2 planes][192][9] = 2*3456 words
#define SM_BIAS 32512
#define SM_WORDS 32896         // *4 = 131584 bytes
template<int WARM>
__global__ void __launch_bounds__(256, 1) k_gru(int layer){
    extern __shared__ unsigned smw[];
    unsigned* Ah = smw + SM_AH;
    unsigned* Al = smw + SM_AL;
    unsigned* Wbuf = smw + SM_WB;
    float* sb = (float*)(smw + SM_BIAS);

    const int comp = blockIdx.y;
    const int cl = comp*6 + layer;
    const int row0 = blockIdx.x*128;
    const int tid = threadIdx.x;
    const int lane = tid & 31;
    const int wid = tid >> 5;
    const int wm = wid & 3;          // M group: rows wm*32..
    const int wn = wid >> 2;         // 0..1
    const int lr = lane >> 2;        // 0..7
    const int lq = lane & 3;         // 0..3

    for (int i = tid; i < 384; i += 256) sb[i] = g_bias[cl*384 + i];

    // ---- stage A (S|h) as bf16 hi/lo planes ----
    #pragma unroll 1
    for (int q = 0; q < 24; q++){
        int fidx = tid + 256*q;          // 0..6143 float4s
        int row = fidx / 48;
        int c4 = fidx - row*48;          // float4 col
        float4 v = make_float4(0.f,0.f,0.f,0.f);
        int r = row0 + row;
        if (r < NC){
            size_t base = (size_t)(comp*NC + r)*96;
            v = (c4 < 24) ? *(const float4*)(g_s + base + c4*4)
                          : *(const float4*)(g_h + base + (c4-24)*4);
        }
        unsigned h0 = f2bf(v.x), h1 = f2bf(v.y), h2 = f2bf(v.z), h3 = f2bf(v.w);
        int w = row*100 + c4*2;
        Ah[w]   = h0 | (h1 << 16);
        Ah[w+1] = h2 | (h3 << 16);
        Al[w]   = f2bf(v.x - bfv(h0)) | (f2bf(v.y - bfv(h1)) << 16);
        Al[w+1] = f2bf(v.z - bfv(h2)) | (f2bf(v.w - bfv(h3)) << 16);
    }

    const unsigned* WhG = ((const unsigned*)g_Wbh) + (size_t)cl*36864;
    const unsigned* WlG = ((const unsigned*)g_Wbl) + (size_t)cl*36864;
    float* outp = WARM ? g_s : g_h;

    #pragma unroll 1
    for (int p = 0; p < 2; p++){
        float acc[2][4][3][4];
        #pragma unroll
        for (int mt = 0; mt < 2; mt++)
            #pragma unroll
            for (int g = 0; g < 4; g++)
                #pragma unroll
                for (int t = 0; t < 3; t++)
                    #pragma unroll
                    for (int i = 0; i < 4; i++) acc[mt][g][t][i] = 0.f;

        unsigned rg[12];
        #pragma unroll
        for (int q = 0; q < 12; q++){
            int idx = tid + 256*q;
            int plane = idx / 1536;
            int rw = idx - plane*1536;
            int nrow = rw >> 3, w = rw & 7;
            int n = (nrow/48)*96 + p*48 + (nrow%48);
            rg[q] = __ldg((plane ? WlG : WhG) + n*96 + w);
        }
        __syncthreads();
        #pragma unroll
        for (int q = 0; q < 12; q++){
            int idx = tid + 256*q;
            int plane = idx / 1536;
            int rw = idx - plane*1536;
            Wbuf[plane*1728 + (rw>>3)*9 + (rw&7)] = rg[q];
        }

        #pragma unroll 1
        for (int ks = 0; ks < 12; ks++){
            int buf = ks & 1;
            __syncthreads();
            if (ks < 11){
                #pragma unroll
                for (int q = 0; q < 12; q++){
                    int idx = tid + 256*q;
                    int plane = idx / 1536;
                    int rw = idx - plane*1536;
                    int nrow = rw >> 3, w = rw & 7;
                    int n = (nrow/48)*96 + p*48 + (nrow%48);
                    rg[q] = __ldg((plane ? WlG : WhG) + n*96 + (ks+1)*8 + w);
                }
            }
            unsigned afh[2][4], afl[2][4];
            #pragma unroll
            for (int mt = 0; mt < 2; mt++){
                int base = (wm*32 + mt*16 + lr)*100 + ks*8 + lq;
                afh[mt][0] = Ah[base];     afh[mt][1] = Ah[base + 800];
                afh[mt][2] = Ah[base + 4]; afh[mt][3] = Ah[base + 804];
                afl[mt][0] = Al[base];     afl[mt][1] = Al[base + 800];
                afl[mt][2] = Al[base + 4]; afl[mt][3] = Al[base + 804];
            }
            const unsigned* WB = Wbuf + buf*3456;
            #pragma unroll
            for (int g = 0; g < 4; g++){
                #pragma unroll
                for (int t = 0; t < 3; t++){
                    int nrow = g*48 + wn*24 + t*8 + lr;
                    int wb = nrow*9 + lq;
                    unsigned bh0 = WB[wb],        bh1 = WB[wb + 4];
                    unsigned bl0 = WB[1728 + wb], bl1 = WB[1728 + wb + 4];
                    #pragma unroll
                    for (int mt = 0; mt < 2; mt++){
                        mma16816(acc[mt][g][t], afh[mt], bh0, bh1);
                        mma16816(acc[mt][g][t], afh[mt], bl0, bl1);
                        mma16816(acc[mt][g][t], afl[mt], bh0, bh1);
                    }
                }
            }
            if (ks < 11){
                #pragma unroll
                for (int q = 0; q < 12; q++){
                    int idx = tid + 256*q;
                    int plane = idx / 1536;
                    int rw = idx - plane*1536;
                    Wbuf[(buf^1)*3456 + plane*1728 + (rw>>3)*9 + (rw&7)] = rg[q];
                }
            }
        }
        __syncthreads();

        // ---- epilogue: lean batched-rcp gates, all in registers ----
        #pragma unroll
        for (int mt = 0; mt < 2; mt++){
            #pragma unroll
            for (int t = 0; t < 3; t++){
                int f0 = p*48 + wn*24 + t*8 + 2*lq;
                float bR0 = sb[f0],       bR1 = sb[f0+1];
                float bZ0 = sb[96+f0],    bZ1 = sb[96+f0+1];
                float bI0 = sb[192+f0],   bI1 = sb[192+f0+1];
                float bN0 = sb[288+f0],   bN1 = sb[288+f0+1];
                #pragma unroll
                for (int half = 0; half < 2; half++){
                    int row = wm*32 + mt*16 + lr + half*8;
                    int w = row*100 + 48 + (f0 >> 1);
                    unsigned hw = Ah[w], lw = Al[w];
                    float ho0 = bflo(hw) + bflo(lw);
                    float ho1 = bfhi(hw) + bfhi(lw);
                    int ci = half*2;
                    // pre-activations (log2 domain for sigmoids)
                    float xr0 = fminf(fmaxf((acc[mt][0][t][ci]   + bR0)*L2E, -30.f), 30.f);
                    float xr1 = fminf(fmaxf((acc[mt][0][t][ci+1] + bR1)*L2E, -30.f), 30.f);
                    float xz0 = fminf(fmaxf((acc[mt][1][t][ci]   + bZ0)*L2E, -30.f), 30.f);
                    float xz1 = fminf(fmaxf((acc[mt][1][t][ci+1] + bZ1)*L2E, -30.f), 30.f);
                    float er0 = ex2f(xr0), er1 = ex2f(xr1);
                    float ez0 = ex2f(xz0), ez1 = ex2f(xz1);
                    float d1 = er0 + 1.f, d2 = ez0 + 1.f, d3 = er1 + 1.f, d4 = ez1 + 1.f;
                    float p12 = d1*d2, p34 = d3*d4;
                    float rp = rcpf(p12*p34);
                    float q12 = rp*p34, q34 = rp*p12;
                    float rr0 = er0*(q12*d2), zz0 = ez0*(q12*d1);
                    float rr1 = er1*(q34*d4), zz1 = ez1*(q34*d3);
                    // n = tanh(i + r*hn) = 1 - 2/(e^{2t}+1)
                    float t0 = fmaf(rr0, acc[mt][3][t][ci]   + bN0, acc[mt][2][t][ci]   + bI0);
                    float t1 = fmaf(rr1, acc[mt][3][t][ci+1] + bN1, acc[mt][2][t][ci+1] + bI1);
                    float lt0 = fminf(fmaxf(t0*(2.f*L2E), -30.f), 30.f);
                    float lt1 = fminf(fmaxf(t1*(2.f*L2E), -30.f), 30.f);
                    float e0 = ex2f(lt0), e1 = ex2f(lt1);
                    float dt0 = e0 + 1.f, dt1 = e1 + 1.f;
                    float rpt = rcpf(dt0*dt1);
                    float nn0 = fmaf(-2.f, rpt*dt1, 1.f);
                    float nn1 = fmaf(-2.f, rpt*dt0, 1.f);
                    float o0 = fmaf(zz0, ho0 - nn0, nn0);
                    float o1 = fmaf(zz1, ho1 - nn1, nn1);
                    int r = row0 + row;
                    if (r < NC){
                        float2 st = make_float2(o0, o1);
                        *(float2*)(outp + (size_t)(comp*NC + r)*96 + f0) = st;
                    }
                }
            }
        }
    }
}

// ---------------- pooling: mean of relu(h) over sorted batch ranges ---------
__global__ void k_pool(const int* __restrict__ b1, const int* __restrict__ b2,
                       const int* __restrict__ b3){
    int b = blockIdx.x;
    int c = blockIdx.y;
    const int* batch = (c==0)?b1:((c==1)?b2:b3);
    int lo = 0, hi = NC;
    while (lo < hi){ int m = (lo+hi) >> 1; if (batch[m] < b) lo = m+1; else hi = m; }
    int s0 = lo;
    hi = NC;
    while (lo < hi){ int m = (lo+hi) >> 1; if (batch[m] < b+1) lo = m+1; else hi = m; }
    int e0 = lo;
    float denom = fmaxf((float)(e0 - s0), 1.f);
    int f = threadIdx.x;
    float sum = 0.f;
    for (int n = s0; n < e0; n++)
        sum += fmaxf(g_h[(size_t)(c*NC + n)*HD + f], 0.f);
    g_pool[((size_t)c*NB + b)*HD + f] = sum / denom;
}

// ---------------- feature assembly ------------------------------------------
__global__ void k_feat(){
    int idx = blockIdx.x*blockDim.x + threadIdx.x;
    if (idx >= NB*384) return;
    int b = idx / 384;
    int j = idx - b*384;
    float v;
    if (j < 96)       v = g_pool[(size_t)b*HD + j];
    else if (j < 192) v = g_pool[((size_t)NB + b)*HD + (j-96)];
    else if (j < 288) v = g_pool[((size_t)2*NB + b)*HD + (j-192)];
    else {
        int jj = j - 288;
        v = g_pool[(size_t)b*HD + jj]
          * g_pool[((size_t)NB + b)*HD + jj]
          * g_pool[((size_t)2*NB + b)*HD + jj];
    }
    g_feat[idx] = v;
}

// ---------------- MLP GEMM (globals resolved in device code) ----------------
template<int MODE>
__global__ void __launch_bounds__(256) k_gemm(const float* __restrict__ B,
                                              const float* __restrict__ bias){
    const float* A = (MODE == 0) ? g_feat : g_t1;
    float*       C = (MODE == 0) ? g_t1   : g_t2;
    const int N = (MODE == 0) ? 1536 : 384;
    const int K = (MODE == 0) ? 384  : 1536;

    __shared__ float As[64*33];
    __shared__ float Bs[32*68];
    int txx = threadIdx.x & 15;
    int tyy = threadIdx.x >> 4;
    int m0 = blockIdx.y*64;
    int n0 = blockIdx.x*64;
    float accv[4][4];
    #pragma unroll
    for (int i = 0; i < 4; i++)
        #pragma unroll
        for (int j = 0; j < 4; j++) accv[i][j] = 0.f;

    for (int kc = 0; kc < K; kc += 32){
        __syncthreads();
        for (int i = threadIdx.x; i < 64*32; i += 256){
            int r = i >> 5, k = i & 31;
            As[r*33 + k] = A[(size_t)(m0 + r)*K + kc + k];
        }
        for (int i = threadIdx.x; i < 32*64; i += 256){
            int k = i >> 6, cc = i & 63;
            Bs[k*68 + cc] = B[(size_t)(kc + k)*N + n0 + cc];
        }
        __syncthreads();
        #pragma unroll 8
        for (int k = 0; k < 32; k++){
            float a[4], bb[4];
            #pragma unroll
            for (int i = 0; i < 4; i++) a[i] = As[(tyy*4 + i)*33 + k];
            float4 bv = *(const float4*)&Bs[k*68 + txx*4];
            bb[0] = bv.x; bb[1] = bv.y; bb[2] = bv.z; bb[3] = bv.w;
            #pragma unroll
            for (int i = 0; i < 4; i++)
                #pragma unroll
                for (int j = 0; j < 4; j++)
                    accv[i][j] += a[i]*bb[j];
        }
    }
    #pragma unroll
    for (int i = 0; i < 4; i++){
        int row = m0 + tyy*4 + i;
        #pragma unroll
        for (int j = 0; j < 4; j++){
            int col = n0 + txx*4 + j;
            float v = accv[i][j] + bias[col];
            C[(size_t)row*N + col] = fmaxf(v, 0.f);
        }
    }
}

// ---------------- fc3: [4096,384] @ [384,3] ---------------------------------
__global__ void k_fc3(const float* __restrict__ w, const float* __restrict__ b,
                      float* __restrict__ out){
    int gt = blockIdx.x*blockDim.x + threadIdx.x;
    int row = gt >> 5;
    int lane = gt & 31;
    if (row >= NB) return;
    float a0 = 0.f, a1 = 0.f, a2 = 0.f;
    for (int k = lane; k < 384; k += 32){
        float f = g_t2[(size_t)row*384 + k];
        a0 += f*w[k*3 + 0];
        a1 += f*w[k*3 + 1];
        a2 += f*w[k*3 + 2];
    }
    #pragma unroll
    for (int o = 16; o; o >>= 1){
        a0 += __shfl_down_sync(0xffffffffu, a0, o);
        a1 += __shfl_down_sync(0xffffffffu, a1, o);
        a2 += __shfl_down_sync(0xffffffffu, a2, o);
    }
    if (lane == 0){
        out[row*3 + 0] = a0 + b[0];
        out[row*3 + 1] = a1 + b[1];
        out[row*3 + 2] = a2 + b[2];
    }
}

// ---------------- launch ----------------------------------------------------
extern "C" void kernel_launch(void* const* d_in, const int* in_sizes, int n_in,
                              void* d_out, int out_size) {
    const float* xs[3]   = {0,0,0};
    const int*   es[3]   = {0,0,0};
    const int*   bs[3]   = {0,0,0};
    const float* Ws[3]   = {0,0,0};
    const float* wihs[3] = {0,0,0};
    const float* whhs[3] = {0,0,0};
    const float* bihs[3] = {0,0,0};
    const float* bhhs[3] = {0,0,0};
    const float* fcw[2]  = {0,0};
    const float* fc1b = 0; const float* fc2b = 0;
    const float* fc3w = 0; const float* fc3b = 0;
    int nx=0, ne=0, nb=0, nW=0, nwpair=0, nbpair=0, nfcw=0;
    for (int i = 0; i < n_in; i++){
        int s = in_sizes[i];
        const void* p = d_in[i];
        switch (s){
            case 6400000: if (nx < 3) xs[nx++] = (const float*)p; break;
            case 800000:  if (ne < 3) es[ne++] = (const int*)p;   break;
            case 200000:  if (nb < 3) bs[nb++] = (const int*)p;   break;
            case 55296:   if (nW < 3) Ws[nW++] = (const float*)p; break;
            case 27648:   { int c = nwpair/2;
                            if (c < 3){ if ((nwpair & 1) == 0) wihs[c] = (const float*)p;
                                        else                   whhs[c] = (const float*)p; }
                            nwpair++; } break;
            case 288:     { int c = nbpair/2;
                            if (c < 3){ if ((nbpair & 1) == 0) bihs[c] = (const float*)p;
                                        else                   bhhs[c] = (const float*)p; }
                            nbpair++; } break;
            case 589824:  if (nfcw < 2) fcw[nfcw++] = (const float*)p; break;
            case 1536:    fc1b = (const float*)p; break;
            case 384:     fc2b = (const float*)p; break;
            case 1152:    fc3w = (const float*)p; break;
            case 3:       fc3b = (const float*)p; break;
            default: break;
        }
    }
    const float* fc1w = fcw[0];
    const float* fc2w = fcw[1];
    float* out = (float*)d_out;

    const int gruSmem = SM_WORDS*4;   // 131584 B
    cudaFuncSetAttribute(k_gru<0>, cudaFuncAttributeMaxDynamicSharedMemorySize, gruSmem);
    cudaFuncSetAttribute(k_gru<1>, cudaFuncAttributeMaxDynamicSharedMemorySize, gruSmem);

    // 1: mega init (h0 + counters + W pack + bias pack)
    k_mega<<<MEGA_IB + MEGA_PB + MEGA_BB, 256>>>(
        xs[0], xs[1], xs[2],
        Ws[0], wihs[0], whhs[0], Ws[1], wihs[1], whhs[1], Ws[2], wihs[2], whhs[2],
        bihs[0], bhhs[0], bihs[1], bhhs[1], bihs[2], bhhs[2]);
    // 2-3: CSR histogram + block scan
    k_deg<<<(EE + 255)/256, 256>>>(es[0], es[1], es[2]);
    k_scan1<<<NPART, SCAN_BLK>>>();
    // 4: telemetry warmup GRU (writes g_s; overwritten by scatter below)
    k_gru<1><<<dim3(200, 3), 256, gruSmem>>>(0);
    // 5-6: finish CSR
    k_scan2<<<1, SCAN_BLK>>>();
    k_fill<<<(EE + 255)/256, 256>>>(es[0], es[1], es[2]);

    const int gruBlocks = (NC + 127)/128;   // 1563
    for (int l = 0; l < 6; l++){
        k_scatter<<<(NN*32 + 255)/256, 256>>>();
        k_gru<0><<<dim3(gruBlocks, 3), 256, gruSmem>>>(l);
    }
    k_pool<<<dim3(NB, 3), 96>>>(bs[0], bs[1], bs[2]);
    k_feat<<<(NB*384 + 255)/256, 256>>>();
    k_gemm<0><<<dim3(1536/64, NB/64), 256>>>(fc1w, fc1b);
    k_gemm<1><<<dim3(384/64,  NB/64), 256>>>(fc2w, fc2b);
    k_fc3<<<(NB*32 + 255)/256, 256>>>(fc3w, fc3b, out);
}

// round 7
// speedup vs baseline: 1.3674x; 1.0497x over previous
#include <cuda_runtime.h>
#include <cstdint>

#define NC 200000
#define NCOMP 3
#define NN (NC*NCOMP)
#define EC 400000
#define EE (EC*NCOMP)
#define HD 96
#define NB 4096
#define SCAN_BLK 1024
#define NPART ((NN + SCAN_BLK - 1)/SCAN_BLK)

// ---------------- device scratch (static, no runtime allocation) ----------
__device__ __align__(16) float g_h[(size_t)NN*HD];
__device__ __align__(16) float g_s[(size_t)NN*HD];
__device__ int   g_deg[NN];
__device__ int   g_fill[NN];
__device__ int   g_off[NN+1];
__device__ int   g_esrc[EE];
__device__ int   g_part[SCAN_BLK];
__device__ __align__(16) unsigned short g_Wbh[(size_t)18*384*192]; // bf16 hi, [cl][n][k]
__device__ __align__(16) unsigned short g_Wbl[(size_t)18*384*192]; // bf16 lo
__device__ __align__(16) float g_bias[18*384];        // [cl][ brz(192) | bin(96) | bnh(96) ]
__device__ __align__(16) float g_pool[NCOMP*NB*HD];
__device__ __align__(16) float g_feat[(size_t)NB*384];
__device__ __align__(16) float g_t1[(size_t)NB*1536];
__device__ __align__(16) float g_t2[(size_t)NB*384];

// ---------------- helpers ---------------------------------------------------
__device__ __forceinline__ unsigned f2bf(float x){
    unsigned u = __float_as_uint(x);
    return (u + 0x7fffu + ((u >> 16) & 1u)) >> 16;   // RN-even
}
__device__ __forceinline__ float bfv(unsigned bits16){ return __uint_as_float(bits16 << 16); }
__device__ __forceinline__ float bflo(unsigned w){ return __uint_as_float(w << 16); }
__device__ __forceinline__ float bfhi(unsigned w){ return __uint_as_float(w & 0xffff0000u); }
__device__ __forceinline__ float ex2f(float x){ float y; asm("ex2.approx.f32 %0, %1;" : "=f"(y) : "f"(x)); return y; }
__device__ __forceinline__ float rcpf(float x){ float y; asm("rcp.approx.f32 %0, %1;" : "=f"(y) : "f"(x)); return y; }
#define L2E 1.4426950408889634f

__device__ __forceinline__ void mma16816(float* d, const unsigned* a, unsigned b0, unsigned b1){
    asm volatile(
        "mma.sync.aligned.m16n8k16.row.col.f32.bf16.bf16.f32 "
        "{%0,%1,%2,%3}, {%4,%5,%6,%7}, {%8,%9}, {%0,%1,%2,%3};"
        : "+f"(d[0]), "+f"(d[1]), "+f"(d[2]), "+f"(d[3])
        : "r"(a[0]), "r"(a[1]), "r"(a[2]), "r"(a[3]), "r"(b0), "r"(b1));
}

// ---------------- mega kernel: init h0 + zero counters + pack W + pack bias --
#define MEGA_IB 225000      // (NN*HD)/256
#define MEGA_PB 5184        // 18*73728/256
#define MEGA_BB 27          // ceil(18*384/256)
__global__ void k_mega(
    const float* __restrict__ x1, const float* __restrict__ x2, const float* __restrict__ x3,
    const float* __restrict__ W1, const float* __restrict__ wih1, const float* __restrict__ whh1,
    const float* __restrict__ W2, const float* __restrict__ wih2, const float* __restrict__ whh2,
    const float* __restrict__ W3, const float* __restrict__ wih3, const float* __restrict__ whh3,
    const float* __restrict__ bih1, const float* __restrict__ bhh1,
    const float* __restrict__ bih2, const float* __restrict__ bhh2,
    const float* __restrict__ bih3, const float* __restrict__ bhh3)
{
    int bid = blockIdx.x;
    int tid = threadIdx.x;
    if (bid < MEGA_IB){
        long long idx = (long long)bid*256 + tid;
        int n = (int)(idx / HD);
        int j = (int)(idx - (long long)n*HD);
        int c = n / NC;
        int ln = n - c*NC;
        const float* x = (c==0)?x1:((c==1)?x2:x3);
        g_h[idx] = (j < 32) ? x[(size_t)ln*32 + j] : 0.f;
        if (idx < NN){ g_deg[(int)idx] = 0; g_fill[(int)idx] = 0; }
    } else if (bid < MEGA_IB + MEGA_PB){
        int gid = (bid - MEGA_IB)*256 + tid;     // < 18*73728
        int cl = gid / 73728;
        int rem = gid - cl*73728;
        int c = cl / 6, l = cl % 6;
        const float* W   = (c==0)?W1:((c==1)?W2:W3);
        const float* wih = (c==0)?wih1:((c==1)?wih2:wih3);
        const float* whh = (c==0)?whh1:((c==1)?whh2:whh3);
        int k = rem / 384, j = rem % 384;
        float v = 0.f;
        if (k < 96){
            if (j < 288){
                const float* wr = W + (size_t)(l*96 + k)*96;
                const float* ir = wih + (size_t)j*96;
                float s = 0.f;
                #pragma unroll 8
                for (int t = 0; t < 96; t++) s += wr[t]*ir[t];
                v = s;
            }
        } else {
            int t = k - 96;
            if (j < 192)       v = whh[(size_t)j*96 + t];
            else if (j >= 288) v = whh[(size_t)(j-96)*96 + t];
        }
        unsigned hb = f2bf(v);
        float remv = v - bfv(hb);
        size_t o = (size_t)cl*73728 + (size_t)j*192 + k;
        g_Wbh[o] = (unsigned short)hb;
        g_Wbl[o] = (unsigned short)f2bf(remv);
    } else {
        int id = (bid - MEGA_IB - MEGA_PB)*256 + tid;
        if (id < 18*384){
            int cl = id / 384;
            int j = id - cl*384;
            int c = cl / 6;
            const float* bih = (c==0)?bih1:((c==1)?bih2:bih3);
            const float* bhh = (c==0)?bhh1:((c==1)?bhh2:bhh3);
            float v;
            if (j < 192)      v = bih[j] + bhh[j];
            else if (j < 288) v = bih[192 + (j-192)];
            else              v = bhh[192 + (j-288)];
            g_bias[cl*384 + j] = v;
        }
    }
}

// ---------------- CSR build -------------------------------------------------
__global__ void k_deg(const int* __restrict__ e1, const int* __restrict__ e2,
                      const int* __restrict__ e3){
    int e = blockIdx.x*blockDim.x + threadIdx.x;
    if (e >= EE) return;
    int c = e / EC, le = e - c*EC;
    const int* ei = (c==0)?e1:((c==1)?e2:e3);
    int dst = ei[EC + le];
    atomicAdd(&g_deg[c*NC + dst], 1);
}

__global__ void k_scan1(){
    __shared__ int sm[SCAN_BLK];
    int tid = threadIdx.x;
    int i = blockIdx.x*SCAN_BLK + tid;
    int v = (i < NN) ? g_deg[i] : 0;
    sm[tid] = v;
    __syncthreads();
    for (int off = 1; off < SCAN_BLK; off <<= 1){
        int t = 0;
        if (tid >= off) t = sm[tid - off];
        __syncthreads();
        sm[tid] += t;
        __syncthreads();
    }
    if (i < NN) g_off[i] = sm[tid] - v;
    if (tid == SCAN_BLK-1) g_part[blockIdx.x] = sm[tid];
}

__global__ void k_scan2(){
    __shared__ int sm[SCAN_BLK];
    int tid = threadIdx.x;
    int v = (tid < NPART) ? g_part[tid] : 0;
    sm[tid] = v;
    __syncthreads();
    for (int off = 1; off < SCAN_BLK; off <<= 1){
        int t = 0;
        if (tid >= off) t = sm[tid - off];
        __syncthreads();
        sm[tid] += t;
        __syncthreads();
    }
    if (tid < NPART) g_part[tid] = sm[tid] - v;
}

// fill with scan3 partial-add inlined
__global__ void k_fill(const int* __restrict__ e1, const int* __restrict__ e2,
                       const int* __restrict__ e3){
    int e = blockIdx.x*blockDim.x + threadIdx.x;
    if (e >= EE) return;
    int c = e / EC, le = e - c*EC;
    const int* ei = (c==0)?e1:((c==1)?e2:e3);
    int dst = ei[EC + le];
    int src = ei[le];
    int dg = c*NC + dst;
    int p = g_off[dg] + g_part[dg >> 10] + atomicAdd(&g_fill[dg], 1);
    g_esrc[p] = c*NC + src;
}

// ---------------- per-layer aggregation: S[dst] = sum_{src} h[src] ----------
__global__ void k_scatter(){
    int gt = blockIdx.x*blockDim.x + threadIdx.x;
    int node = gt >> 5;
    int lane = gt & 31;
    if (node >= NN) return;
    int o0 = g_off[node] + g_part[node >> 10];
    int n1 = node + 1;
    int o1 = (n1 == NN) ? EE : (g_off[n1] + g_part[n1 >> 10]);
    float a0 = 0.f, a1 = 0.f, a2 = 0.f;
    for (int e = o0; e < o1; e++){
        int s = __ldg(&g_esrc[e]);
        const float* hp = g_h + (size_t)s*HD;
        a0 += hp[lane];
        a1 += hp[lane+32];
        a2 += hp[lane+64];
    }
    float* sp = g_s + (size_t)node*HD;
    sp[lane]    = a0;
    sp[lane+32] = a1;
    sp[lane+64] = a2;
}

// ---------------- fused GRU layer (tensor-core, bf16 3-term split) ----------
// 512 threads, 16 warps = 8(M, 16 rows each) x 2(N-slice). Two passes p over
// feature halves. Per warp N-tiles = (gate g, t): col = g*96 + p*48 + wn*24 + t*8.
// A = [S(96)|h(96)] bf16 hi/lo planes in smem (stride 100 words/row).
// W k16-chunks double-buffered, [n'][9 words].
// WARM=1: telemetry pass, writes g_s (overwritten by scatter later).
#define SM_AH 0
#define SM_AL 12800
#define SM_WB 25600            // [2 bufs][2 planes][192][9] = 2*3456 words
#define SM_BIAS 32512
#define SM_WORDS 32896         // *4 = 131584 bytes
template<int WARM>
__global__ void __launch_bounds__(512, 1) k_gru(int layer){
    extern __shared__ unsigned smw[];
    unsigned* Ah = smw + SM_AH;
    unsigned* Al = smw + SM_AL;
    unsigned* Wbuf = smw + SM_WB;
    float* sb = (float*)(smw + SM_BIAS);

    const int comp = blockIdx.y;
    const int cl = comp*6 + layer;
    const int row0 = blockIdx.x*128;
    const int tid = threadIdx.x;
    const int lane = tid & 31;
    const int wid = tid >> 5;
    const int wm = wid & 7;          // M group: rows wm*16..+15
    const int wn = wid >> 3;         // 0..1
    const int lr = lane >> 2;        // 0..7
    const int lq = lane & 3;         // 0..3

    for (int i = tid; i < 384; i += 512) sb[i] = g_bias[cl*384 + i];

    // ---- stage A (S|h) as bf16 hi/lo planes ----
    #pragma unroll 1
    for (int q = 0; q < 12; q++){
        int fidx = tid + 512*q;          // 0..6143 float4s
        int row = fidx / 48;
        int c4 = fidx - row*48;          // float4 col
        float4 v = make_float4(0.f,0.f,0.f,0.f);
        int r = row0 + row;
        if (r < NC){
            size_t base = (size_t)(comp*NC + r)*96;
            v = (c4 < 24) ? *(const float4*)(g_s + base + c4*4)
                          : *(const float4*)(g_h + base + (c4-24)*4);
        }
        unsigned h0 = f2bf(v.x), h1 = f2bf(v.y), h2 = f2bf(v.z), h3 = f2bf(v.w);
        int w = row*100 + c4*2;
        Ah[w]   = h0 | (h1 << 16);
        Ah[w+1] = h2 | (h3 << 16);
        Al[w]   = f2bf(v.x - bfv(h0)) | (f2bf(v.y - bfv(h1)) << 16);
        Al[w+1] = f2bf(v.z - bfv(h2)) | (f2bf(v.w - bfv(h3)) << 16);
    }

    const unsigned* WhG = ((const unsigned*)g_Wbh) + (size_t)cl*36864;
    const unsigned* WlG = ((const unsigned*)g_Wbl) + (size_t)cl*36864;
    float* outp = WARM ? g_s : g_h;

    #pragma unroll 1
    for (int p = 0; p < 2; p++){
        float acc[4][3][4];
        #pragma unroll
        for (int g = 0; g < 4; g++)
            #pragma unroll
            for (int t = 0; t < 3; t++)
                #pragma unroll
                for (int i = 0; i < 4; i++) acc[g][t][i] = 0.f;

        unsigned rg[6];
        #pragma unroll
        for (int q = 0; q < 6; q++){
            int idx = tid + 512*q;
            int plane = idx / 1536;
            int rw = idx - plane*1536;
            int nrow = rw >> 3, w = rw & 7;
            int n = (nrow/48)*96 + p*48 + (nrow%48);
            rg[q] = __ldg((plane ? WlG : WhG) + n*96 + w);
        }
        __syncthreads();
        #pragma unroll
        for (int q = 0; q < 6; q++){
            int idx = tid + 512*q;
            int plane = idx / 1536;
            int rw = idx - plane*1536;
            Wbuf[plane*1728 + (rw>>3)*9 + (rw&7)] = rg[q];
        }

        #pragma unroll 1
        for (int ks = 0; ks < 12; ks++){
            int buf = ks & 1;
            __syncthreads();
            if (ks < 11){
                #pragma unroll
                for (int q = 0; q < 6; q++){
                    int idx = tid + 512*q;
                    int plane = idx / 1536;
                    int rw = idx - plane*1536;
                    int nrow = rw >> 3, w = rw & 7;
                    int n = (nrow/48)*96 + p*48 + (nrow%48);
                    rg[q] = __ldg((plane ? WlG : WhG) + n*96 + (ks+1)*8 + w);
                }
            }
            unsigned afh[4], afl[4];
            {
                int base = (wm*16 + lr)*100 + ks*8 + lq;
                afh[0] = Ah[base];     afh[1] = Ah[base + 800];
                afh[2] = Ah[base + 4]; afh[3] = Ah[base + 804];
                afl[0] = Al[base];     afl[1] = Al[base + 800];
                afl[2] = Al[base + 4]; afl[3] = Al[base + 804];
            }
            const unsigned* WB = Wbuf + buf*3456;
            #pragma unroll
            for (int g = 0; g < 4; g++){
                #pragma unroll
                for (int t = 0; t < 3; t++){
                    int nrow = g*48 + wn*24 + t*8 + lr;
                    int wb = nrow*9 + lq;
                    unsigned bh0 = WB[wb],        bh1 = WB[wb + 4];
                    unsigned bl0 = WB[1728 + wb], bl1 = WB[1728 + wb + 4];
                    mma16816(acc[g][t], afh, bh0, bh1);
                    mma16816(acc[g][t], afh, bl0, bl1);
                    mma16816(acc[g][t], afl, bh0, bh1);
                }
            }
            if (ks < 11){
                #pragma unroll
                for (int q = 0; q < 6; q++){
                    int idx = tid + 512*q;
                    int plane = idx / 1536;
                    int rw = idx - plane*1536;
                    Wbuf[(buf^1)*3456 + plane*1728 + (rw>>3)*9 + (rw&7)] = rg[q];
                }
            }
        }
        __syncthreads();

        // ---- epilogue: lean batched-rcp gates, all in registers ----
        #pragma unroll
        for (int t = 0; t < 3; t++){
            int f0 = p*48 + wn*24 + t*8 + 2*lq;
            float bR0 = sb[f0],       bR1 = sb[f0+1];
            float bZ0 = sb[96+f0],    bZ1 = sb[96+f0+1];
            float bI0 = sb[192+f0],   bI1 = sb[192+f0+1];
            float bN0 = sb[288+f0],   bN1 = sb[288+f0+1];
            #pragma unroll
            for (int half = 0; half < 2; half++){
                int row = wm*16 + lr + half*8;
                int w = row*100 + 48 + (f0 >> 1);
                unsigned hw = Ah[w], lw = Al[w];
                float ho0 = bflo(hw) + bflo(lw);
                float ho1 = bfhi(hw) + bfhi(lw);
                int ci = half*2;
                float xr0 = fminf(fmaxf((acc[0][t][ci]   + bR0)*L2E, -30.f), 30.f);
                float xr1 = fminf(fmaxf((acc[0][t][ci+1] + bR1)*L2E, -30.f), 30.f);
                float xz0 = fminf(fmaxf((acc[1][t][ci]   + bZ0)*L2E, -30.f), 30.f);
                float xz1 = fminf(fmaxf((acc[1][t][ci+1] + bZ1)*L2E, -30.f), 30.f);
                float er0 = ex2f(xr0), er1 = ex2f(xr1);
                float ez0 = ex2f(xz0), ez1 = ex2f(xz1);
                float d1 = er0 + 1.f, d2 = ez0 + 1.f, d3 = er1 + 1.f, d4 = ez1 + 1.f;
                float p12 = d1*d2, p34 = d3*d4;
                float rp = rcpf(p12*p34);
                float q12 = rp*p34, q34 = rp*p12;
                float rr0 = er0*(q12*d2), zz0 = ez0*(q12*d1);
                float rr1 = er1*(q34*d4), zz1 = ez1*(q34*d3);
                float t0 = fmaf(rr0, acc[3][t][ci]   + bN0, acc[2][t][ci]   + bI0);
                float t1 = fmaf(rr1, acc[3][t][ci+1] + bN1, acc[2][t][ci+1] + bI1);
                float lt0 = fminf(fmaxf(t0*(2.f*L2E), -30.f), 30.f);
                float lt1 = fminf(fmaxf(t1*(2.f*L2E), -30.f), 30.f);
                float e0 = ex2f(lt0), e1 = ex2f(lt1);
                float dt0 = e0 + 1.f, dt1 = e1 + 1.f;
                float rpt = rcpf(dt0*dt1);
                float nn0 = fmaf(-2.f, rpt*dt1, 1.f);
                float nn1 = fmaf(-2.f, rpt*dt0, 1.f);
                float o0 = fmaf(zz0, ho0 - nn0, nn0);
                float o1 = fmaf(zz1, ho1 - nn1, nn1);
                int r = row0 + row;
                if (r < NC){
                    float2 st = make_float2(o0, o1);
                    *(float2*)(outp + (size_t)(comp*NC + r)*96 + f0) = st;
                }
            }
        }
    }
}

// ---------------- pooling: mean of relu(h) over sorted batch ranges ---------
__global__ void k_pool(const int* __restrict__ b1, const int* __restrict__ b2,
                       const int* __restrict__ b3){
    int b = blockIdx.x;
    int c = blockIdx.y;
    const int* batch = (c==0)?b1:((c==1)?b2:b3);
    int lo = 0, hi = NC;
    while (lo < hi){ int m = (lo+hi) >> 1; if (batch[m] < b) lo = m+1; else hi = m; }
    int s0 = lo;
    hi = NC;
    while (lo < hi){ int m = (lo+hi) >> 1; if (batch[m] < b+1) lo = m+1; else hi = m; }
    int e0 = lo;
    float denom = fmaxf((float)(e0 - s0), 1.f);
    int f = threadIdx.x;
    float sum = 0.f;
    for (int n = s0; n < e0; n++)
        sum += fmaxf(g_h[(size_t)(c*NC + n)*HD + f], 0.f);
    g_pool[((size_t)c*NB + b)*HD + f] = sum / denom;
}

// ---------------- feature assembly ------------------------------------------
__global__ void k_feat(){
    int idx = blockIdx.x*blockDim.x + threadIdx.x;
    if (idx >= NB*384) return;
    int b = idx / 384;
    int j = idx - b*384;
    float v;
    if (j < 96)       v = g_pool[(size_t)b*HD + j];
    else if (j < 192) v = g_pool[((size_t)NB + b)*HD + (j-96)];
    else if (j < 288) v = g_pool[((size_t)2*NB + b)*HD + (j-192)];
    else {
        int jj = j - 288;
        v = g_pool[(size_t)b*HD + jj]
          * g_pool[((size_t)NB + b)*HD + jj]
          * g_pool[((size_t)2*NB + b)*HD + jj];
    }
    g_feat[idx] = v;
}

// ---------------- MLP GEMM (globals resolved in device code) ----------------
template<int MODE>
__global__ void __launch_bounds__(256) k_gemm(const float* __restrict__ B,
                                              const float* __restrict__ bias){
    const float* A = (MODE == 0) ? g_feat : g_t1;
    float*       C = (MODE == 0) ? g_t1   : g_t2;
    const int N = (MODE == 0) ? 1536 : 384;
    const int K = (MODE == 0) ? 384  : 1536;

    __shared__ float As[64*33];
    __shared__ float Bs[32*68];
    int txx = threadIdx.x & 15;
    int tyy = threadIdx.x >> 4;
    int m0 = blockIdx.y*64;
    int n0 = blockIdx.x*64;
    float accv[4][4];
    #pragma unroll
    for (int i = 0; i < 4; i++)
        #pragma unroll
        for (int j = 0; j < 4; j++) accv[i][j] = 0.f;

    for (int kc = 0; kc < K; kc += 32){
        __syncthreads();
        for (int i = threadIdx.x; i < 64*32; i += 256){
            int r = i >> 5, k = i & 31;
            As[r*33 + k] = A[(size_t)(m0 + r)*K + kc + k];
        }
        for (int i = threadIdx.x; i < 32*64; i += 256){
            int k = i >> 6, cc = i & 63;
            Bs[k*68 + cc] = B[(size_t)(kc + k)*N + n0 + cc];
        }
        __syncthreads();
        #pragma unroll 8
        for (int k = 0; k < 32; k++){
            float a[4], bb[4];
            #pragma unroll
            for (int i = 0; i < 4; i++) a[i] = As[(tyy*4 + i)*33 + k];
            float4 bv = *(const float4*)&Bs[k*68 + txx*4];
            bb[0] = bv.x; bb[1] = bv.y; bb[2] = bv.z; bb[3] = bv.w;
            #pragma unroll
            for (int i = 0; i < 4; i++)
                #pragma unroll
                for (int j = 0; j < 4; j++)
                    accv[i][j] += a[i]*bb[j];
        }
    }
    #pragma unroll
    for (int i = 0; i < 4; i++){
        int row = m0 + tyy*4 + i;
        #pragma unroll
        for (int j = 0; j < 4; j++){
            int col = n0 + txx*4 + j;
            float v = accv[i][j] + bias[col];
            C[(size_t)row*N + col] = fmaxf(v, 0.f);
        }
    }
}

// ---------------- fc3: [4096,384] @ [384,3] ---------------------------------
__global__ void k_fc3(const float* __restrict__ w, const float* __restrict__ b,
                      float* __restrict__ out){
    int gt = blockIdx.x*blockDim.x + threadIdx.x;
    int row = gt >> 5;
    int lane = gt & 31;
    if (row >= NB) return;
    float a0 = 0.f, a1 = 0.f, a2 = 0.f;
    for (int k = lane; k < 384; k += 32){
        float f = g_t2[(size_t)row*384 + k];
        a0 += f*w[k*3 + 0];
        a1 += f*w[k*3 + 1];
        a2 += f*w[k*3 + 2];
    }
    #pragma unroll
    for (int o = 16; o; o >>= 1){
        a0 += __shfl_down_sync(0xffffffffu, a0, o);
        a1 += __shfl_down_sync(0xffffffffu, a1, o);
        a2 += __shfl_down_sync(0xffffffffu, a2, o);
    }
    if (lane == 0){
        out[row*3 + 0] = a0 + b[0];
        out[row*3 + 1] = a1 + b[1];
        out[row*3 + 2] = a2 + b[2];
    }
}

// ---------------- launch ----------------------------------------------------
extern "C" void kernel_launch(void* const* d_in, const int* in_sizes, int n_in,
                              void* d_out, int out_size) {
    const float* xs[3]   = {0,0,0};
    const int*   es[3]   = {0,0,0};
    const int*   bs[3]   = {0,0,0};
    const float* Ws[3]   = {0,0,0};
    const float* wihs[3] = {0,0,0};
    const float* whhs[3] = {0,0,0};
    const float* bihs[3] = {0,0,0};
    const float* bhhs[3] = {0,0,0};
    const float* fcw[2]  = {0,0};
    const float* fc1b = 0; const float* fc2b = 0;
    const float* fc3w = 0; const float* fc3b = 0;
    int nx=0, ne=0, nb=0, nW=0, nwpair=0, nbpair=0, nfcw=0;
    for (int i = 0; i < n_in; i++){
        int s = in_sizes[i];
        const void* p = d_in[i];
        switch (s){
            case 6400000: if (nx < 3) xs[nx++] = (const float*)p; break;
            case 800000:  if (ne < 3) es[ne++] = (const int*)p;   break;
            case 200000:  if (nb < 3) bs[nb++] = (const int*)p;   break;
            case 55296:   if (nW < 3) Ws[nW++] = (const float*)p; break;
            case 27648:   { int c = nwpair/2;
                            if (c < 3){ if ((nwpair & 1) == 0) wihs[c] = (const float*)p;
                                        else                   whhs[c] = (const float*)p; }
                            nwpair++; } break;
            case 288:     { int c = nbpair/2;
                            if (c < 3){ if ((nbpair & 1) == 0) bihs[c] = (const float*)p;
                                        else                   bhhs[c] = (const float*)p; }
                            nbpair++; } break;
            case 589824:  if (nfcw < 2) fcw[nfcw++] = (const float*)p; break;
            case 1536:    fc1b = (const float*)p; break;
            case 384:     fc2b = (const float*)p; break;
            case 1152:    fc3w = (const float*)p; break;
            case 3:       fc3b = (const float*)p; break;
            default: break;
        }
    }
    const float* fc1w = fcw[0];
    const float* fc2w = fcw[1];
    float* out = (float*)d_out;

    const int gruSmem = SM_WORDS*4;   // 131584 B
    cudaFuncSetAttribute(k_gru<0>, cudaFuncAttributeMaxDynamicSharedMemorySize, gruSmem);
    cudaFuncSetAttribute(k_gru<1>, cudaFuncAttributeMaxDynamicSharedMemorySize, gruSmem);

    // 1: mega init (h0 + counters + W pack + bias pack)
    k_mega<<<MEGA_IB + MEGA_PB + MEGA_BB, 256>>>(
        xs[0], xs[1], xs[2],
        Ws[0], wihs[0], whhs[0], Ws[1], wihs[1], whhs[1], Ws[2], wihs[2], whhs[2],
        bihs[0], bhhs[0], bihs[1], bhhs[1], bihs[2], bhhs[2]);
    // 2-3: CSR histogram + block scan
    k_deg<<<(EE + 255)/256, 256>>>(es[0], es[1], es[2]);
    k_scan1<<<NPART, SCAN_BLK>>>();
    // 4: telemetry warmup GRU (writes g_s; overwritten by scatter below)
    k_gru<1><<<dim3(200, 3), 512, gruSmem>>>(0);
    // 5-6: finish CSR
    k_scan2<<<1, SCAN_BLK>>>();
    k_fill<<<(EE + 255)/256, 256>>>(es[0], es[1], es[2]);

    const int gruBlocks = (NC + 127)/128;   // 1563
    for (int l = 0; l < 6; l++){
        k_scatter<<<(NN*32 + 255)/256, 256>>>();
        k_gru<0><<<dim3(gruBlocks, 3), 512, gruSmem>>>(l);
    }
    k_pool<<<dim3(NB, 3), 96>>>(bs[0], bs[1], bs[2]);
    k_feat<<<(NB*384 + 255)/256, 256>>>();
    k_gemm<0><<<dim3(1536/64, NB/64), 256>>>(fc1w, fc1b);
    k_gemm<1><<<dim3(384/64,  NB/64), 256>>>(fc2w, fc2b);
    k_fc3<<<(NB*32 + 255)/256, 256>>>(fc3w, fc3b, out);
}

// round 9
// speedup vs baseline: 1.6938x; 1.2387x over previous
#include <cuda_runtime.h>
#include <cstdint>

#define NC 200000
#define NCOMP 3
#define NN (NC*NCOMP)
#define EC 400000
#define EE (EC*NCOMP)
#define HD 96
#define NB 4096
#define SCAN_BLK 1024
#define NPART ((NN + SCAN_BLK - 1)/SCAN_BLK)

// ---------------- device scratch (static, no runtime allocation) ----------
__device__ __align__(16) float g_h[(size_t)NN*HD];
__device__ __align__(16) float g_s[(size_t)NN*HD];
__device__ int   g_deg[NN];
__device__ int   g_fill[NN];
__device__ int   g_off[NN+1];
__device__ int   g_esrc[EE];
__device__ int   g_part[SCAN_BLK];
// W prepacked: [cl(18)][p(2)][chunk(12)][plane(2)][row 192][8 words]
// row n = (row/48)*96 + p*48 + row%48 ; k = chunk*16 + word*2 (bf16 pairs)
__device__ __align__(16) unsigned g_Wp[(size_t)18*73728];
__device__ __align__(16) float g_bias[18*384];   // [cl][ brz(192) | bin(96) | bnh(96) ]
__device__ __align__(16) float g_pool[NCOMP*NB*HD];
__device__ __align__(16) float g_feat[(size_t)NB*384];
__device__ __align__(16) float g_t1[(size_t)NB*1536];
__device__ __align__(16) float g_t2[(size_t)NB*384];

// ---------------- helpers ---------------------------------------------------
__device__ __forceinline__ unsigned f2bf(float x){
    unsigned u = __float_as_uint(x);
    return (u + 0x7fffu + ((u >> 16) & 1u)) >> 16;   // RN-even
}
__device__ __forceinline__ float bfv(unsigned bits16){ return __uint_as_float(bits16 << 16); }
__device__ __forceinline__ float ex2f(float x){ float y; asm("ex2.approx.f32 %0, %1;" : "=f"(y) : "f"(x)); return y; }
__device__ __forceinline__ float rcpf(float x){ float y; asm("rcp.approx.f32 %0, %1;" : "=f"(y) : "f"(x)); return y; }
#define L2E 1.4426950408889634f

__device__ __forceinline__ uint32_t smem_u32(const void* p){
    uint32_t a;
    asm("{ .reg .u64 t; cvta.to.shared.u64 t, %1; cvt.u32.u64 %0, t; }" : "=r"(a) : "l"(p));
    return a;
}
__device__ __forceinline__ void mma16816(float* d, const unsigned* a, unsigned b0, unsigned b1){
    asm volatile(
        "mma.sync.aligned.m16n8k16.row.col.f32.bf16.bf16.f32 "
        "{%0,%1,%2,%3}, {%4,%5,%6,%7}, {%8,%9}, {%0,%1,%2,%3};"
        : "+f"(d[0]), "+f"(d[1]), "+f"(d[2]), "+f"(d[3])
        : "r"(a[0]), "r"(a[1]), "r"(a[2]), "r"(a[3]), "r"(b0), "r"(b1));
}
#define LDSM_X4(r0,r1,r2,r3,addr) \
    asm volatile("ldmatrix.sync.aligned.m8n8.x4.shared.b16 {%0,%1,%2,%3}, [%4];" \
        : "=r"(r0), "=r"(r1), "=r"(r2), "=r"(r3) : "r"(addr))
#define LDSM_X2(r0,r1,addr) \
    asm volatile("ldmatrix.sync.aligned.m8n8.x2.shared.b16 {%0,%1}, [%2];" \
        : "=r"(r0), "=r"(r1) : "r"(addr))

// logical Wpack[k][j]: k<96: (W_l@wih^T)[k][j] (j<288), else 0.
// k>=96: t=k-96: j<192 -> whh[j][t]; 192..288 -> 0; j>=288 -> whh[j-96][t]
__device__ float wval(const float* __restrict__ W, const float* __restrict__ wih,
                      const float* __restrict__ whh, int l, int k, int j){
    if (k < 96){
        if (j >= 288) return 0.f;
        const float* wr = W + (size_t)(l*96 + k)*96;
        const float* ir = wih + (size_t)j*96;
        float s = 0.f;
        #pragma unroll 8
        for (int t = 0; t < 96; t++) s += wr[t]*ir[t];
        return s;
    }
    int t = k - 96;
    if (j < 192) return whh[(size_t)j*96 + t];
    if (j < 288) return 0.f;
    return whh[(size_t)(j-96)*96 + t];
}

// ---------------- mega kernel: init h0 + counters + pack W + pack bias ------
#define MEGA_IB 225000      // (NN*HD)/256
#define MEGA_PB 5184        // 18*73728/256
#define MEGA_BB 27
__global__ void k_mega(
    const float* __restrict__ x1, const float* __restrict__ x2, const float* __restrict__ x3,
    const float* __restrict__ W1, const float* __restrict__ wih1, const float* __restrict__ whh1,
    const float* __restrict__ W2, const float* __restrict__ wih2, const float* __restrict__ whh2,
    const float* __restrict__ W3, const float* __restrict__ wih3, const float* __restrict__ whh3,
    const float* __restrict__ bih1, const float* __restrict__ bhh1,
    const float* __restrict__ bih2, const float* __restrict__ bhh2,
    const float* __restrict__ bih3, const float* __restrict__ bhh3)
{
    int bid = blockIdx.x;
    int tid = threadIdx.x;
    if (bid < MEGA_IB){
        long long idx = (long long)bid*256 + tid;
        int n = (int)(idx / HD);
        int j = (int)(idx - (long long)n*HD);
        int c = n / NC;
        int ln = n - c*NC;
        const float* x = (c==0)?x1:((c==1)?x2:x3);
        g_h[idx] = (j < 32) ? x[(size_t)ln*32 + j] : 0.f;
        if (idx < NN){ g_deg[(int)idx] = 0; g_fill[(int)idx] = 0; }
    } else if (bid < MEGA_IB + MEGA_PB){
        int gid = (bid - MEGA_IB)*256 + tid;      // < 18*73728
        int cl = gid / 73728;
        int r  = gid - cl*73728;
        int p  = r / 36864;
        int r2 = r - p*36864;
        int chunk = r2 / 3072;
        int r3 = r2 - chunk*3072;
        int plane = r3 / 1536;
        int w  = r3 - plane*1536;
        int row = w >> 3, wk = w & 7;
        int c = cl / 6, l = cl % 6;
        const float* W   = (c==0)?W1:((c==1)?W2:W3);
        const float* wih = (c==0)?wih1:((c==1)?wih2:wih3);
        const float* whh = (c==0)?whh1:((c==1)?whh2:whh3);
        int n = (row/48)*96 + p*48 + (row%48);
        int k = chunk*16 + wk*2;
        float v0 = wval(W, wih, whh, l, k, n);
        float v1 = wval(W, wih, whh, l, k+1, n);
        unsigned h0 = f2bf(v0), h1 = f2bf(v1);
        unsigned word;
        if (plane == 0) word = h0 | (h1 << 16);
        else            word = f2bf(v0 - bfv(h0)) | (f2bf(v1 - bfv(h1)) << 16);
        g_Wp[(size_t)gid] = word;
    } else {
        int id = (bid - MEGA_IB - MEGA_PB)*256 + tid;
        if (id < 18*384){
            int cl = id / 384;
            int j = id - cl*384;
            int c = cl / 6;
            const float* bih = (c==0)?bih1:((c==1)?bih2:bih3);
            const float* bhh = (c==0)?bhh1:((c==1)?bhh2:bhh3);
            float v;
            if (j < 192)      v = bih[j] + bhh[j];
            else if (j < 288) v = bih[192 + (j-192)];
            else              v = bhh[192 + (j-288)];
            g_bias[cl*384 + j] = v;
        }
    }
}

// ---------------- CSR build -------------------------------------------------
__global__ void k_deg(const int* __restrict__ e1, const int* __restrict__ e2,
                      const int* __restrict__ e3){
    int e = blockIdx.x*blockDim.x + threadIdx.x;
    if (e >= EE) return;
    int c = e / EC, le = e - c*EC;
    const int* ei = (c==0)?e1:((c==1)?e2:e3);
    atomicAdd(&g_deg[c*NC + ei[EC + le]], 1);
}

__global__ void k_scan1(){
    __shared__ int sm[SCAN_BLK];
    int tid = threadIdx.x;
    int i = blockIdx.x*SCAN_BLK + tid;
    int v = (i < NN) ? g_deg[i] : 0;
    sm[tid] = v;
    __syncthreads();
    for (int off = 1; off < SCAN_BLK; off <<= 1){
        int t = 0;
        if (tid >= off) t = sm[tid - off];
        __syncthreads();
        sm[tid] += t;
        __syncthreads();
    }
    if (i < NN) g_off[i] = sm[tid] - v;
    if (tid == SCAN_BLK-1) g_part[blockIdx.x] = sm[tid];
}

__global__ void k_scan2(){
    __shared__ int sm[SCAN_BLK];
    int tid = threadIdx.x;
    int v = (tid < NPART) ? g_part[tid] : 0;
    sm[tid] = v;
    __syncthreads();
    for (int off = 1; off < SCAN_BLK; off <<= 1){
        int t = 0;
        if (tid >= off) t = sm[tid - off];
        __syncthreads();
        sm[tid] += t;
        __syncthreads();
    }
    if (tid < NPART) g_part[tid] = sm[tid] - v;
}

__global__ void k_fill(const int* __restrict__ e1, const int* __restrict__ e2,
                       const int* __restrict__ e3){
    int e = blockIdx.x*blockDim.x + threadIdx.x;
    if (e >= EE) return;
    int c = e / EC, le = e - c*EC;
    const int* ei = (c==0)?e1:((c==1)?e2:e3);
    int dst = ei[EC + le];
    int src = ei[le];
    int dg = c*NC + dst;
    int p = g_off[dg] + g_part[dg >> 10] + atomicAdd(&g_fill[dg], 1);
    g_esrc[p] = c*NC + src;
}

// ---------------- per-layer aggregation: S[dst] = sum_{src} h[src] ----------
__global__ void k_scatter(){
    int gt = blockIdx.x*blockDim.x + threadIdx.x;
    int node = gt >> 5;
    int lane = gt & 31;
    if (node >= NN) return;
    int o0 = g_off[node] + g_part[node >> 10];
    int n1 = node + 1;
    int o1 = (n1 == NN) ? EE : (g_off[n1] + g_part[n1 >> 10]);
    float a0 = 0.f, a1 = 0.f, a2 = 0.f;
    for (int e = o0; e < o1; e++){
        int s = __ldg(&g_esrc[e]);
        const float* hp = g_h + (size_t)s*HD;
        a0 += hp[lane];
        a1 += hp[lane+32];
        a2 += hp[lane+64];
    }
    float* sp = g_s + (size_t)node*HD;
    sp[lane]    = a0;
    sp[lane+32] = a1;
    sp[lane+64] = a2;
}

// ---------------- fused GRU layer (mma.sync + ldmatrix, bf16 3-term) --------
// 512 threads, 16 warps = 8(M, 16 rows) x 2(N-slice). Two passes p over
// feature halves. Warp N-tiles: col = g*96 + p*48 + wn*24 + t*8 (t=0..2).
// A = [S(96)|h(96)] bf16 hi/lo in smem, 100-word row stride, LDSM.x4 loads.
// W k16-chunks double-buffered: [plane][192 rows][48B stride], LDSM non-trans.
#define BIAS_OFF 0            // 1536 B
#define A_HI_OFF 2048         // 51200 B (128 rows x 100 words)
#define A_LO_OFF 53248
#define WB_OFF   104448       // 2 bufs x 2 planes x 192 rows x 48 B = 36864 B
#define WB_BUF   18432
#define WB_PLANE 9216
#define SMEM_GRU_TOTAL 141312
template<int WARM>
__global__ void __launch_bounds__(512, 1) k_gru(int layer){
    extern __shared__ char smc[];
    const uint32_t smb = smem_u32(smc);
    float* sb = (float*)(smc + BIAS_OFF);

    const int comp = blockIdx.y;
    const int cl = comp*6 + layer;
    const int row0 = blockIdx.x*128;
    const int tid = threadIdx.x;
    const int lane = tid & 31;
    const int wid = tid >> 5;
    const int wm = wid & 7;          // rows wm*16..+15
    const int wn = wid >> 3;         // 0..1
    const int lr = lane >> 2;        // 0..7
    const int lq = lane & 3;         // 0..3

    for (int i = tid; i < 384; i += 512) sb[i] = g_bias[cl*384 + i];

    // ---- stage A (S|h) as bf16 hi/lo planes, 100-word row stride ----
    #pragma unroll 1
    for (int q = 0; q < 12; q++){
        int fidx = tid + 512*q;          // 0..6143 float4s
        int row = fidx / 48;
        int c4 = fidx - row*48;
        float4 v = make_float4(0.f,0.f,0.f,0.f);
        int r = row0 + row;
        if (r < NC){
            size_t base = (size_t)(comp*NC + r)*96;
            v = (c4 < 24) ? *(const float4*)(g_s + base + c4*4)
                          : *(const float4*)(g_h + base + (c4-24)*4);
        }
        unsigned h0 = f2bf(v.x), h1 = f2bf(v.y), h2 = f2bf(v.z), h3 = f2bf(v.w);
        int w = (row*100 + c4*2)*4;
        *(unsigned*)(smc + A_HI_OFF + w)     = h0 | (h1 << 16);
        *(unsigned*)(smc + A_HI_OFF + w + 4) = h2 | (h3 << 16);
        *(unsigned*)(smc + A_LO_OFF + w)     = f2bf(v.x - bfv(h0)) | (f2bf(v.y - bfv(h1)) << 16);
        *(unsigned*)(smc + A_LO_OFF + w + 4) = f2bf(v.z - bfv(h2)) | (f2bf(v.w - bfv(h3)) << 16);
    }

    float* outp = WARM ? g_s : g_h;
    // per-warp ldmatrix base addresses
    const uint32_t a_h = smb + A_HI_OFF +
        ((wm*16 + (lane & 15))*100 + ((lane >> 4) << 2))*4;
    const uint32_t a_l = a_h + (A_LO_OFF - A_HI_OFF);
    const uint32_t b_x4off = ((wn*24 + ((lane >> 4) << 3) + (lane & 7))*48) + (((lane >> 3) & 1) << 4);
    const uint32_t b_x2off = ((wn*24 + 16 + (lane & 7))*48) + (((lane >> 3) & 1) << 4);

    #pragma unroll 1
    for (int p = 0; p < 2; p++){
        float acc[4][3][4];
        #pragma unroll
        for (int g = 0; g < 4; g++)
            #pragma unroll
            for (int t = 0; t < 3; t++)
                #pragma unroll
                for (int i = 0; i < 4; i++) acc[g][t][i] = 0.f;

        const uint4* wsrc0 = (const uint4*)(g_Wp + ((size_t)(cl*2 + p)*12)*3072);
        uint4 rg0, rg1;
        // prefetch chunk 0
        rg0 = wsrc0[tid];
        if (tid < 256) rg1 = wsrc0[512 + tid];
        __syncthreads();
        {
            int idx = tid;
            int plane = idx / 384, rh = idx - plane*384;
            *(uint4*)(smc + WB_OFF + plane*WB_PLANE + (rh>>1)*48 + (rh&1)*16) = rg0;
            if (tid < 256){
                idx = 512 + tid;
                plane = idx / 384; rh = idx - plane*384;
                *(uint4*)(smc + WB_OFF + plane*WB_PLANE + (rh>>1)*48 + (rh&1)*16) = rg1;
            }
        }

        #pragma unroll 1
        for (int ks = 0; ks < 12; ks++){
            int buf = ks & 1;
            __syncthreads();
            if (ks < 11){
                const uint4* wsrc = wsrc0 + (ks+1)*768;
                rg0 = wsrc[tid];
                if (tid < 256) rg1 = wsrc[512 + tid];
            }
            // A fragments
            unsigned afh[4], afl[4];
            LDSM_X4(afh[0], afh[1], afh[2], afh[3], a_h + ks*32);
            LDSM_X4(afl[0], afl[1], afl[2], afl[3], a_l + ks*32);
            const uint32_t wb0 = smb + WB_OFF + buf*WB_BUF;
            // plane hi: Ah*Bh + Al*Bh
            unsigned bf[4][6];
            #pragma unroll
            for (int g = 0; g < 4; g++){
                uint32_t nb = wb0 + g*48*48;
                LDSM_X4(bf[g][0], bf[g][1], bf[g][2], bf[g][3], nb + b_x4off);
                LDSM_X2(bf[g][4], bf[g][5], nb + b_x2off);
            }
            #pragma unroll
            for (int g = 0; g < 4; g++)
                #pragma unroll
                for (int t = 0; t < 3; t++){
                    mma16816(acc[g][t], afh, bf[g][2*t], bf[g][2*t+1]);
                    mma16816(acc[g][t], afl, bf[g][2*t], bf[g][2*t+1]);
                }
            // plane lo: Ah*Bl
            #pragma unroll
            for (int g = 0; g < 4; g++){
                uint32_t nb = wb0 + WB_PLANE + g*48*48;
                LDSM_X4(bf[g][0], bf[g][1], bf[g][2], bf[g][3], nb + b_x4off);
                LDSM_X2(bf[g][4], bf[g][5], nb + b_x2off);
            }
            #pragma unroll
            for (int g = 0; g < 4; g++)
                #pragma unroll
                for (int t = 0; t < 3; t++)
                    mma16816(acc[g][t], afh, bf[g][2*t], bf[g][2*t+1]);

            if (ks < 11){
                int idx = tid;
                int plane = idx / 384, rh = idx - plane*384;
                *(uint4*)(smc + WB_OFF + (buf^1)*WB_BUF + plane*WB_PLANE + (rh>>1)*48 + (rh&1)*16) = rg0;
                if (tid < 256){
                    idx = 512 + tid;
                    plane = idx / 384; rh = idx - plane*384;
                    *(uint4*)(smc + WB_OFF + (buf^1)*WB_BUF + plane*WB_PLANE + (rh>>1)*48 + (rh&1)*16) = rg1;
                }
            }
        }
        __syncthreads();

        // ---- epilogue: lean batched-rcp gates ----
        #pragma unroll
        for (int t = 0; t < 3; t++){
            int f0 = p*48 + wn*24 + t*8 + 2*lq;
            float bR0 = sb[f0],       bR1 = sb[f0+1];
            float bZ0 = sb[96+f0],    bZ1 = sb[96+f0+1];
            float bI0 = sb[192+f0],   bI1 = sb[192+f0+1];
            float bN0 = sb[288+f0],   bN1 = sb[288+f0+1];
            #pragma unroll
            for (int half = 0; half < 2; half++){
                int row = wm*16 + lr + half*8;
                int r = row0 + row;
                bool ok = (r < NC);
                size_t base = (size_t)(comp*NC + r)*96;
                float2 hv = make_float2(0.f, 0.f);
                if (ok) hv = *(const float2*)(g_h + base + f0);
                int ci = half*2;
                float xr0 = fminf(fmaxf((acc[0][t][ci]   + bR0)*L2E, -30.f), 30.f);
                float xr1 = fminf(fmaxf((acc[0][t][ci+1] + bR1)*L2E, -30.f), 30.f);
                float xz0 = fminf(fmaxf((acc[1][t][ci]   + bZ0)*L2E, -30.f), 30.f);
                float xz1 = fminf(fmaxf((acc[1][t][ci+1] + bZ1)*L2E, -30.f), 30.f);
                float er0 = ex2f(xr0), er1 = ex2f(xr1);
                float ez0 = ex2f(xz0), ez1 = ex2f(xz1);
                float d1 = er0 + 1.f, d2 = ez0 + 1.f, d3 = er1 + 1.f, d4 = ez1 + 1.f;
                float p12 = d1*d2, p34 = d3*d4;
                float rp = rcpf(p12*p34);
                float q12 = rp*p34, q34 = rp*p12;
                float rr0 = er0*(q12*d2), zz0 = ez0*(q12*d1);
                float rr1 = er1*(q34*d4), zz1 = ez1*(q34*d3);
                float t0 = fmaf(rr0, acc[3][t][ci]   + bN0, acc[2][t][ci]   + bI0);
                float t1 = fmaf(rr1, acc[3][t][ci+1] + bN1, acc[2][t][ci+1] + bI1);
                float lt0 = fminf(fmaxf(t0*(2.f*L2E), -30.f), 30.f);
                float lt1 = fminf(fmaxf(t1*(2.f*L2E), -30.f), 30.f);
                float e0 = ex2f(lt0), e1 = ex2f(lt1);
                float dt0 = e0 + 1.f, dt1 = e1 + 1.f;
                float rpt = rcpf(dt0*dt1);
                float nn0 = fmaf(-2.f, rpt*dt1, 1.f);
                float nn1 = fmaf(-2.f, rpt*dt0, 1.f);
                float o0 = fmaf(zz0, hv.x - nn0, nn0);
                float o1 = fmaf(zz1, hv.y - nn1, nn1);
                if (ok) *(float2*)(outp + base + f0) = make_float2(o0, o1);
            }
        }
        if (p == 0) __syncthreads();   // protect Wbuf before next pass refill
    }
}

// ---------------- pooling: mean of relu(h) over sorted batch ranges ---------
__global__ void k_pool(const int* __restrict__ b1, const int* __restrict__ b2,
                       const int* __restrict__ b3){
    int b = blockIdx.x;
    int c = blockIdx.y;
    const int* batch = (c==0)?b1:((c==1)?b2:b3);
    int lo = 0, hi = NC;
    while (lo < hi){ int m = (lo+hi) >> 1; if (batch[m] < b) lo = m+1; else hi = m; }
    int s0 = lo;
    hi = NC;
    while (lo < hi){ int m = (lo+hi) >> 1; if (batch[m] < b+1) lo = m+1; else hi = m; }
    int e0 = lo;
    float denom = fmaxf((float)(e0 - s0), 1.f);
    int f = threadIdx.x;
    float sum = 0.f;
    for (int n = s0; n < e0; n++)
        sum += fmaxf(g_h[(size_t)(c*NC + n)*HD + f], 0.f);
    g_pool[((size_t)c*NB + b)*HD + f] = sum / denom;
}

// ---------------- feature assembly ------------------------------------------
__global__ void k_feat(){
    int idx = blockIdx.x*blockDim.x + threadIdx.x;
    if (idx >= NB*384) return;
    int b = idx / 384;
    int j = idx - b*384;
    float v;
    if (j < 96)       v = g_pool[(size_t)b*HD + j];
    else if (j < 192) v = g_pool[((size_t)NB + b)*HD + (j-96)];
    else if (j < 288) v = g_pool[((size_t)2*NB + b)*HD + (j-192)];
    else {
        int jj = j - 288;
        v = g_pool[(size_t)b*HD + jj]
          * g_pool[((size_t)NB + b)*HD + jj]
          * g_pool[((size_t)2*NB + b)*HD + jj];
    }
    g_feat[idx] = v;
}

// ---------------- MLP GEMM (globals resolved in device code) ----------------
template<int MODE>
__global__ void __launch_bounds__(256) k_gemm(const float* __restrict__ B,
                                              const float* __restrict__ bias){
    const float* A = (MODE == 0) ? g_feat : g_t1;
    float*       C = (MODE == 0) ? g_t1   : g_t2;
    const int N = (MODE == 0) ? 1536 : 384;
    const int K = (MODE == 0) ? 384  : 1536;

    __shared__ float As[64*33];
    __shared__ float Bs[32*68];
    int txx = threadIdx.x & 15;
    int tyy = threadIdx.x >> 4;
    int m0 = blockIdx.y*64;
    int n0 = blockIdx.x*64;
    float accv[4][4];
    #pragma unroll
    for (int i = 0; i < 4; i++)
        #pragma unroll
        for (int j = 0; j < 4; j++) accv[i][j] = 0.f;

    for (int kc = 0; kc < K; kc += 32){
        __syncthreads();
        for (int i = threadIdx.x; i < 64*32; i += 256){
            int r = i >> 5, k = i & 31;
            As[r*33 + k] = A[(size_t)(m0 + r)*K + kc + k];
        }
        for (int i = threadIdx.x; i < 32*64; i += 256){
            int k = i >> 6, cc = i & 63;
            Bs[k*68 + cc] = B[(size_t)(kc + k)*N + n0 + cc];
        }
        __syncthreads();
        #pragma unroll 8
        for (int k = 0; k < 32; k++){
            float a[4], bb[4];
            #pragma unroll
            for (int i = 0; i < 4; i++) a[i] = As[(tyy*4 + i)*33 + k];
            float4 bv = *(const float4*)&Bs[k*68 + txx*4];
            bb[0] = bv.x; bb[1] = bv.y; bb[2] = bv.z; bb[3] = bv.w;
            #pragma unroll
            for (int i = 0; i < 4; i++)
                #pragma unroll
                for (int j = 0; j < 4; j++)
                    accv[i][j] += a[i]*bb[j];
        }
    }
    #pragma unroll
    for (int i = 0; i < 4; i++){
        int row = m0 + tyy*4 + i;
        #pragma unroll
        for (int j = 0; j < 4; j++){
            int col = n0 + txx*4 + j;
            float v = accv[i][j] + bias[col];
            C[(size_t)row*N + col] = fmaxf(v, 0.f);
        }
    }
}

// ---------------- fc3: [4096,384] @ [384,3] ---------------------------------
__global__ void k_fc3(const float* __restrict__ w, const float* __restrict__ b,
                      float* __restrict__ out){
    int gt = blockIdx.x*blockDim.x + threadIdx.x;
    int row = gt >> 5;
    int lane = gt & 31;
    if (row >= NB) return;
    float a0 = 0.f, a1 = 0.f, a2 = 0.f;
    for (int k = lane; k < 384; k += 32){
        float f = g_t2[(size_t)row*384 + k];
        a0 += f*w[k*3 + 0];
        a1 += f*w[k*3 + 1];
        a2 += f*w[k*3 + 2];
    }
    #pragma unroll
    for (int o = 16; o; o >>= 1){
        a0 += __shfl_down_sync(0xffffffffu, a0, o);
        a1 += __shfl_down_sync(0xffffffffu, a1, o);
        a2 += __shfl_down_sync(0xffffffffu, a2, o);
    }
    if (lane == 0){
        out[row*3 + 0] = a0 + b[0];
        out[row*3 + 1] = a1 + b[1];
        out[row*3 + 2] = a2 + b[2];
    }
}

// ---------------- launch ----------------------------------------------------
extern "C" void kernel_launch(void* const* d_in, const int* in_sizes, int n_in,
                              void* d_out, int out_size) {
    const float* xs[3]   = {0,0,0};
    const int*   es[3]   = {0,0,0};
    const int*   bs[3]   = {0,0,0};
    const float* Ws[3]   = {0,0,0};
    const float* wihs[3] = {0,0,0};
    const float* whhs[3] = {0,0,0};
    const float* bihs[3] = {0,0,0};
    const float* bhhs[3] = {0,0,0};
    const float* fcw[2]  = {0,0};
    const float* fc1b = 0; const float* fc2b = 0;
    const float* fc3w = 0; const float* fc3b = 0;
    int nx=0, ne=0, nb=0, nW=0, nwpair=0, nbpair=0, nfcw=0;
    for (int i = 0; i < n_in; i++){
        int s = in_sizes[i];
        const void* p = d_in[i];
        switch (s){
            case 6400000: if (nx < 3) xs[nx++] = (const float*)p; break;
            case 800000:  if (ne < 3) es[ne++] = (const int*)p;   break;
            case 200000:  if (nb < 3) bs[nb++] = (const int*)p;   break;
            case 55296:   if (nW < 3) Ws[nW++] = (const float*)p; break;
            case 27648:   { int c = nwpair/2;
                            if (c < 3){ if ((nwpair & 1) == 0) wihs[c] = (const float*)p;
                                        else                   whhs[c] = (const float*)p; }
                            nwpair++; } break;
            case 288:     { int c = nbpair/2;
                            if (c < 3){ if ((nbpair & 1) == 0) bihs[c] = (const float*)p;
                                        else                   bhhs[c] = (const float*)p; }
                            nbpair++; } break;
            case 589824:  if (nfcw < 2) fcw[nfcw++] = (const float*)p; break;
            case 1536:    fc1b = (const float*)p; break;
            case 384:     fc2b = (const float*)p; break;
            case 1152:    fc3w = (const float*)p; break;
            case 3:       fc3b = (const float*)p; break;
            default: break;
        }
    }
    const float* fc1w = fcw[0];
    const float* fc2w = fcw[1];
    float* out = (float*)d_out;

    cudaFuncSetAttribute(k_gru<0>, cudaFuncAttributeMaxDynamicSharedMemorySize, SMEM_GRU_TOTAL);
    cudaFuncSetAttribute(k_gru<1>, cudaFuncAttributeMaxDynamicSharedMemorySize, SMEM_GRU_TOTAL);

    // 1: mega init (h0 + counters + W prepack + bias pack)
    k_mega<<<MEGA_IB + MEGA_PB + MEGA_BB, 256>>>(
        xs[0], xs[1], xs[2],
        Ws[0], wihs[0], whhs[0], Ws[1], wihs[1], whhs[1], Ws[2], wihs[2], whhs[2],
        bihs[0], bhhs[0], bihs[1], bhhs[1], bihs[2], bhhs[2]);
    // 2-3: CSR histogram + block scan
    k_deg<<<(EE + 255)/256, 256>>>(es[0], es[1], es[2]);
    k_scan1<<<NPART, SCAN_BLK>>>();
    // 4: telemetry warmup GRU (writes g_s; overwritten by scatter below)
    k_gru<1><<<dim3(200, 3), 512, SMEM_GRU_TOTAL>>>(0);
    // 5-6: finish CSR
    k_scan2<<<1, SCAN_BLK>>>();
    k_fill<<<(EE + 255)/256, 256>>>(es[0], es[1], es[2]);

    const int gruBlocks = (NC + 127)/128;   // 1563
    for (int l = 0; l < 6; l++){
        k_scatter<<<(NN*32 + 255)/256, 256>>>();
        k_gru<0><<<dim3(gruBlocks, 3), 512, SMEM_GRU_TOTAL>>>(l);
    }
    k_pool<<<dim3(NB, 3), 96>>>(bs[0], bs[1], bs[2]);
    k_feat<<<(NB*384 + 255)/256, 256>>>();
    k_gemm<0><<<dim3(1536/64, NB/64), 256>>>(fc1w, fc1b);
    k_gemm<1><<<dim3(384/64,  NB/64), 256>>>(fc2w, fc2b);
    k_fc3<<<(NB*32 + 255)/256, 256>>>(fc3w, fc3b, out);
}

// round 10
// speedup vs baseline: 1.8599x; 1.0981x over previous
#include <cuda_runtime.h>
#include <cstdint>

#define NC 200000
#define NCOMP 3
#define NN (NC*NCOMP)
#define EC 400000
#define EE (EC*NCOMP)
#define HD 96
#define NB 4096
#define SCAN_BLK 1024
#define NPART ((NN + SCAN_BLK - 1)/SCAN_BLK)

// ---------------- device scratch (static, no runtime allocation) ----------
__device__ __align__(16) float g_h[(size_t)NN*HD];   // ping buffer (h0, even-layer in)
__device__ __align__(16) float g_s[(size_t)NN*HD];   // pong buffer
__device__ int   g_deg[NN];
__device__ int   g_fill[NN];
__device__ int   g_off[NN+1];
__device__ int   g_esrc[EE];
__device__ int   g_part[SCAN_BLK];
// W prepacked: [cl(18)][p(2)][chunk(12)][plane(2)][row 192][8 words]
// row n = (row/48)*96 + p*48 + row%48 ; k = chunk*16 + word*2 (bf16 pairs)
__device__ __align__(16) unsigned g_Wp[(size_t)18*73728];
__device__ __align__(16) float g_bias[18*384];   // [cl][ brz(192) | bin(96) | bnh(96) ]
__device__ __align__(16) float g_pool[NCOMP*NB*HD];
__device__ __align__(16) float g_feat[(size_t)NB*384];
__device__ __align__(16) float g_t1[(size_t)NB*1536];
__device__ __align__(16) float g_t2[(size_t)NB*384];

// ---------------- helpers ---------------------------------------------------
__device__ __forceinline__ unsigned f2bf(float x){
    unsigned u = __float_as_uint(x);
    return (u + 0x7fffu + ((u >> 16) & 1u)) >> 16;   // RN-even
}
__device__ __forceinline__ float bfv(unsigned bits16){ return __uint_as_float(bits16 << 16); }
__device__ __forceinline__ void pack2(float x, float y, unsigned &hi, unsigned &lo){
    unsigned hx = f2bf(x), hy = f2bf(y);
    hi = hx | (hy << 16);
    lo = f2bf(x - bfv(hx)) | (f2bf(y - bfv(hy)) << 16);
}
__device__ __forceinline__ float ex2f(float x){ float y; asm("ex2.approx.f32 %0, %1;" : "=f"(y) : "f"(x)); return y; }
__device__ __forceinline__ float rcpf(float x){ float y; asm("rcp.approx.f32 %0, %1;" : "=f"(y) : "f"(x)); return y; }
#define L2E 1.4426950408889634f

__device__ __forceinline__ uint32_t smem_u32(const void* p){
    uint32_t a;
    asm("{ .reg .u64 t; cvta.to.shared.u64 t, %1; cvt.u32.u64 %0, t; }" : "=r"(a) : "l"(p));
    return a;
}
__device__ __forceinline__ void mma16816(float* d, const unsigned* a, unsigned b0, unsigned b1){
    asm volatile(
        "mma.sync.aligned.m16n8k16.row.col.f32.bf16.bf16.f32 "
        "{%0,%1,%2,%3}, {%4,%5,%6,%7}, {%8,%9}, {%0,%1,%2,%3};"
        : "+f"(d[0]), "+f"(d[1]), "+f"(d[2]), "+f"(d[3])
        : "r"(a[0]), "r"(a[1]), "r"(a[2]), "r"(a[3]), "r"(b0), "r"(b1));
}
#define LDSM_X4(r0,r1,r2,r3,addr) \
    asm volatile("ldmatrix.sync.aligned.m8n8.x4.shared.b16 {%0,%1,%2,%3}, [%4];" \
        : "=r"(r0), "=r"(r1), "=r"(r2), "=r"(r3) : "r"(addr))
#define LDSM_X2(r0,r1,addr) \
    asm volatile("ldmatrix.sync.aligned.m8n8.x2.shared.b16 {%0,%1}, [%2];" \
        : "=r"(r0), "=r"(r1) : "r"(addr))

// logical Wpack[k][j]: k<96: (W_l@wih^T)[k][j] (j<288), else 0.
// k>=96: t=k-96: j<192 -> whh[j][t]; 192..288 -> 0; j>=288 -> whh[j-96][t]
__device__ float wval(const float* __restrict__ W, const float* __restrict__ wih,
                      const float* __restrict__ whh, int l, int k, int j){
    if (k < 96){
        if (j >= 288) return 0.f;
        const float* wr = W + (size_t)(l*96 + k)*96;
        const float* ir = wih + (size_t)j*96;
        float s = 0.f;
        #pragma unroll 8
        for (int t = 0; t < 96; t++) s += wr[t]*ir[t];
        return s;
    }
    int t = k - 96;
    if (j < 192) return whh[(size_t)j*96 + t];
    if (j < 288) return 0.f;
    return whh[(size_t)(j-96)*96 + t];
}

// ---------------- mega kernel: init h0 + counters + pack W + pack bias ------
#define MEGA_IB 225000      // (NN*HD)/256
#define MEGA_PB 5184        // 18*73728/256
#define MEGA_BB 27
__global__ void k_mega(
    const float* __restrict__ x1, const float* __restrict__ x2, const float* __restrict__ x3,
    const float* __restrict__ W1, const float* __restrict__ wih1, const float* __restrict__ whh1,
    const float* __restrict__ W2, const float* __restrict__ wih2, const float* __restrict__ whh2,
    const float* __restrict__ W3, const float* __restrict__ wih3, const float* __restrict__ whh3,
    const float* __restrict__ bih1, const float* __restrict__ bhh1,
    const float* __restrict__ bih2, const float* __restrict__ bhh2,
    const float* __restrict__ bih3, const float* __restrict__ bhh3)
{
    int bid = blockIdx.x;
    int tid = threadIdx.x;
    if (bid < MEGA_IB){
        long long idx = (long long)bid*256 + tid;
        int n = (int)(idx / HD);
        int j = (int)(idx - (long long)n*HD);
        int c = n / NC;
        int ln = n - c*NC;
        const float* x = (c==0)?x1:((c==1)?x2:x3);
        g_h[idx] = (j < 32) ? x[(size_t)ln*32 + j] : 0.f;
        if (idx < NN){ g_deg[(int)idx] = 0; g_fill[(int)idx] = 0; }
    } else if (bid < MEGA_IB + MEGA_PB){
        int gid = (bid - MEGA_IB)*256 + tid;      // < 18*73728
        int cl = gid / 73728;
        int r  = gid - cl*73728;
        int p  = r / 36864;
        int r2 = r - p*36864;
        int chunk = r2 / 3072;
        int r3 = r2 - chunk*3072;
        int plane = r3 / 1536;
        int w  = r3 - plane*1536;
        int row = w >> 3, wk = w & 7;
        int c = cl / 6, l = cl % 6;
        const float* W   = (c==0)?W1:((c==1)?W2:W3);
        const float* wih = (c==0)?wih1:((c==1)?wih2:wih3);
        const float* whh = (c==0)?whh1:((c==1)?whh2:whh3);
        int n = (row/48)*96 + p*48 + (row%48);
        int k = chunk*16 + wk*2;
        float v0 = wval(W, wih, whh, l, k, n);
        float v1 = wval(W, wih, whh, l, k+1, n);
        unsigned hi, lo;
        pack2(v0, v1, hi, lo);
        g_Wp[(size_t)gid] = plane ? lo : hi;
    } else {
        int id = (bid - MEGA_IB - MEGA_PB)*256 + tid;
        if (id < 18*384){
            int cl = id / 384;
            int j = id - cl*384;
            int c = cl / 6;
            const float* bih = (c==0)?bih1:((c==1)?bih2:bih3);
            const float* bhh = (c==0)?bhh1:((c==1)?bhh2:bhh3);
            float v;
            if (j < 192)      v = bih[j] + bhh[j];
            else if (j < 288) v = bih[192 + (j-192)];
            else              v = bhh[192 + (j-288)];
            g_bias[cl*384 + j] = v;
        }
    }
}

// ---------------- CSR build -------------------------------------------------
__global__ void k_deg(const int* __restrict__ e1, const int* __restrict__ e2,
                      const int* __restrict__ e3){
    int e = blockIdx.x*blockDim.x + threadIdx.x;
    if (e >= EE) return;
    int c = e / EC, le = e - c*EC;
    const int* ei = (c==0)?e1:((c==1)?e2:e3);
    atomicAdd(&g_deg[c*NC + ei[EC + le]], 1);
}

__global__ void k_scan1(){
    __shared__ int sm[SCAN_BLK];
    int tid = threadIdx.x;
    int i = blockIdx.x*SCAN_BLK + tid;
    int v = (i < NN) ? g_deg[i] : 0;
    sm[tid] = v;
    __syncthreads();
    for (int off = 1; off < SCAN_BLK; off <<= 1){
        int t = 0;
        if (tid >= off) t = sm[tid - off];
        __syncthreads();
        sm[tid] += t;
        __syncthreads();
    }
    if (i < NN) g_off[i] = sm[tid] - v;
    if (tid == SCAN_BLK-1) g_part[blockIdx.x] = sm[tid];
}

__global__ void k_scan2(){
    __shared__ int sm[SCAN_BLK];
    int tid = threadIdx.x;
    int v = (tid < NPART) ? g_part[tid] : 0;
    sm[tid] = v;
    __syncthreads();
    for (int off = 1; off < SCAN_BLK; off <<= 1){
        int t = 0;
        if (tid >= off) t = sm[tid - off];
        __syncthreads();
        sm[tid] += t;
        __syncthreads();
    }
    if (tid < NPART) g_part[tid] = sm[tid] - v;
}

__global__ void k_fill(const int* __restrict__ e1, const int* __restrict__ e2,
                       const int* __restrict__ e3){
    int e = blockIdx.x*blockDim.x + threadIdx.x;
    if (e >= EE) return;
    int c = e / EC, le = e - c*EC;
    const int* ei = (c==0)?e1:((c==1)?e2:e3);
    int dst = ei[EC + le];
    int src = ei[le];
    int dg = c*NC + dst;
    int p = g_off[dg] + g_part[dg >> 10] + atomicAdd(&g_fill[dg], 1);
    g_esrc[p] = c*NC + src;
}

// ---------------- fused GRU layer: gather + mma.sync(ldmatrix) + gates -------
// 64 rows/block, 256 threads (8 warps = 4M x 2N), 2 CTAs/SM.
// Ping-pong: layer l reads hin=buf[l%2], writes hout=buf[(l+1)%2].
// A = [S(96)|h(96)] bf16 hi/lo, 100-word row stride. S gathered in-kernel.
// W k16-chunks double-buffered: [plane][192 rows][48B stride], LDSM non-trans.
#define BIAS_OFF 0            // 1536 B
#define A_HI_OFF 1536         // 64 rows x 400 B = 25600
#define A_LO_OFF 27136
#define WB_OFF   52736        // 2 bufs x 18432
#define WB_BUF   18432
#define WB_PLANE 9216
#define SMEM_GRU_TOTAL 89600
template<int WARM>
__global__ void __launch_bounds__(256, 2) k_gru(int layer){
    extern __shared__ char smc[];
    const uint32_t smb = smem_u32(smc);
    float* sb = (float*)(smc + BIAS_OFF);

    const int comp = blockIdx.y;
    const int cl = comp*6 + layer;
    const int row0 = blockIdx.x*64;
    const int tid = threadIdx.x;
    const int lane = tid & 31;
    const int wid = tid >> 5;
    const int wm = wid & 3;          // rows wm*16..+15
    const int wn = wid >> 2;         // 0..1
    const int lr = lane >> 2;        // 0..7
    const int lq = lane & 3;         // 0..3

    for (int i = tid; i < 384; i += 256) sb[i] = g_bias[cl*384 + i];

    const float* hin  = WARM ? g_h : ((layer & 1) ? g_s : g_h);
    float*       hout = WARM ? g_s : ((layer & 1) ? g_h : g_s);

    // ---- fused gather + stage A (bf16 hi/lo, 100-word row stride) ----
    {
        unsigned* Ahw = (unsigned*)(smc + A_HI_OFF);
        unsigned* Alw = (unsigned*)(smc + A_LO_OFF);
        int rbase = wid*8;
        #pragma unroll 1
        for (int rr = 0; rr < 8; rr++){
            int row = rbase + rr;
            int node = comp*NC + row0 + row;
            float2 s0 = make_float2(0.f, 0.f);
            float2 s1 = make_float2(0.f, 0.f);
            if (!WARM){
                int o0 = g_off[node] + g_part[node >> 10];
                int n1 = node + 1;
                int o1 = (n1 == NN) ? EE : (g_off[n1] + g_part[n1 >> 10]);
                for (int e = o0; e < o1; e++){
                    int s = __ldg(&g_esrc[e]);
                    const float2* hp = (const float2*)(hin + (size_t)s*96);
                    float2 v0 = __ldg(hp + lane);
                    s0.x += v0.x; s0.y += v0.y;
                    if (lane < 16){
                        float2 v1 = __ldg(hp + 32 + lane);
                        s1.x += v1.x; s1.y += v1.y;
                    }
                }
            }
            const float2* hr = (const float2*)(hin + (size_t)node*96);
            float2 h0 = hr[lane];
            int wb = row*100;
            unsigned hi, lo;
            pack2(s0.x, s0.y, hi, lo);
            Ahw[wb + lane] = hi;  Alw[wb + lane] = lo;
            pack2(h0.x, h0.y, hi, lo);
            Ahw[wb + 48 + lane] = hi;  Alw[wb + 48 + lane] = lo;
            if (lane < 16){
                float2 h1 = hr[32 + lane];
                pack2(s1.x, s1.y, hi, lo);
                Ahw[wb + 32 + lane] = hi;  Alw[wb + 32 + lane] = lo;
                pack2(h1.x, h1.y, hi, lo);
                Ahw[wb + 80 + lane] = hi;  Alw[wb + 80 + lane] = lo;
            }
        }
    }

    // per-warp ldmatrix base addresses
    const uint32_t a_h = smb + A_HI_OFF +
        ((wm*16 + (lane & 15))*100 + ((lane >> 4) << 2))*4;
    const uint32_t a_l = a_h + (A_LO_OFF - A_HI_OFF);
    const uint32_t b_x4off = ((wn*24 + ((lane >> 4) << 3) + (lane & 7))*48) + (((lane >> 3) & 1) << 4);
    const uint32_t b_x2off = ((wn*24 + 16 + (lane & 7))*48) + (((lane >> 3) & 1) << 4);

    #pragma unroll 1
    for (int p = 0; p < 2; p++){
        float acc[4][3][4];
        #pragma unroll
        for (int g = 0; g < 4; g++)
            #pragma unroll
            for (int t = 0; t < 3; t++)
                #pragma unroll
                for (int i = 0; i < 4; i++) acc[g][t][i] = 0.f;

        const uint4* wsrc0 = (const uint4*)(g_Wp + ((size_t)(cl*2 + p)*12)*3072);
        uint4 rg[3];
        // prefetch chunk 0 (768 uint4 / 256 threads = 3 each)
        #pragma unroll
        for (int q = 0; q < 3; q++) rg[q] = wsrc0[tid + 256*q];
        __syncthreads();
        #pragma unroll
        for (int q = 0; q < 3; q++){
            int idx = tid + 256*q;
            int plane = idx / 384, rh = idx - plane*384;
            *(uint4*)(smc + WB_OFF + plane*WB_PLANE + (rh>>1)*48 + (rh&1)*16) = rg[q];
        }

        #pragma unroll 1
        for (int ks = 0; ks < 12; ks++){
            int buf = ks & 1;
            __syncthreads();
            if (ks < 11){
                const uint4* wsrc = wsrc0 + (ks+1)*768;
                #pragma unroll
                for (int q = 0; q < 3; q++) rg[q] = wsrc[tid + 256*q];
            }
            // A fragments
            unsigned afh[4], afl[4];
            LDSM_X4(afh[0], afh[1], afh[2], afh[3], a_h + ks*32);
            LDSM_X4(afl[0], afl[1], afl[2], afl[3], a_l + ks*32);
            const uint32_t wb0 = smb + WB_OFF + buf*WB_BUF;
            // plane hi: Ah*Bh + Al*Bh
            unsigned bf[4][6];
            #pragma unroll
            for (int g = 0; g < 4; g++){
                uint32_t nb = wb0 + g*48*48;
                LDSM_X4(bf[g][0], bf[g][1], bf[g][2], bf[g][3], nb + b_x4off);
                LDSM_X2(bf[g][4], bf[g][5], nb + b_x2off);
            }
            #pragma unroll
            for (int g = 0; g < 4; g++)
                #pragma unroll
                for (int t = 0; t < 3; t++){
                    mma16816(acc[g][t], afh, bf[g][2*t], bf[g][2*t+1]);
                    mma16816(acc[g][t], afl, bf[g][2*t], bf[g][2*t+1]);
                }
            // plane lo: Ah*Bl
            #pragma unroll
            for (int g = 0; g < 4; g++){
                uint32_t nb = wb0 + WB_PLANE + g*48*48;
                LDSM_X4(bf[g][0], bf[g][1], bf[g][2], bf[g][3], nb + b_x4off);
                LDSM_X2(bf[g][4], bf[g][5], nb + b_x2off);
            }
            #pragma unroll
            for (int g = 0; g < 4; g++)
                #pragma unroll
                for (int t = 0; t < 3; t++)
                    mma16816(acc[g][t], afh, bf[g][2*t], bf[g][2*t+1]);

            if (ks < 11){
                #pragma unroll
                for (int q = 0; q < 3; q++){
                    int idx = tid + 256*q;
                    int plane = idx / 384, rh = idx - plane*384;
                    *(uint4*)(smc + WB_OFF + (buf^1)*WB_BUF + plane*WB_PLANE + (rh>>1)*48 + (rh&1)*16) = rg[q];
                }
            }
        }
        __syncthreads();

        // ---- epilogue: lean batched-rcp gates ----
        #pragma unroll
        for (int t = 0; t < 3; t++){
            int f0 = p*48 + wn*24 + t*8 + 2*lq;
            float bR0 = sb[f0],       bR1 = sb[f0+1];
            float bZ0 = sb[96+f0],    bZ1 = sb[96+f0+1];
            float bI0 = sb[192+f0],   bI1 = sb[192+f0+1];
            float bN0 = sb[288+f0],   bN1 = sb[288+f0+1];
            #pragma unroll
            for (int half = 0; half < 2; half++){
                int row = wm*16 + lr + half*8;
                size_t base = (size_t)(comp*NC + row0 + row)*96;
                float2 hv = *(const float2*)(hin + base + f0);
                int ci = half*2;
                float xr0 = fminf(fmaxf((acc[0][t][ci]   + bR0)*L2E, -30.f), 30.f);
                float xr1 = fminf(fmaxf((acc[0][t][ci+1] + bR1)*L2E, -30.f), 30.f);
                float xz0 = fminf(fmaxf((acc[1][t][ci]   + bZ0)*L2E, -30.f), 30.f);
                float xz1 = fminf(fmaxf((acc[1][t][ci+1] + bZ1)*L2E, -30.f), 30.f);
                float er0 = ex2f(xr0), er1 = ex2f(xr1);
                float ez0 = ex2f(xz0), ez1 = ex2f(xz1);
                float d1 = er0 + 1.f, d2 = ez0 + 1.f, d3 = er1 + 1.f, d4 = ez1 + 1.f;
                float p12 = d1*d2, p34 = d3*d4;
                float rp = rcpf(p12*p34);
                float q12 = rp*p34, q34 = rp*p12;
                float rr0 = er0*(q12*d2), zz0 = ez0*(q12*d1);
                float rr1 = er1*(q34*d4), zz1 = ez1*(q34*d3);
                float t0 = fmaf(rr0, acc[3][t][ci]   + bN0, acc[2][t][ci]   + bI0);
                float t1 = fmaf(rr1, acc[3][t][ci+1] + bN1, acc[2][t][ci+1] + bI1);
                float lt0 = fminf(fmaxf(t0*(2.f*L2E), -30.f), 30.f);
                float lt1 = fminf(fmaxf(t1*(2.f*L2E), -30.f), 30.f);
                float e0 = ex2f(lt0), e1 = ex2f(lt1);
                float dt0 = e0 + 1.f, dt1 = e1 + 1.f;
                float rpt = rcpf(dt0*dt1);
                float nn0 = fmaf(-2.f, rpt*dt1, 1.f);
                float nn1 = fmaf(-2.f, rpt*dt0, 1.f);
                float o0 = fmaf(zz0, hv.x - nn0, nn0);
                float o1 = fmaf(zz1, hv.y - nn1, nn1);
                *(float2*)(hout + base + f0) = make_float2(o0, o1);
            }
        }
        if (p == 0) __syncthreads();   // protect Wbuf before next pass refill
    }
}

// ---------------- pooling: mean of relu(h) over sorted batch ranges ---------
__global__ void k_pool(const int* __restrict__ b1, const int* __restrict__ b2,
                       const int* __restrict__ b3){
    int b = blockIdx.x;
    int c = blockIdx.y;
    const int* batch = (c==0)?b1:((c==1)?b2:b3);
    int lo = 0, hi = NC;
    while (lo < hi){ int m = (lo+hi) >> 1; if (batch[m] < b) lo = m+1; else hi = m; }
    int s0 = lo;
    hi = NC;
    while (lo < hi){ int m = (lo+hi) >> 1; if (batch[m] < b+1) lo = m+1; else hi = m; }
    int e0 = lo;
    float denom = fmaxf((float)(e0 - s0), 1.f);
    int f = threadIdx.x;
    float sum = 0.f;
    for (int n = s0; n < e0; n++)
        sum += fmaxf(g_h[(size_t)(c*NC + n)*HD + f], 0.f);
    g_pool[((size_t)c*NB + b)*HD + f] = sum / denom;
}

// ---------------- feature assembly ------------------------------------------
__global__ void k_feat(){
    int idx = blockIdx.x*blockDim.x + threadIdx.x;
    if (idx >= NB*384) return;
    int b = idx / 384;
    int j = idx - b*384;
    float v;
    if (j < 96)       v = g_pool[(size_t)b*HD + j];
    else if (j < 192) v = g_pool[((size_t)NB + b)*HD + (j-96)];
    else if (j < 288) v = g_pool[((size_t)2*NB + b)*HD + (j-192)];
    else {
        int jj = j - 288;
        v = g_pool[(size_t)b*HD + jj]
          * g_pool[((size_t)NB + b)*HD + jj]
          * g_pool[((size_t)2*NB + b)*HD + jj];
    }
    g_feat[idx] = v;
}

// ---------------- MLP GEMM (globals resolved in device code) ----------------
template<int MODE>
__global__ void __launch_bounds__(256) k_gemm(const float* __restrict__ B,
                                              const float* __restrict__ bias){
    const float* A = (MODE == 0) ? g_feat : g_t1;
    float*       C = (MODE == 0) ? g_t1   : g_t2;
    const int N = (MODE == 0) ? 1536 : 384;
    const int K = (MODE == 0) ? 384  : 1536;

    __shared__ float As[64*33];
    __shared__ float Bs[32*68];
    int txx = threadIdx.x & 15;
    int tyy = threadIdx.x >> 4;
    int m0 = blockIdx.y*64;
    int n0 = blockIdx.x*64;
    float accv[4][4];
    #pragma unroll
    for (int i = 0; i < 4; i++)
        #pragma unroll
        for (int j = 0; j < 4; j++) accv[i][j] = 0.f;

    for (int kc = 0; kc < K; kc += 32){
        __syncthreads();
        for (int i = threadIdx.x; i < 64*32; i += 256){
            int r = i >> 5, k = i & 31;
            As[r*33 + k] = A[(size_t)(m0 + r)*K + kc + k];
        }
        for (int i = threadIdx.x; i < 32*64; i += 256){
            int k = i >> 6, cc = i & 63;
            Bs[k*68 + cc] = B[(size_t)(kc + k)*N + n0 + cc];
        }
        __syncthreads();
        #pragma unroll 8
        for (int k = 0; k < 32; k++){
            float a[4], bb[4];
            #pragma unroll
            for (int i = 0; i < 4; i++) a[i] = As[(tyy*4 + i)*33 + k];
            float4 bv = *(const float4*)&Bs[k*68 + txx*4];
            bb[0] = bv.x; bb[1] = bv.y; bb[2] = bv.z; bb[3] = bv.w;
            #pragma unroll
            for (int i = 0; i < 4; i++)
                #pragma unroll
                for (int j = 0; j < 4; j++)
                    accv[i][j] += a[i]*bb[j];
        }
    }
    #pragma unroll
    for (int i = 0; i < 4; i++){
        int row = m0 + tyy*4 + i;
        #pragma unroll
        for (int j = 0; j < 4; j++){
            int col = n0 + txx*4 + j;
            float v = accv[i][j] + bias[col];
            C[(size_t)row*N + col] = fmaxf(v, 0.f);
        }
    }
}

// ---------------- fc3: [4096,384] @ [384,3] ---------------------------------
__global__ void k_fc3(const float* __restrict__ w, const float* __restrict__ b,
                      float* __restrict__ out){
    int gt = blockIdx.x*blockDim.x + threadIdx.x;
    int row = gt >> 5;
    int lane = gt & 31;
    if (row >= NB) return;
    float a0 = 0.f, a1 = 0.f, a2 = 0.f;
    for (int k = lane; k < 384; k += 32){
        float f = g_t2[(size_t)row*384 + k];
        a0 += f*w[k*3 + 0];
        a1 += f*w[k*3 + 1];
        a2 += f*w[k*3 + 2];
    }
    #pragma unroll
    for (int o = 16; o; o >>= 1){
        a0 += __shfl_down_sync(0xffffffffu, a0, o);
        a1 += __shfl_down_sync(0xffffffffu, a1, o);
        a2 += __shfl_down_sync(0xffffffffu, a2, o);
    }
    if (lane == 0){
        out[row*3 + 0] = a0 + b[0];
        out[row*3 + 1] = a1 + b[1];
        out[row*3 + 2] = a2 + b[2];
    }
}

// ---------------- launch ----------------------------------------------------
extern "C" void kernel_launch(void* const* d_in, const int* in_sizes, int n_in,
                              void* d_out, int out_size) {
    const float* xs[3]   = {0,0,0};
    const int*   es[3]   = {0,0,0};
    const int*   bs[3]   = {0,0,0};
    const float* Ws[3]   = {0,0,0};
    const float* wihs[3] = {0,0,0};
    const float* whhs[3] = {0,0,0};
    const float* bihs[3] = {0,0,0};
    const float* bhhs[3] = {0,0,0};
    const float* fcw[2]  = {0,0};
    const float* fc1b = 0; const float* fc2b = 0;
    const float* fc3w = 0; const float* fc3b = 0;
    int nx=0, ne=0, nb=0, nW=0, nwpair=0, nbpair=0, nfcw=0;
    for (int i = 0; i < n_in; i++){
        int s = in_sizes[i];
        const void* p = d_in[i];
        switch (s){
            case 6400000: if (nx < 3) xs[nx++] = (const float*)p; break;
            case 800000:  if (ne < 3) es[ne++] = (const int*)p;   break;
            case 200000:  if (nb < 3) bs[nb++] = (const int*)p;   break;
            case 55296:   if (nW < 3) Ws[nW++] = (const float*)p; break;
            case 27648:   { int c = nwpair/2;
                            if (c < 3){ if ((nwpair & 1) == 0) wihs[c] = (const float*)p;
                                        else                   whhs[c] = (const float*)p; }
                            nwpair++; } break;
            case 288:     { int c = nbpair/2;
                            if (c < 3){ if ((nbpair & 1) == 0) bihs[c] = (const float*)p;
                                        else                   bhhs[c] = (const float*)p; }
                            nbpair++; } break;
            case 589824:  if (nfcw < 2) fcw[nfcw++] = (const float*)p; break;
            case 1536:    fc1b = (const float*)p; break;
            case 384:     fc2b = (const float*)p; break;
            case 1152:    fc3w = (const float*)p; break;
            case 3:       fc3b = (const float*)p; break;
            default: break;
        }
    }
    const float* fc1w = fcw[0];
    const float* fc2w = fcw[1];
    float* out = (float*)d_out;

    cudaFuncSetAttribute(k_gru<0>, cudaFuncAttributeMaxDynamicSharedMemorySize, SMEM_GRU_TOTAL);
    cudaFuncSetAttribute(k_gru<1>, cudaFuncAttributeMaxDynamicSharedMemorySize, SMEM_GRU_TOTAL);

    // 1: mega init (h0 + counters + W prepack + bias pack)
    k_mega<<<MEGA_IB + MEGA_PB + MEGA_BB, 256>>>(
        xs[0], xs[1], xs[2],
        Ws[0], wihs[0], whhs[0], Ws[1], wihs[1], whhs[1], Ws[2], wihs[2], whhs[2],
        bihs[0], bhhs[0], bihs[1], bhhs[1], bihs[2], bhhs[2]);
    // 2-3: CSR histogram + block scan
    k_deg<<<(EE + 255)/256, 256>>>(es[0], es[1], es[2]);
    k_scan1<<<NPART, SCAN_BLK>>>();
    // 4: telemetry warmup GRU (no gather; writes g_s, overwritten by layer 0)
    k_gru<1><<<dim3(200, 3), 256, SMEM_GRU_TOTAL>>>(0);
    // 5-6: finish CSR
    k_scan2<<<1, SCAN_BLK>>>();
    k_fill<<<(EE + 255)/256, 256>>>(es[0], es[1], es[2]);

    const int gruBlocks = NC/64;   // 3125
    for (int l = 0; l < 6; l++)
        k_gru<0><<<dim3(gruBlocks, 3), 256, SMEM_GRU_TOTAL>>>(l);

    k_pool<<<dim3(NB, 3), 96>>>(bs[0], bs[1], bs[2]);
    k_feat<<<(NB*384 + 255)/256, 256>>>();
    k_gemm<0><<<dim3(1536/64, NB/64), 256>>>(fc1w, fc1b);
    k_gemm<1><<<dim3(384/64,  NB/64), 256>>>(fc2w, fc2b);
    k_fc3<<<(NB*32 + 255)/256, 256>>>(fc3w, fc3b, out);
}

// round 11
// speedup vs baseline: 2.0802x; 1.1185x over previous
#include <cuda_runtime.h>
#include <cstdint>

#define NC 200000
#define NCOMP 3
#define NN (NC*NCOMP)
#define EC 400000
#define EE (EC*NCOMP)
#define HD 96
#define NB 4096
#define SCAN_BLK 1024
#define NPART ((NN + SCAN_BLK - 1)/SCAN_BLK)

// ---------------- device scratch (static, no runtime allocation) ----------
__device__ __align__(16) float g_h[(size_t)NN*HD];   // ping buffer (h0, even-layer in)
__device__ __align__(16) float g_s[(size_t)NN*HD];   // pong buffer
__device__ int   g_deg[NN];
__device__ int   g_fill[NN];
__device__ int   g_off[NN+1];
__device__ int   g_esrc[EE];
__device__ int   g_part[SCAN_BLK];
// W prepacked with zero-blocks ELIDED:
// [cl(18)][p(2)][chunk(12)][plane(2)][row 144][8 words]
// row: gi=row/48, rloc=row%48 ; nbase = gi==0?0 : gi==1?96 : (chunk<6?192:288)
// n = nbase + p*48 + rloc ; k = chunk*16 + word*2 (bf16 pairs)
__device__ __align__(16) unsigned g_Wp[(size_t)18*55296];
__device__ __align__(16) float g_bias[18*384];   // [cl][ brz(192) | bin(96) | bnh(96) ]
__device__ __align__(16) float g_pool[NCOMP*NB*HD];
__device__ __align__(16) float g_feat[(size_t)NB*384];
__device__ __align__(16) float g_t1[(size_t)NB*1536];
__device__ __align__(16) float g_t2[(size_t)NB*384];

// ---------------- helpers ---------------------------------------------------
__device__ __forceinline__ unsigned f2bf(float x){
    unsigned u = __float_as_uint(x);
    return (u + 0x7fffu + ((u >> 16) & 1u)) >> 16;   // RN-even
}
__device__ __forceinline__ float bfv(unsigned bits16){ return __uint_as_float(bits16 << 16); }
__device__ __forceinline__ float bflo(unsigned w){ return __uint_as_float(w << 16); }
__device__ __forceinline__ float bfhi(unsigned w){ return __uint_as_float(w & 0xffff0000u); }
__device__ __forceinline__ void pack2(float x, float y, unsigned &hi, unsigned &lo){
    unsigned hx = f2bf(x), hy = f2bf(y);
    hi = hx | (hy << 16);
    lo = f2bf(x - bfv(hx)) | (f2bf(y - bfv(hy)) << 16);
}
__device__ __forceinline__ float ex2f(float x){ float y; asm("ex2.approx.f32 %0, %1;" : "=f"(y) : "f"(x)); return y; }
__device__ __forceinline__ float rcpf(float x){ float y; asm("rcp.approx.f32 %0, %1;" : "=f"(y) : "f"(x)); return y; }
#define L2E 1.4426950408889634f

__device__ __forceinline__ uint32_t smem_u32(const void* p){
    uint32_t a;
    asm("{ .reg .u64 t; cvta.to.shared.u64 t, %1; cvt.u32.u64 %0, t; }" : "=r"(a) : "l"(p));
    return a;
}
__device__ __forceinline__ void mma16816(float* d, const unsigned* a, unsigned b0, unsigned b1){
    asm volatile(
        "mma.sync.aligned.m16n8k16.row.col.f32.bf16.bf16.f32 "
        "{%0,%1,%2,%3}, {%4,%5,%6,%7}, {%8,%9}, {%0,%1,%2,%3};"
        : "+f"(d[0]), "+f"(d[1]), "+f"(d[2]), "+f"(d[3])
        : "r"(a[0]), "r"(a[1]), "r"(a[2]), "r"(a[3]), "r"(b0), "r"(b1));
}
#define LDSM_X4(r0,r1,r2,r3,addr) \
    asm volatile("ldmatrix.sync.aligned.m8n8.x4.shared.b16 {%0,%1,%2,%3}, [%4];" \
        : "=r"(r0), "=r"(r1), "=r"(r2), "=r"(r3) : "r"(addr))
#define LDSM_X2(r0,r1,addr) \
    asm volatile("ldmatrix.sync.aligned.m8n8.x2.shared.b16 {%0,%1}, [%2];" \
        : "=r"(r0), "=r"(r1) : "r"(addr))

// logical Wpack[k][j]: k<96: (W_l@wih^T)[k][j] ; k>=96: t=k-96:
// j<192 -> whh[j][t]; j>=288 -> whh[j-96][t]   (zero blocks never requested)
__device__ float wval(const float* __restrict__ W, const float* __restrict__ wih,
                      const float* __restrict__ whh, int l, int k, int j){
    if (k < 96){
        const float* wr = W + (size_t)(l*96 + k)*96;
        const float* ir = wih + (size_t)j*96;
        float s = 0.f;
        #pragma unroll 8
        for (int t = 0; t < 96; t++) s += wr[t]*ir[t];
        return s;
    }
    int t = k - 96;
    if (j < 192) return whh[(size_t)j*96 + t];
    return whh[(size_t)(j-96)*96 + t];
}

// ---------------- mega kernel: init h0 + counters + pack W + pack bias ------
#define MEGA_IB 225000      // (NN*HD)/256
#define MEGA_PB 3888        // 18*55296/256
#define MEGA_BB 27
__global__ void k_mega(
    const float* __restrict__ x1, const float* __restrict__ x2, const float* __restrict__ x3,
    const float* __restrict__ W1, const float* __restrict__ wih1, const float* __restrict__ whh1,
    const float* __restrict__ W2, const float* __restrict__ wih2, const float* __restrict__ whh2,
    const float* __restrict__ W3, const float* __restrict__ wih3, const float* __restrict__ whh3,
    const float* __restrict__ bih1, const float* __restrict__ bhh1,
    const float* __restrict__ bih2, const float* __restrict__ bhh2,
    const float* __restrict__ bih3, const float* __restrict__ bhh3)
{
    int bid = blockIdx.x;
    int tid = threadIdx.x;
    if (bid < MEGA_IB){
        long long idx = (long long)bid*256 + tid;
        int n = (int)(idx / HD);
        int j = (int)(idx - (long long)n*HD);
        int c = n / NC;
        int ln = n - c*NC;
        const float* x = (c==0)?x1:((c==1)?x2:x3);
        g_h[idx] = (j < 32) ? x[(size_t)ln*32 + j] : 0.f;
        if (idx < NN){ g_deg[(int)idx] = 0; g_fill[(int)idx] = 0; }
    } else if (bid < MEGA_IB + MEGA_PB){
        int gid = (bid - MEGA_IB)*256 + tid;      // < 18*55296
        int cl = gid / 55296;
        int r  = gid - cl*55296;
        int p  = r / 27648;
        int r2 = r - p*27648;
        int chunk = r2 / 2304;
        int r3 = r2 - chunk*2304;
        int plane = r3 / 1152;
        int w  = r3 - plane*1152;
        int row = w >> 3, wk = w & 7;
        int c = cl / 6, l = cl % 6;
        const float* W   = (c==0)?W1:((c==1)?W2:W3);
        const float* wih = (c==0)?wih1:((c==1)?wih2:wih3);
        const float* whh = (c==0)?whh1:((c==1)?whh2:whh3);
        int gi = row / 48, rloc = row - gi*48;
        int nbase = (gi == 0) ? 0 : (gi == 1) ? 96 : ((chunk < 6) ? 192 : 288);
        int n = nbase + p*48 + rloc;
        int k = chunk*16 + wk*2;
        float v0 = wval(W, wih, whh, l, k, n);
        float v1 = wval(W, wih, whh, l, k+1, n);
        unsigned hi, lo;
        pack2(v0, v1, hi, lo);
        g_Wp[(size_t)gid] = plane ? lo : hi;
    } else {
        int id = (bid - MEGA_IB - MEGA_PB)*256 + tid;
        if (id < 18*384){
            int cl = id / 384;
            int j = id - cl*384;
            int c = cl / 6;
            const float* bih = (c==0)?bih1:((c==1)?bih2:bih3);
            const float* bhh = (c==0)?bhh1:((c==1)?bhh2:bhh3);
            float v;
            if (j < 192)      v = bih[j] + bhh[j];
            else if (j < 288) v = bih[192 + (j-192)];
            else              v = bhh[192 + (j-288)];
            g_bias[cl*384 + j] = v;
        }
    }
}

// ---------------- CSR build -------------------------------------------------
__global__ void k_deg(const int* __restrict__ e1, const int* __restrict__ e2,
                      const int* __restrict__ e3){
    int e = blockIdx.x*blockDim.x + threadIdx.x;
    if (e >= EE) return;
    int c = e / EC, le = e - c*EC;
    const int* ei = (c==0)?e1:((c==1)?e2:e3);
    atomicAdd(&g_deg[c*NC + ei[EC + le]], 1);
}

__global__ void k_scan1(){
    __shared__ int sm[SCAN_BLK];
    int tid = threadIdx.x;
    int i = blockIdx.x*SCAN_BLK + tid;
    int v = (i < NN) ? g_deg[i] : 0;
    sm[tid] = v;
    __syncthreads();
    for (int off = 1; off < SCAN_BLK; off <<= 1){
        int t = 0;
        if (tid >= off) t = sm[tid - off];
        __syncthreads();
        sm[tid] += t;
        __syncthreads();
    }
    if (i < NN) g_off[i] = sm[tid] - v;
    if (tid == SCAN_BLK-1) g_part[blockIdx.x] = sm[tid];
}

__global__ void k_scan2(){
    __shared__ int sm[SCAN_BLK];
    int tid = threadIdx.x;
    int v = (tid < NPART) ? g_part[tid] : 0;
    sm[tid] = v;
    __syncthreads();
    for (int off = 1; off < SCAN_BLK; off <<= 1){
        int t = 0;
        if (tid >= off) t = sm[tid - off];
        __syncthreads();
        sm[tid] += t;
        __syncthreads();
    }
    if (tid < NPART) g_part[tid] = sm[tid] - v;
}

__global__ void k_fill(const int* __restrict__ e1, const int* __restrict__ e2,
                       const int* __restrict__ e3){
    int e = blockIdx.x*blockDim.x + threadIdx.x;
    if (e >= EE) return;
    int c = e / EC, le = e - c*EC;
    const int* ei = (c==0)?e1:((c==1)?e2:e3);
    int dst = ei[EC + le];
    int src = ei[le];
    int dg = c*NC + dst;
    int p = g_off[dg] + g_part[dg >> 10] + atomicAdd(&g_fill[dg], 1);
    g_esrc[p] = c*NC + src;
}

// ---------------- fused GRU layer: gather + mma.sync(ldmatrix) + gates -------
// 64 rows/block, 256 threads (8 warps = 4M x 2N), 2 CTAs/SM.
// Zero-block-aware K loop: chunks 0-5 (S rows) update {r,z,ni};
// chunks 6-11 (h rows) update {r,z,nh}. acc[2]=ni, acc[3]=nh.
#define BIAS_OFF 0            // 1536 B
#define A_HI_OFF 1536         // 64 rows x 400 B = 25600
#define A_LO_OFF 27136
#define WB_OFF   52736        // 2 bufs x 13824
#define WB_BUF   13824
#define WB_PLANE 6912
#define SMEM_GRU_TOTAL 80384
template<int G2>
__device__ __forceinline__ void gru_chunk(uint32_t wb0, uint32_t a_h, uint32_t a_l, int ks,
                                          uint32_t b_x4off, uint32_t b_x2off,
                                          float (&acc)[4][3][4]){
    unsigned afh[4], afl[4];
    LDSM_X4(afh[0], afh[1], afh[2], afh[3], a_h + ks*32);
    LDSM_X4(afl[0], afl[1], afl[2], afl[3], a_l + ks*32);
    unsigned bf[3][6];
    #pragma unroll
    for (int gi = 0; gi < 3; gi++){
        uint32_t nb = wb0 + gi*2304;
        LDSM_X4(bf[gi][0], bf[gi][1], bf[gi][2], bf[gi][3], nb + b_x4off);
        LDSM_X2(bf[gi][4], bf[gi][5], nb + b_x2off);
    }
    #pragma unroll
    for (int gi = 0; gi < 3; gi++){
        const int ga = (gi < 2) ? gi : G2;
        #pragma unroll
        for (int t = 0; t < 3; t++){
            mma16816(acc[ga][t], afh, bf[gi][2*t], bf[gi][2*t+1]);
            mma16816(acc[ga][t], afl, bf[gi][2*t], bf[gi][2*t+1]);
        }
    }
    #pragma unroll
    for (int gi = 0; gi < 3; gi++){
        uint32_t nb = wb0 + WB_PLANE + gi*2304;
        LDSM_X4(bf[gi][0], bf[gi][1], bf[gi][2], bf[gi][3], nb + b_x4off);
        LDSM_X2(bf[gi][4], bf[gi][5], nb + b_x2off);
    }
    #pragma unroll
    for (int gi = 0; gi < 3; gi++){
        const int ga = (gi < 2) ? gi : G2;
        #pragma unroll
        for (int t = 0; t < 3; t++)
            mma16816(acc[ga][t], afh, bf[gi][2*t], bf[gi][2*t+1]);
    }
}

template<int WARM>
__global__ void __launch_bounds__(256, 2) k_gru(int layer){
    extern __shared__ char smc[];
    const uint32_t smb = smem_u32(smc);
    float* sb = (float*)(smc + BIAS_OFF);

    const int comp = blockIdx.y;
    const int cl = comp*6 + layer;
    const int row0 = blockIdx.x*64;
    const int tid = threadIdx.x;
    const int lane = tid & 31;
    const int wid = tid >> 5;
    const int wm = wid & 3;          // rows wm*16..+15
    const int wn = wid >> 2;         // 0..1
    const int lr = lane >> 2;        // 0..7
    const int lq = lane & 3;         // 0..3

    for (int i = tid; i < 384; i += 256) sb[i] = g_bias[cl*384 + i];

    const float* hin  = WARM ? g_h : ((layer & 1) ? g_s : g_h);
    float*       hout = WARM ? g_s : ((layer & 1) ? g_h : g_s);

    // ---- fused gather + stage A (bf16 hi/lo, 100-word row stride) ----
    {
        unsigned* Ahw = (unsigned*)(smc + A_HI_OFF);
        unsigned* Alw = (unsigned*)(smc + A_LO_OFF);
        int rbase = wid*8;
        #pragma unroll 1
        for (int rr = 0; rr < 8; rr++){
            int row = rbase + rr;
            int node = comp*NC + row0 + row;
            float2 s0 = make_float2(0.f, 0.f);
            float2 s1 = make_float2(0.f, 0.f);
            if (!WARM){
                int o0 = g_off[node] + g_part[node >> 10];
                int n1 = node + 1;
                int o1 = (n1 == NN) ? EE : (g_off[n1] + g_part[n1 >> 10]);
                for (int e = o0; e < o1; e++){
                    int s = __ldg(&g_esrc[e]);
                    const float2* hp = (const float2*)(hin + (size_t)s*96);
                    float2 v0 = __ldg(hp + lane);
                    s0.x += v0.x; s0.y += v0.y;
                    if (lane < 16){
                        float2 v1 = __ldg(hp + 32 + lane);
                        s1.x += v1.x; s1.y += v1.y;
                    }
                }
            }
            const float2* hr = (const float2*)(hin + (size_t)node*96);
            float2 h0 = hr[lane];
            int wb = row*100;
            unsigned hi, lo;
            pack2(s0.x, s0.y, hi, lo);
            Ahw[wb + lane] = hi;  Alw[wb + lane] = lo;
            pack2(h0.x, h0.y, hi, lo);
            Ahw[wb + 48 + lane] = hi;  Alw[wb + 48 + lane] = lo;
            if (lane < 16){
                float2 h1 = hr[32 + lane];
                pack2(s1.x, s1.y, hi, lo);
                Ahw[wb + 32 + lane] = hi;  Alw[wb + 32 + lane] = lo;
                pack2(h1.x, h1.y, hi, lo);
                Ahw[wb + 80 + lane] = hi;  Alw[wb + 80 + lane] = lo;
            }
        }
    }

    // per-warp ldmatrix base addresses
    const uint32_t a_h = smb + A_HI_OFF +
        ((wm*16 + (lane & 15))*100 + ((lane >> 4) << 2))*4;
    const uint32_t a_l = a_h + (A_LO_OFF - A_HI_OFF);
    const uint32_t b_x4off = ((wn*24 + ((lane >> 4) << 3) + (lane & 7))*48) + (((lane >> 3) & 1) << 4);
    const uint32_t b_x2off = ((wn*24 + 16 + (lane & 7))*48) + (((lane >> 3) & 1) << 4);

    const unsigned* Ahw = (const unsigned*)(smc + A_HI_OFF);
    const unsigned* Alw = (const unsigned*)(smc + A_LO_OFF);

    #pragma unroll 1
    for (int p = 0; p < 2; p++){
        float acc[4][3][4];
        #pragma unroll
        for (int g = 0; g < 4; g++)
            #pragma unroll
            for (int t = 0; t < 3; t++)
                #pragma unroll
                for (int i = 0; i < 4; i++) acc[g][t][i] = 0.f;

        const uint4* wsrc0 = (const uint4*)(g_Wp + (size_t)(cl*2 + p)*27648);
        uint4 rg[3];
        // prefetch chunk 0 (576 uint4 / 256 threads)
        rg[0] = wsrc0[tid];
        rg[1] = wsrc0[tid + 256];
        if (tid < 64) rg[2] = wsrc0[tid + 512];
        __syncthreads();
        #pragma unroll
        for (int q = 0; q < 3; q++){
            int idx = tid + 256*q;
            if (idx < 576){
                int plane = idx / 288, rh = idx - plane*288;
                *(uint4*)(smc + WB_OFF + plane*WB_PLANE + (rh>>1)*48 + (rh&1)*16) = rg[q];
            }
        }

        #pragma unroll 1
        for (int ks = 0; ks < 12; ks++){
            int buf = ks & 1;
            __syncthreads();
            if (ks < 11){
                const uint4* wsrc = wsrc0 + (ks+1)*576;
                rg[0] = wsrc[tid];
                rg[1] = wsrc[tid + 256];
                if (tid < 64) rg[2] = wsrc[tid + 512];
            }
            uint32_t wb0 = smb + WB_OFF + buf*WB_BUF;
            if (ks < 6) gru_chunk<2>(wb0, a_h, a_l, ks, b_x4off, b_x2off, acc);
            else        gru_chunk<3>(wb0, a_h, a_l, ks, b_x4off, b_x2off, acc);
            if (ks < 11){
                #pragma unroll
                for (int q = 0; q < 3; q++){
                    int idx = tid + 256*q;
                    if (idx < 576){
                        int plane = idx / 288, rh = idx - plane*288;
                        *(uint4*)(smc + WB_OFF + (buf^1)*WB_BUF + plane*WB_PLANE + (rh>>1)*48 + (rh&1)*16) = rg[q];
                    }
                }
            }
        }
        __syncthreads();

        // ---- epilogue: lean batched-rcp gates; h_old from A smem ----
        #pragma unroll
        for (int t = 0; t < 3; t++){
            int f0 = p*48 + wn*24 + t*8 + 2*lq;
            float bR0 = sb[f0],       bR1 = sb[f0+1];
            float bZ0 = sb[96+f0],    bZ1 = sb[96+f0+1];
            float bI0 = sb[192+f0],   bI1 = sb[192+f0+1];
            float bN0 = sb[288+f0],   bN1 = sb[288+f0+1];
            #pragma unroll
            for (int half = 0; half < 2; half++){
                int row = wm*16 + lr + half*8;
                size_t base = (size_t)(comp*NC + row0 + row)*96;
                int wofs = row*100 + 48 + (f0 >> 1);
                unsigned hw = Ahw[wofs], lw = Alw[wofs];
                float hx = bflo(hw) + bflo(lw);
                float hy = bfhi(hw) + bfhi(lw);
                int ci = half*2;
                float xr0 = fminf(fmaxf((acc[0][t][ci]   + bR0)*L2E, -30.f), 30.f);
                float xr1 = fminf(fmaxf((acc[0][t][ci+1] + bR1)*L2E, -30.f), 30.f);
                float xz0 = fminf(fmaxf((acc[1][t][ci]   + bZ0)*L2E, -30.f), 30.f);
                float xz1 = fminf(fmaxf((acc[1][t][ci+1] + bZ1)*L2E, -30.f), 30.f);
                float er0 = ex2f(xr0), er1 = ex2f(xr1);
                float ez0 = ex2f(xz0), ez1 = ex2f(xz1);
                float d1 = er0 + 1.f, d2 = ez0 + 1.f, d3 = er1 + 1.f, d4 = ez1 + 1.f;
                float p12 = d1*d2, p34 = d3*d4;
                float rp = rcpf(p12*p34);
                float q12 = rp*p34, q34 = rp*p12;
                float rr0 = er0*(q12*d2), zz0 = ez0*(q12*d1);
                float rr1 = er1*(q34*d4), zz1 = ez1*(q34*d3);
                float t0 = fmaf(rr0, acc[3][t][ci]   + bN0, acc[2][t][ci]   + bI0);
                float t1 = fmaf(rr1, acc[3][t][ci+1] + bN1, acc[2][t][ci+1] + bI1);
                float lt0 = fminf(fmaxf(t0*(2.f*L2E), -30.f), 30.f);
                float lt1 = fminf(fmaxf(t1*(2.f*L2E), -30.f), 30.f);
                float e0 = ex2f(lt0), e1 = ex2f(lt1);
                float dt0 = e0 + 1.f, dt1 = e1 + 1.f;
                float rpt = rcpf(dt0*dt1);
                float nn0 = fmaf(-2.f, rpt*dt1, 1.f);
                float nn1 = fmaf(-2.f, rpt*dt0, 1.f);
                float o0 = fmaf(zz0, hx - nn0, nn0);
                float o1 = fmaf(zz1, hy - nn1, nn1);
                *(float2*)(hout + base + f0) = make_float2(o0, o1);
            }
        }
        if (p == 0) __syncthreads();   // protect Wbuf before next pass refill
    }
}

// ---------------- pooling: mean of relu(h) over sorted batch ranges ---------
__global__ void k_pool(const int* __restrict__ b1, const int* __restrict__ b2,
                       const int* __restrict__ b3){
    int b = blockIdx.x;
    int c = blockIdx.y;
    const int* batch = (c==0)?b1:((c==1)?b2:b3);
    int lo = 0, hi = NC;
    while (lo < hi){ int m = (lo+hi) >> 1; if (batch[m] < b) lo = m+1; else hi = m; }
    int s0 = lo;
    hi = NC;
    while (lo < hi){ int m = (lo+hi) >> 1; if (batch[m] < b+1) lo = m+1; else hi = m; }
    int e0 = lo;
    float denom = fmaxf((float)(e0 - s0), 1.f);
    int f = threadIdx.x;
    float sum = 0.f;
    for (int n = s0; n < e0; n++)
        sum += fmaxf(g_h[(size_t)(c*NC + n)*HD + f], 0.f);
    g_pool[((size_t)c*NB + b)*HD + f] = sum / denom;
}

// ---------------- feature assembly ------------------------------------------
__global__ void k_feat(){
    int idx = blockIdx.x*blockDim.x + threadIdx.x;
    if (idx >= NB*384) return;
    int b = idx / 384;
    int j = idx - b*384;
    float v;
    if (j < 96)       v = g_pool[(size_t)b*HD + j];
    else if (j < 192) v = g_pool[((size_t)NB + b)*HD + (j-96)];
    else if (j < 288) v = g_pool[((size_t)2*NB + b)*HD + (j-192)];
    else {
        int jj = j - 288;
        v = g_pool[(size_t)b*HD + jj]
          * g_pool[((size_t)NB + b)*HD + jj]
          * g_pool[((size_t)2*NB + b)*HD + jj];
    }
    g_feat[idx] = v;
}

// ---------------- MLP GEMM (globals resolved in device code) ----------------
template<int MODE>
__global__ void __launch_bounds__(256) k_gemm(const float* __restrict__ B,
                                              const float* __restrict__ bias){
    const float* A = (MODE == 0) ? g_feat : g_t1;
    float*       C = (MODE == 0) ? g_t1   : g_t2;
    const int N = (MODE == 0) ? 1536 : 384;
    const int K = (MODE == 0) ? 384  : 1536;

    __shared__ float As[64*33];
    __shared__ float Bs[32*68];
    int txx = threadIdx.x & 15;
    int tyy = threadIdx.x >> 4;
    int m0 = blockIdx.y*64;
    int n0 = blockIdx.x*64;
    float accv[4][4];
    #pragma unroll
    for (int i = 0; i < 4; i++)
        #pragma unroll
        for (int j = 0; j < 4; j++) accv[i][j] = 0.f;

    for (int kc = 0; kc < K; kc += 32){
        __syncthreads();
        for (int i = threadIdx.x; i < 64*32; i += 256){
            int r = i >> 5, k = i & 31;
            As[r*33 + k] = A[(size_t)(m0 + r)*K + kc + k];
        }
        for (int i = threadIdx.x; i < 32*64; i += 256){
            int k = i >> 6, cc = i & 63;
            Bs[k*68 + cc] = B[(size_t)(kc + k)*N + n0 + cc];
        }
        __syncthreads();
        #pragma unroll 8
        for (int k = 0; k < 32; k++){
            float a[4], bb[4];
            #pragma unroll
            for (int i = 0; i < 4; i++) a[i] = As[(tyy*4 + i)*33 + k];
            float4 bv = *(const float4*)&Bs[k*68 + txx*4];
            bb[0] = bv.x; bb[1] = bv.y; bb[2] = bv.z; bb[3] = bv.w;
            #pragma unroll
            for (int i = 0; i < 4; i++)
                #pragma unroll
                for (int j = 0; j < 4; j++)
                    accv[i][j] += a[i]*bb[j];
        }
    }
    #pragma unroll
    for (int i = 0; i < 4; i++){
        int row = m0 + tyy*4 + i;
        #pragma unroll
        for (int j = 0; j < 4; j++){
            int col = n0 + txx*4 + j;
            float v = accv[i][j] + bias[col];
            C[(size_t)row*N + col] = fmaxf(v, 0.f);
        }
    }
}

// ---------------- fc3: [4096,384] @ [384,3] ---------------------------------
__global__ void k_fc3(const float* __restrict__ w, const float* __restrict__ b,
                      float* __restrict__ out){
    int gt = blockIdx.x*blockDim.x + threadIdx.x;
    int row = gt >> 5;
    int lane = gt & 31;
    if (row >= NB) return;
    float a0 = 0.f, a1 = 0.f, a2 = 0.f;
    for (int k = lane; k < 384; k += 32){
        float f = g_t2[(size_t)row*384 + k];
        a0 += f*w[k*3 + 0];
        a1 += f*w[k*3 + 1];
        a2 += f*w[k*3 + 2];
    }
    #pragma unroll
    for (int o = 16; o; o >>= 1){
        a0 += __shfl_down_sync(0xffffffffu, a0, o);
        a1 += __shfl_down_sync(0xffffffffu, a1, o);
        a2 += __shfl_down_sync(0xffffffffu, a2, o);
    }
    if (lane == 0){
        out[row*3 + 0] = a0 + b[0];
        out[row*3 + 1] = a1 + b[1];
        out[row*3 + 2] = a2 + b[2];
    }
}

// ---------------- launch ----------------------------------------------------
extern "C" void kernel_launch(void* const* d_in, const int* in_sizes, int n_in,
                              void* d_out, int out_size) {
    const float* xs[3]   = {0,0,0};
    const int*   es[3]   = {0,0,0};
    const int*   bs[3]   = {0,0,0};
    const float* Ws[3]   = {0,0,0};
    const float* wihs[3] = {0,0,0};
    const float* whhs[3] = {0,0,0};
    const float* bihs[3] = {0,0,0};
    const float* bhhs[3] = {0,0,0};
    const float* fcw[2]  = {0,0};
    const float* fc1b = 0; const float* fc2b = 0;
    const float* fc3w = 0; const float* fc3b = 0;
    int nx=0, ne=0, nb=0, nW=0, nwpair=0, nbpair=0, nfcw=0;
    for (int i = 0; i < n_in; i++){
        int s = in_sizes[i];
        const void* p = d_in[i];
        switch (s){
            case 6400000: if (nx < 3) xs[nx++] = (const float*)p; break;
            case 800000:  if (ne < 3) es[ne++] = (const int*)p;   break;
            case 200000:  if (nb < 3) bs[nb++] = (const int*)p;   break;
            case 55296:   if (nW < 3) Ws[nW++] = (const float*)p; break;
            case 27648:   { int c = nwpair/2;
                            if (c < 3){ if ((nwpair & 1) == 0) wihs[c] = (const float*)p;
                                        else                   whhs[c] = (const float*)p; }
                            nwpair++; } break;
            case 288:     { int c = nbpair/2;
                            if (c < 3){ if ((nbpair & 1) == 0) bihs[c] = (const float*)p;
                                        else                   bhhs[c] = (const float*)p; }
                            nbpair++; } break;
            case 589824:  if (nfcw < 2) fcw[nfcw++] = (const float*)p; break;
            case 1536:    fc1b = (const float*)p; break;
            case 384:     fc2b = (const float*)p; break;
            case 1152:    fc3w = (const float*)p; break;
            case 3:       fc3b = (const float*)p; break;
            default: break;
        }
    }
    const float* fc1w = fcw[0];
    const float* fc2w = fcw[1];
    float* out = (float*)d_out;

    cudaFuncSetAttribute(k_gru<0>, cudaFuncAttributeMaxDynamicSharedMemorySize, SMEM_GRU_TOTAL);
    cudaFuncSetAttribute(k_gru<1>, cudaFuncAttributeMaxDynamicSharedMemorySize, SMEM_GRU_TOTAL);

    // 1: mega init (h0 + counters + W prepack + bias pack)
    k_mega<<<MEGA_IB + MEGA_PB + MEGA_BB, 256>>>(
        xs[0], xs[1], xs[2],
        Ws[0], wihs[0], whhs[0], Ws[1], wihs[1], whhs[1], Ws[2], wihs[2], whhs[2],
        bihs[0], bhhs[0], bihs[1], bhhs[1], bihs[2], bhhs[2]);
    // 2-3: CSR histogram + block scan
    k_deg<<<(EE + 255)/256, 256>>>(es[0], es[1], es[2]);
    k_scan1<<<NPART, SCAN_BLK>>>();
    // 4: telemetry warmup GRU (no gather; writes g_s, overwritten by layer 0)
    k_gru<1><<<dim3(200, 3), 256, SMEM_GRU_TOTAL>>>(0);
    // 5-6: finish CSR
    k_scan2<<<1, SCAN_BLK>>>();
    k_fill<<<(EE + 255)/256, 256>>>(es[0], es[1], es[2]);

    const int gruBlocks = NC/64;   // 3125
    for (int l = 0; l < 6; l++)
        k_gru<0><<<dim3(gruBlocks, 3), 256, SMEM_GRU_TOTAL>>>(l);

    k_pool<<<dim3(NB, 3), 96>>>(bs[0], bs[1], bs[2]);
    k_feat<<<(NB*384 + 255)/256, 256>>>();
    k_gemm<0><<<dim3(1536/64, NB/64), 256>>>(fc1w, fc1b);
    k_gemm<1><<<dim3(384/64,  NB/64), 256>>>(fc2w, fc2b);
    k_fc3<<<(NB*32 + 255)/256, 256>>>(fc3w, fc3b, out);
}

// round 12
// speedup vs baseline: 2.2680x; 1.0903x over previous
#include <cuda_runtime.h>
#include <cstdint>

#define NC 200000
#define NCOMP 3
#define NN (NC*NCOMP)
#define EC 400000
#define EE (EC*NCOMP)
#define HD 96
#define NB 4096
#define SCAN_BLK 1024
#define NPART ((NN + SCAN_BLK - 1)/SCAN_BLK)

// ---------------- device scratch (static, no runtime allocation) ----------
__device__ __align__(16) float g_h[(size_t)NN*HD];   // ping buffer (h0, even-layer in)
__device__ __align__(16) float g_s[(size_t)NN*HD];   // pong buffer
__device__ int   g_deg[NN];
__device__ int   g_fill[NN];
__device__ int   g_off[NN+1];
__device__ int   g_esrc[EE];
__device__ int   g_part[SCAN_BLK];
// W prepacked, zero-blocks elided, 16B-half XOR swizzle pre-applied:
// [cl(18)][p(2)][chunk(12)][plane(2)][row 144][8 words]
// row: gi=row/48, rloc=row%48 ; nbase = gi==0?0 : gi==1?96 : (chunk<6?192:288)
// n = nbase + p*48 + rloc
// stored word wk (0..7): half=wk>>2, sub=wk&3; logical khalf = half ^ ((row>>2)&1)
// k = chunk*16 + (khalf*4 + sub)*2  (bf16 pairs)
__device__ __align__(16) unsigned g_Wp[(size_t)18*55296];
__device__ __align__(16) float g_bias[18*384];   // [cl][ brz(192) | bin(96) | bnh(96) ]
__device__ __align__(16) float g_pool[NCOMP*NB*HD];
__device__ __align__(16) float g_feat[(size_t)NB*384];
__device__ __align__(16) float g_t1[(size_t)NB*1536];
__device__ __align__(16) float g_t2[(size_t)NB*384];

// ---------------- helpers ---------------------------------------------------
__device__ __forceinline__ unsigned f2bf(float x){
    unsigned u = __float_as_uint(x);
    return (u + 0x7fffu + ((u >> 16) & 1u)) >> 16;   // RN-even
}
__device__ __forceinline__ float bfv(unsigned bits16){ return __uint_as_float(bits16 << 16); }
__device__ __forceinline__ float bflo(unsigned w){ return __uint_as_float(w << 16); }
__device__ __forceinline__ float bfhi(unsigned w){ return __uint_as_float(w & 0xffff0000u); }
__device__ __forceinline__ void pack2(float x, float y, unsigned &hi, unsigned &lo){
    unsigned hx = f2bf(x), hy = f2bf(y);
    hi = hx | (hy << 16);
    lo = f2bf(x - bfv(hx)) | (f2bf(y - bfv(hy)) << 16);
}
__device__ __forceinline__ float ex2f(float x){ float y; asm("ex2.approx.f32 %0, %1;" : "=f"(y) : "f"(x)); return y; }
__device__ __forceinline__ float rcpf(float x){ float y; asm("rcp.approx.f32 %0, %1;" : "=f"(y) : "f"(x)); return y; }
#define L2E 1.4426950408889634f

__device__ __forceinline__ uint32_t smem_u32(const void* p){
    uint32_t a;
    asm("{ .reg .u64 t; cvta.to.shared.u64 t, %1; cvt.u32.u64 %0, t; }" : "=r"(a) : "l"(p));
    return a;
}
__device__ __forceinline__ void mma16816(float* d, const unsigned* a, unsigned b0, unsigned b1){
    asm volatile(
        "mma.sync.aligned.m16n8k16.row.col.f32.bf16.bf16.f32 "
        "{%0,%1,%2,%3}, {%4,%5,%6,%7}, {%8,%9}, {%0,%1,%2,%3};"
        : "+f"(d[0]), "+f"(d[1]), "+f"(d[2]), "+f"(d[3])
        : "r"(a[0]), "r"(a[1]), "r"(a[2]), "r"(a[3]), "r"(b0), "r"(b1));
}
#define LDSM_X4(r0,r1,r2,r3,addr) \
    asm volatile("ldmatrix.sync.aligned.m8n8.x4.shared.b16 {%0,%1,%2,%3}, [%4];" \
        : "=r"(r0), "=r"(r1), "=r"(r2), "=r"(r3) : "r"(addr))
#define LDSM_X2(r0,r1,addr) \
    asm volatile("ldmatrix.sync.aligned.m8n8.x2.shared.b16 {%0,%1}, [%2];" \
        : "=r"(r0), "=r"(r1) : "r"(addr))
#define CP_ASYNC16(sa, ga) \
    asm volatile("cp.async.cg.shared.global [%0], [%1], 16;" :: "r"(sa), "l"(ga))
#define CP_COMMIT() asm volatile("cp.async.commit_group;" ::: "memory")
#define CP_WAIT0()  asm volatile("cp.async.wait_group 0;" ::: "memory")

// swizzled byte offset of (row, 16B-half h) within a W plane
__device__ __forceinline__ uint32_t swzoff(int r, int h){
    return (uint32_t)(r*32 + ((h ^ ((r >> 2) & 1)) << 4));
}

// logical Wpack[k][j]: k<96: (W_l@wih^T)[k][j] ; k>=96: t=k-96:
// j<192 -> whh[j][t]; j>=288 -> whh[j-96][t]   (zero blocks never requested)
__device__ float wval(const float* __restrict__ W, const float* __restrict__ wih,
                      const float* __restrict__ whh, int l, int k, int j){
    if (k < 96){
        const float* wr = W + (size_t)(l*96 + k)*96;
        const float* ir = wih + (size_t)j*96;
        float s = 0.f;
        #pragma unroll 8
        for (int t = 0; t < 96; t++) s += wr[t]*ir[t];
        return s;
    }
    int t = k - 96;
    if (j < 192) return whh[(size_t)j*96 + t];
    return whh[(size_t)(j-96)*96 + t];
}

// ---------------- mega kernel: init h0 + counters + pack W + pack bias ------
#define MEGA_IB 225000      // (NN*HD)/256
#define MEGA_PB 3888        // 18*55296/256
#define MEGA_BB 27
__global__ void k_mega(
    const float* __restrict__ x1, const float* __restrict__ x2, const float* __restrict__ x3,
    const float* __restrict__ W1, const float* __restrict__ wih1, const float* __restrict__ whh1,
    const float* __restrict__ W2, const float* __restrict__ wih2, const float* __restrict__ whh2,
    const float* __restrict__ W3, const float* __restrict__ wih3, const float* __restrict__ whh3,
    const float* __restrict__ bih1, const float* __restrict__ bhh1,
    const float* __restrict__ bih2, const float* __restrict__ bhh2,
    const float* __restrict__ bih3, const float* __restrict__ bhh3)
{
    int bid = blockIdx.x;
    int tid = threadIdx.x;
    if (bid < MEGA_IB){
        long long idx = (long long)bid*256 + tid;
        int n = (int)(idx / HD);
        int j = (int)(idx - (long long)n*HD);
        int c = n / NC;
        int ln = n - c*NC;
        const float* x = (c==0)?x1:((c==1)?x2:x3);
        g_h[idx] = (j < 32) ? x[(size_t)ln*32 + j] : 0.f;
        if (idx < NN){ g_deg[(int)idx] = 0; g_fill[(int)idx] = 0; }
    } else if (bid < MEGA_IB + MEGA_PB){
        int gid = (bid - MEGA_IB)*256 + tid;      // < 18*55296
        int cl = gid / 55296;
        int r  = gid - cl*55296;
        int p  = r / 27648;
        int r2 = r - p*27648;
        int chunk = r2 / 2304;
        int r3 = r2 - chunk*2304;
        int plane = r3 / 1152;
        int w  = r3 - plane*1152;
        int row = w >> 3, wk = w & 7;
        int c = cl / 6, l = cl % 6;
        const float* W   = (c==0)?W1:((c==1)?W2:W3);
        const float* wih = (c==0)?wih1:((c==1)?wih2:wih3);
        const float* whh = (c==0)?whh1:((c==1)?whh2:whh3);
        int gi = row / 48, rloc = row - gi*48;
        int nbase = (gi == 0) ? 0 : (gi == 1) ? 96 : ((chunk < 6) ? 192 : 288);
        int n = nbase + p*48 + rloc;
        int khalf = (wk >> 2) ^ ((row >> 2) & 1);
        int k = chunk*16 + (khalf*4 + (wk & 3))*2;
        float v0 = wval(W, wih, whh, l, k, n);
        float v1 = wval(W, wih, whh, l, k+1, n);
        unsigned hi, lo;
        pack2(v0, v1, hi, lo);
        g_Wp[(size_t)gid] = plane ? lo : hi;
    } else {
        int id = (bid - MEGA_IB - MEGA_PB)*256 + tid;
        if (id < 18*384){
            int cl = id / 384;
            int j = id - cl*384;
            int c = cl / 6;
            const float* bih = (c==0)?bih1:((c==1)?bih2:bih3);
            const float* bhh = (c==0)?bhh1:((c==1)?bhh2:bhh3);
            float v;
            if (j < 192)      v = bih[j] + bhh[j];
            else if (j < 288) v = bih[192 + (j-192)];
            else              v = bhh[192 + (j-288)];
            g_bias[cl*384 + j] = v;
        }
    }
}

// ---------------- CSR build -------------------------------------------------
__global__ void k_deg(const int* __restrict__ e1, const int* __restrict__ e2,
                      const int* __restrict__ e3){
    int e = blockIdx.x*blockDim.x + threadIdx.x;
    if (e >= EE) return;
    int c = e / EC, le = e - c*EC;
    const int* ei = (c==0)?e1:((c==1)?e2:e3);
    atomicAdd(&g_deg[c*NC + ei[EC + le]], 1);
}

__global__ void k_scan1(){
    __shared__ int sm[SCAN_BLK];
    int tid = threadIdx.x;
    int i = blockIdx.x*SCAN_BLK + tid;
    int v = (i < NN) ? g_deg[i] : 0;
    sm[tid] = v;
    __syncthreads();
    for (int off = 1; off < SCAN_BLK; off <<= 1){
        int t = 0;
        if (tid >= off) t = sm[tid - off];
        __syncthreads();
        sm[tid] += t;
        __syncthreads();
    }
    if (i < NN) g_off[i] = sm[tid] - v;
    if (tid == SCAN_BLK-1) g_part[blockIdx.x] = sm[tid];
}

__global__ void k_scan2(){
    __shared__ int sm[SCAN_BLK];
    int tid = threadIdx.x;
    int v = (tid < NPART) ? g_part[tid] : 0;
    sm[tid] = v;
    __syncthreads();
    for (int off = 1; off < SCAN_BLK; off <<= 1){
        int t = 0;
        if (tid >= off) t = sm[tid - off];
        __syncthreads();
        sm[tid] += t;
        __syncthreads();
    }
    if (tid < NPART) g_part[tid] = sm[tid] - v;
}

__global__ void k_fill(const int* __restrict__ e1, const int* __restrict__ e2,
                       const int* __restrict__ e3){
    int e = blockIdx.x*blockDim.x + threadIdx.x;
    if (e >= EE) return;
    int c = e / EC, le = e - c*EC;
    const int* ei = (c==0)?e1:((c==1)?e2:e3);
    int dst = ei[EC + le];
    int src = ei[le];
    int dg = c*NC + dst;
    int p = g_off[dg] + g_part[dg >> 10] + atomicAdd(&g_fill[dg], 1);
    g_esrc[p] = c*NC + src;
}

// ---------------- fused GRU layer: gather + mma.sync(ldmatrix) + gates -------
// 64 rows/block, 256 threads (8 warps = 4M x 2N), 2 CTAs/SM.
// Resident 6-chunk W buffer, swizzled 32B rows, cp.async fills, sync-free k-loop.
#define BIAS_OFF 0            // 1536 B
#define A_HI_OFF 1536         // 64 rows x 400 B = 25600
#define A_LO_OFF 27136
#define W6_OFF   52736        // 6 chunks x 9216 B = 55296
#define SMEM_GRU_TOTAL 108032

__device__ __forceinline__ void fill_w6(uint32_t smW, const unsigned* gsrc, int tid){
    #pragma unroll
    for (int q = 0; q < 14; q++){
        int idx = tid + 256*q;
        if (idx < 3456){
            CP_ASYNC16(smW + idx*16, (const void*)(gsrc + idx*4));
        }
    }
    CP_COMMIT();
}

template<int G2>
__device__ __forceinline__ void gru_chunk(uint32_t wchunk, uint32_t a_h, uint32_t a_l,
                                          int kglob, uint32_t b4off, uint32_t bt2off,
                                          uint32_t bx2off, float (&acc)[4][3][4]){
    unsigned afh[4], afl[4];
    LDSM_X4(afh[0], afh[1], afh[2], afh[3], a_h + kglob*32);
    LDSM_X4(afl[0], afl[1], afl[2], afl[3], a_l + kglob*32);
    #pragma unroll
    for (int plane = 0; plane < 2; plane++){
        uint32_t pb = wchunk + plane*4608;
        unsigned b[3][6];
        LDSM_X4(b[0][0], b[0][1], b[0][2], b[0][3], pb + b4off);
        LDSM_X4(b[1][0], b[1][1], b[1][2], b[1][3], pb + 1536 + b4off);
        LDSM_X4(b[2][0], b[2][1], b[2][2], b[2][3], pb + 3072 + b4off);
        LDSM_X4(b[0][4], b[0][5], b[1][4], b[1][5], pb + bt2off);
        LDSM_X2(b[2][4], b[2][5], pb + bx2off);
        #pragma unroll
        for (int gi = 0; gi < 3; gi++){
            const int ga = (gi < 2) ? gi : G2;
            #pragma unroll
            for (int t = 0; t < 3; t++){
                mma16816(acc[ga][t], afh, b[gi][2*t], b[gi][2*t+1]);
                if (plane == 0) mma16816(acc[ga][t], afl, b[gi][2*t], b[gi][2*t+1]);
            }
        }
    }
}

template<int WARM>
__global__ void __launch_bounds__(256, 2) k_gru(int layer){
    extern __shared__ char smc[];
    const uint32_t smb = smem_u32(smc);
    float* sb = (float*)(smc + BIAS_OFF);

    const int comp = blockIdx.y;
    const int cl = comp*6 + layer;
    const int row0 = blockIdx.x*64;
    const int tid = threadIdx.x;
    const int lane = tid & 31;
    const int wid = tid >> 5;
    const int wm = wid & 3;          // rows wm*16..+15
    const int wn = wid >> 2;         // 0..1
    const int lr = lane >> 2;        // 0..7
    const int lq = lane & 3;         // 0..3

    const unsigned* wsrc = g_Wp + (size_t)(cl*2)*27648;

    // kick off W fill for pass0/half0 immediately (overlaps the gather)
    fill_w6(smb + W6_OFF, wsrc, tid);

    for (int i = tid; i < 384; i += 256) sb[i] = g_bias[cl*384 + i];

    const float* hin  = WARM ? g_h : ((layer & 1) ? g_s : g_h);
    float*       hout = WARM ? g_s : ((layer & 1) ? g_h : g_s);

    // ---- fused gather + stage A (bf16 hi/lo, 100-word row stride) ----
    {
        unsigned* Ahw2 = (unsigned*)(smc + A_HI_OFF);
        unsigned* Alw2 = (unsigned*)(smc + A_LO_OFF);
        int rbase = wid*8;
        #pragma unroll 1
        for (int rr = 0; rr < 8; rr++){
            int row = rbase + rr;
            int node = comp*NC + row0 + row;
            float2 s0 = make_float2(0.f, 0.f);
            float2 s1 = make_float2(0.f, 0.f);
            if (!WARM){
                int o0 = g_off[node] + g_part[node >> 10];
                int n1 = node + 1;
                int o1 = (n1 == NN) ? EE : (g_off[n1] + g_part[n1 >> 10]);
                for (int e = o0; e < o1; e++){
                    int s = __ldg(&g_esrc[e]);
                    const float2* hp = (const float2*)(hin + (size_t)s*96);
                    float2 v0 = __ldg(hp + lane);
                    s0.x += v0.x; s0.y += v0.y;
                    if (lane < 16){
                        float2 v1 = __ldg(hp + 32 + lane);
                        s1.x += v1.x; s1.y += v1.y;
                    }
                }
            }
            const float2* hr = (const float2*)(hin + (size_t)node*96);
            float2 h0 = hr[lane];
            int wb = row*100;
            unsigned hi, lo;
            pack2(s0.x, s0.y, hi, lo);
            Ahw2[wb + lane] = hi;  Alw2[wb + lane] = lo;
            pack2(h0.x, h0.y, hi, lo);
            Ahw2[wb + 48 + lane] = hi;  Alw2[wb + 48 + lane] = lo;
            if (lane < 16){
                float2 h1 = hr[32 + lane];
                pack2(s1.x, s1.y, hi, lo);
                Ahw2[wb + 32 + lane] = hi;  Alw2[wb + 32 + lane] = lo;
                pack2(h1.x, h1.y, hi, lo);
                Ahw2[wb + 80 + lane] = hi;  Alw2[wb + 80 + lane] = lo;
            }
        }
    }

    // per-warp ldmatrix addresses
    const uint32_t a_h = smb + A_HI_OFF +
        ((wm*16 + (lane & 15))*100 + ((lane >> 4) << 2))*4;
    const uint32_t a_l = a_h + (A_LO_OFF - A_HI_OFF);
    const int hsel = (lane >> 3) & 1;
    const uint32_t b4off  = wn*768 + swzoff(((lane >> 4) << 3) + (lane & 7), hsel);
    const uint32_t bt2off = (lane >> 4)*1536 + wn*768 + swzoff(16 + (lane & 7), hsel);
    const uint32_t bx2off = 3072 + wn*768 + swzoff(16 + (lane & 7), hsel);

    const unsigned* Ahw = (const unsigned*)(smc + A_HI_OFF);
    const unsigned* Alw = (const unsigned*)(smc + A_LO_OFF);
    const uint32_t w6 = smb + W6_OFF;

    CP_WAIT0();
    __syncthreads();   // A staged + fill0 complete

    #pragma unroll 1
    for (int p = 0; p < 2; p++){
        float acc[4][3][4];
        #pragma unroll
        for (int g = 0; g < 4; g++)
            #pragma unroll
            for (int t = 0; t < 3; t++)
                #pragma unroll
                for (int i = 0; i < 4; i++) acc[g][t][i] = 0.f;

        // chunks 0-5 (S part -> ni), sync-free
        #pragma unroll
        for (int ks = 0; ks < 6; ks++)
            gru_chunk<2>(w6 + ks*9216, a_h, a_l, ks, b4off, bt2off, bx2off, acc);
        __syncthreads();
        // refill with chunks 6-11 of this pass
        fill_w6(w6, wsrc + p*27648 + 13824, tid);
        CP_WAIT0();
        __syncthreads();
        // chunks 6-11 (h part -> nh), sync-free
        #pragma unroll
        for (int ks = 0; ks < 6; ks++)
            gru_chunk<3>(w6 + ks*9216, a_h, a_l, 6 + ks, b4off, bt2off, bx2off, acc);
        __syncthreads();
        if (p == 0) fill_w6(w6, wsrc + 27648, tid);   // pass1/half0, overlaps epilogue

        // ---- epilogue: lean batched-rcp gates; h_old from A smem ----
        #pragma unroll
        for (int t = 0; t < 3; t++){
            int f0 = p*48 + wn*24 + t*8 + 2*lq;
            float bR0 = sb[f0],       bR1 = sb[f0+1];
            float bZ0 = sb[96+f0],    bZ1 = sb[96+f0+1];
            float bI0 = sb[192+f0],   bI1 = sb[192+f0+1];
            float bN0 = sb[288+f0],   bN1 = sb[288+f0+1];
            #pragma unroll
            for (int half = 0; half < 2; half++){
                int row = wm*16 + lr + half*8;
                size_t base = (size_t)(comp*NC + row0 + row)*96;
                int wofs = row*100 + 48 + (f0 >> 1);
                unsigned hw = Ahw[wofs], lw = Alw[wofs];
                float hx = bflo(hw) + bflo(lw);
                float hy = bfhi(hw) + bfhi(lw);
                int ci = half*2;
                float xr0 = fminf(fmaxf((acc[0][t][ci]   + bR0)*L2E, -30.f), 30.f);
                float xr1 = fminf(fmaxf((acc[0][t][ci+1] + bR1)*L2E, -30.f), 30.f);
                float xz0 = fminf(fmaxf((acc[1][t][ci]   + bZ0)*L2E, -30.f), 30.f);
                float xz1 = fminf(fmaxf((acc[1][t][ci+1] + bZ1)*L2E, -30.f), 30.f);
                float er0 = ex2f(xr0), er1 = ex2f(xr1);
                float ez0 = ex2f(xz0), ez1 = ex2f(xz1);
                float d1 = er0 + 1.f, d2 = ez0 + 1.f, d3 = er1 + 1.f, d4 = ez1 + 1.f;
                float p12 = d1*d2, p34 = d3*d4;
                float rp = rcpf(p12*p34);
                float q12 = rp*p34, q34 = rp*p12;
                float rr0 = er0*(q12*d2), zz0 = ez0*(q12*d1);
                float rr1 = er1*(q34*d4), zz1 = ez1*(q34*d3);
                float t0 = fmaf(rr0, acc[3][t][ci]   + bN0, acc[2][t][ci]   + bI0);
                float t1 = fmaf(rr1, acc[3][t][ci+1] + bN1, acc[2][t][ci+1] + bI1);
                float lt0 = fminf(fmaxf(t0*(2.f*L2E), -30.f), 30.f);
                float lt1 = fminf(fmaxf(t1*(2.f*L2E), -30.f), 30.f);
                float e0 = ex2f(lt0), e1 = ex2f(lt1);
                float dt0 = e0 + 1.f, dt1 = e1 + 1.f;
                float rpt = rcpf(dt0*dt1);
                float nn0 = fmaf(-2.f, rpt*dt1, 1.f);
                float nn1 = fmaf(-2.f, rpt*dt0, 1.f);
                float o0 = fmaf(zz0, hx - nn0, nn0);
                float o1 = fmaf(zz1, hy - nn1, nn1);
                *(float2*)(hout + base + f0) = make_float2(o0, o1);
            }
        }
        if (p == 0){
            CP_WAIT0();
            __syncthreads();   // pass1 W ready
        }
    }
}

// ---------------- pooling: mean of relu(h) over sorted batch ranges ---------
__global__ void k_pool(const int* __restrict__ b1, const int* __restrict__ b2,
                       const int* __restrict__ b3){
    int b = blockIdx.x;
    int c = blockIdx.y;
    const int* batch = (c==0)?b1:((c==1)?b2:b3);
    int lo = 0, hi = NC;
    while (lo < hi){ int m = (lo+hi) >> 1; if (batch[m] < b) lo = m+1; else hi = m; }
    int s0 = lo;
    hi = NC;
    while (lo < hi){ int m = (lo+hi) >> 1; if (batch[m] < b+1) lo = m+1; else hi = m; }
    int e0 = lo;
    float denom = fmaxf((float)(e0 - s0), 1.f);
    int f = threadIdx.x;
    float sum = 0.f;
    for (int n = s0; n < e0; n++)
        sum += fmaxf(g_h[(size_t)(c*NC + n)*HD + f], 0.f);
    g_pool[((size_t)c*NB + b)*HD + f] = sum / denom;
}

// ---------------- feature assembly ------------------------------------------
__global__ void k_feat(){
    int idx = blockIdx.x*blockDim.x + threadIdx.x;
    if (idx >= NB*384) return;
    int b = idx / 384;
    int j = idx - b*384;
    float v;
    if (j < 96)       v = g_pool[(size_t)b*HD + j];
    else if (j < 192) v = g_pool[((size_t)NB + b)*HD + (j-96)];
    else if (j < 288) v = g_pool[((size_t)2*NB + b)*HD + (j-192)];
    else {
        int jj = j - 288;
        v = g_pool[(size_t)b*HD + jj]
          * g_pool[((size_t)NB + b)*HD + jj]
          * g_pool[((size_t)2*NB + b)*HD + jj];
    }
    g_feat[idx] = v;
}

// ---------------- MLP GEMM (globals resolved in device code) ----------------
template<int MODE>
__global__ void __launch_bounds__(256) k_gemm(const float* __restrict__ B,
                                              const float* __restrict__ bias){
    const float* A = (MODE == 0) ? g_feat : g_t1;
    float*       C = (MODE == 0) ? g_t1   : g_t2;
    const int N = (MODE == 0) ? 1536 : 384;
    const int K = (MODE == 0) ? 384  : 1536;

    __shared__ float As[64*33];
    __shared__ float Bs[32*68];
    int txx = threadIdx.x & 15;
    int tyy = threadIdx.x >> 4;
    int m0 = blockIdx.y*64;
    int n0 = blockIdx.x*64;
    float accv[4][4];
    #pragma unroll
    for (int i = 0; i < 4; i++)
        #pragma unroll
        for (int j = 0; j < 4; j++) accv[i][j] = 0.f;

    for (int kc = 0; kc < K; kc += 32){
        __syncthreads();
        for (int i = threadIdx.x; i < 64*32; i += 256){
            int r = i >> 5, k = i & 31;
            As[r*33 + k] = A[(size_t)(m0 + r)*K + kc + k];
        }
        for (int i = threadIdx.x; i < 32*64; i += 256){
            int k = i >> 6, cc = i & 63;
            Bs[k*68 + cc] = B[(size_t)(kc + k)*N + n0 + cc];
        }
        __syncthreads();
        #pragma unroll 8
        for (int k = 0; k < 32; k++){
            float a[4], bb[4];
            #pragma unroll
            for (int i = 0; i < 4; i++) a[i] = As[(tyy*4 + i)*33 + k];
            float4 bv = *(const float4*)&Bs[k*68 + txx*4];
            bb[0] = bv.x; bb[1] = bv.y; bb[2] = bv.z; bb[3] = bv.w;
            #pragma unroll
            for (int i = 0; i < 4; i++)
                #pragma unroll
                for (int j = 0; j < 4; j++)
                    accv[i][j] += a[i]*bb[j];
        }
    }
    #pragma unroll
    for (int i = 0; i < 4; i++){
        int row = m0 + tyy*4 + i;
        #pragma unroll
        for (int j = 0; j < 4; j++){
            int col = n0 + txx*4 + j;
            float v = accv[i][j] + bias[col];
            C[(size_t)row*N + col] = fmaxf(v, 0.f);
        }
    }
}

// ---------------- fc3: [4096,384] @ [384,3] ---------------------------------
__global__ void k_fc3(const float* __restrict__ w, const float* __restrict__ b,
                      float* __restrict__ out){
    int gt = blockIdx.x*blockDim.x + threadIdx.x;
    int row = gt >> 5;
    int lane = gt & 31;
    if (row >= NB) return;
    float a0 = 0.f, a1 = 0.f, a2 = 0.f;
    for (int k = lane; k < 384; k += 32){
        float f = g_t2[(size_t)row*384 + k];
        a0 += f*w[k*3 + 0];
        a1 += f*w[k*3 + 1];
        a2 += f*w[k*3 + 2];
    }
    #pragma unroll
    for (int o = 16; o; o >>= 1){
        a0 += __shfl_down_sync(0xffffffffu, a0, o);
        a1 += __shfl_down_sync(0xffffffffu, a1, o);
        a2 += __shfl_down_sync(0xffffffffu, a2, o);
    }
    if (lane == 0){
        out[row*3 + 0] = a0 + b[0];
        out[row*3 + 1] = a1 + b[1];
        out[row*3 + 2] = a2 + b[2];
    }
}

// ---------------- launch ----------------------------------------------------
extern "C" void kernel_launch(void* const* d_in, const int* in_sizes, int n_in,
                              void* d_out, int out_size) {
    const float* xs[3]   = {0,0,0};
    const int*   es[3]   = {0,0,0};
    const int*   bs[3]   = {0,0,0};
    const float* Ws[3]   = {0,0,0};
    const float* wihs[3] = {0,0,0};
    const float* whhs[3] = {0,0,0};
    const float* bihs[3] = {0,0,0};
    const float* bhhs[3] = {0,0,0};
    const float* fcw[2]  = {0,0};
    const float* fc1b = 0; const float* fc2b = 0;
    const float* fc3w = 0; const float* fc3b = 0;
    int nx=0, ne=0, nb=0, nW=0, nwpair=0, nbpair=0, nfcw=0;
    for (int i = 0; i < n_in; i++){
        int s = in_sizes[i];
        const void* p = d_in[i];
        switch (s){
            case 6400000: if (nx < 3) xs[nx++] = (const float*)p; break;
            case 800000:  if (ne < 3) es[ne++] = (const int*)p;   break;
            case 200000:  if (nb < 3) bs[nb++] = (const int*)p;   break;
            case 55296:   if (nW < 3) Ws[nW++] = (const float*)p; break;
            case 27648:   { int c = nwpair/2;
                            if (c < 3){ if ((nwpair & 1) == 0) wihs[c] = (const float*)p;
                                        else                   whhs[c] = (const float*)p; }
                            nwpair++; } break;
            case 288:     { int c = nbpair/2;
                            if (c < 3){ if ((nbpair & 1) == 0) bihs[c] = (const float*)p;
                                        else                   bhhs[c] = (const float*)p; }
                            nbpair++; } break;
            case 589824:  if (nfcw < 2) fcw[nfcw++] = (const float*)p; break;
            case 1536:    fc1b = (const float*)p; break;
            case 384:     fc2b = (const float*)p; break;
            case 1152:    fc3w = (const float*)p; break;
            case 3:       fc3b = (const float*)p; break;
            default: break;
        }
    }
    const float* fc1w = fcw[0];
    const float* fc2w = fcw[1];
    float* out = (float*)d_out;

    cudaFuncSetAttribute(k_gru<0>, cudaFuncAttributeMaxDynamicSharedMemorySize, SMEM_GRU_TOTAL);
    cudaFuncSetAttribute(k_gru<1>, cudaFuncAttributeMaxDynamicSharedMemorySize, SMEM_GRU_TOTAL);

    // 1: mega init (h0 + counters + W prepack + bias pack)
    k_mega<<<MEGA_IB + MEGA_PB + MEGA_BB, 256>>>(
        xs[0], xs[1], xs[2],
        Ws[0], wihs[0], whhs[0], Ws[1], wihs[1], whhs[1], Ws[2], wihs[2], whhs[2],
        bihs[0], bhhs[0], bihs[1], bhhs[1], bihs[2], bhhs[2]);
    // 2-3: CSR histogram + block scan
    k_deg<<<(EE + 255)/256, 256>>>(es[0], es[1], es[2]);
    k_scan1<<<NPART, SCAN_BLK>>>();
    // 4: telemetry warmup GRU (no gather; writes g_s, overwritten by layer 0)
    k_gru<1><<<dim3(200, 3), 256, SMEM_GRU_TOTAL>>>(0);
    // 5-6: finish CSR
    k_scan2<<<1, SCAN_BLK>>>();
    k_fill<<<(EE + 255)/256, 256>>>(es[0], es[1], es[2]);

    const int gruBlocks = NC/64;   // 3125
    for (int l = 0; l < 6; l++)
        k_gru<0><<<dim3(gruBlocks, 3), 256, SMEM_GRU_TOTAL>>>(l);

    k_pool<<<dim3(NB, 3), 96>>>(bs[0], bs[1], bs[2]);
    k_feat<<<(NB*384 + 255)/256, 256>>>();
    k_gemm<0><<<dim3(1536/64, NB/64), 256>>>(fc1w, fc1b);
    k_gemm<1><<<dim3(384/64,  NB/64), 256>>>(fc2w, fc2b);
    k_fc3<<<(NB*32 + 255)/256, 256>>>(fc3w, fc3b, out);
}

// round 14
// speedup vs baseline: 2.6276x; 1.1586x over previous
#include <cuda_runtime.h>
#include <cstdint>

#define NC 200000
#define NCOMP 3
#define NN (NC*NCOMP)
#define EC 400000
#define EE (EC*NCOMP)
#define HD 96
#define NB 4096
#define SCAN_BLK 1024
#define NPART ((NN + SCAN_BLK - 1)/SCAN_BLK)

// ---------------- device scratch (static, no runtime allocation) ----------
__device__ __align__(16) float g_h[(size_t)NN*HD];   // ping buffer (h0, even-layer in)
__device__ __align__(16) float g_s[(size_t)NN*HD];   // pong buffer
__device__ int   g_deg[NN];
__device__ int   g_fill[NN];
__device__ int   g_off[NN+1];
__device__ int   g_esrc[EE];
__device__ int   g_part[SCAN_BLK];
// W prepacked, zero-blocks elided, 16B-half XOR swizzle pre-applied:
// [cl(18)][p(2)][chunk(12)][plane(2)][row 144][8 words]
__device__ __align__(16) unsigned g_Wp[(size_t)18*55296];
__device__ __align__(16) float g_bias[18*384];   // [cl][ brz(192) | bin(96) | bnh(96) ]
__device__ __align__(16) float g_pool[NCOMP*NB*HD];
__device__ __align__(16) float g_feat[(size_t)NB*384];
__device__ __align__(16) float g_t1[(size_t)NB*1536];
__device__ __align__(16) float g_t2[(size_t)NB*384];

// ---------------- helpers ---------------------------------------------------
__device__ __forceinline__ unsigned f2bf(float x){
    unsigned u = __float_as_uint(x);
    return (u + 0x7fffu + ((u >> 16) & 1u)) >> 16;   // RN-even
}
__device__ __forceinline__ float bfv(unsigned bits16){ return __uint_as_float(bits16 << 16); }
__device__ __forceinline__ float bflo(unsigned w){ return __uint_as_float(w << 16); }
__device__ __forceinline__ float bfhi(unsigned w){ return __uint_as_float(w & 0xffff0000u); }
__device__ __forceinline__ void pack2(float x, float y, unsigned &hi, unsigned &lo){
    unsigned hx = f2bf(x), hy = f2bf(y);
    hi = hx | (hy << 16);
    lo = f2bf(x - bfv(hx)) | (f2bf(y - bfv(hy)) << 16);
}
__device__ __forceinline__ float ex2f(float x){ float y; asm("ex2.approx.f32 %0, %1;" : "=f"(y) : "f"(x)); return y; }
__device__ __forceinline__ float rcpf(float x){ float y; asm("rcp.approx.f32 %0, %1;" : "=f"(y) : "f"(x)); return y; }
#define L2E 1.4426950408889634f

__device__ __forceinline__ uint32_t smem_u32(const void* p){
    uint32_t a;
    asm("{ .reg .u64 t; cvta.to.shared.u64 t, %1; cvt.u32.u64 %0, t; }" : "=r"(a) : "l"(p));
    return a;
}
__device__ __forceinline__ void mma16816(float* d, const unsigned* a, unsigned b0, unsigned b1){
    asm volatile(
        "mma.sync.aligned.m16n8k16.row.col.f32.bf16.bf16.f32 "
        "{%0,%1,%2,%3}, {%4,%5,%6,%7}, {%8,%9}, {%0,%1,%2,%3};"
        : "+f"(d[0]), "+f"(d[1]), "+f"(d[2]), "+f"(d[3])
        : "r"(a[0]), "r"(a[1]), "r"(a[2]), "r"(a[3]), "r"(b0), "r"(b1));
}
#define LDSM_X4(r0,r1,r2,r3,addr) \
    asm volatile("ldmatrix.sync.aligned.m8n8.x4.shared.b16 {%0,%1,%2,%3}, [%4];" \
        : "=r"(r0), "=r"(r1), "=r"(r2), "=r"(r3) : "r"(addr))
#define LDSM_X2(r0,r1,addr) \
    asm volatile("ldmatrix.sync.aligned.m8n8.x2.shared.b16 {%0,%1}, [%2];" \
        : "=r"(r0), "=r"(r1) : "r"(addr))
#define CP_ASYNC16(sa, ga) \
    asm volatile("cp.async.cg.shared.global [%0], [%1], 16;" :: "r"(sa), "l"(ga))
#define CP_COMMIT() asm volatile("cp.async.commit_group;" ::: "memory")
#define CP_WAITG(n) asm volatile("cp.async.wait_group %0;" :: "n"(n) : "memory")

// f32x2 packed FMA (FFMA2)
__device__ __forceinline__ unsigned long long dup2(float x){
    unsigned u = __float_as_uint(x);
    unsigned long long r;
    asm("mov.b64 %0, {%1, %1};" : "=l"(r) : "r"(u));
    return r;
}
__device__ __forceinline__ unsigned long long ffma2(unsigned long long a,
                                                    unsigned long long b,
                                                    unsigned long long c){
    unsigned long long d;
    asm("fma.rn.f32x2 %0, %1, %2, %3;" : "=l"(d) : "l"(a), "l"(b), "l"(c));
    return d;
}
__device__ __forceinline__ float2 unpk2(unsigned long long v){
    unsigned lo, hi;
    asm("mov.b64 {%0, %1}, %2;" : "=r"(lo), "=r"(hi) : "l"(v));
    float2 f; f.x = __uint_as_float(lo); f.y = __uint_as_float(hi); return f;
}

// swizzled byte offset of (row, 16B-half h) within a W plane
__device__ __forceinline__ uint32_t swzoff(int r, int h){
    return (uint32_t)(r*32 + ((h ^ ((r >> 2) & 1)) << 4));
}

// logical Wpack[k][j]
__device__ float wval(const float* __restrict__ W, const float* __restrict__ wih,
                      const float* __restrict__ whh, int l, int k, int j){
    if (k < 96){
        const float* wr = W + (size_t)(l*96 + k)*96;
        const float* ir = wih + (size_t)j*96;
        float s = 0.f;
        #pragma unroll 8
        for (int t = 0; t < 96; t++) s += wr[t]*ir[t];
        return s;
    }
    int t = k - 96;
    if (j < 192) return whh[(size_t)j*96 + t];
    return whh[(size_t)(j-96)*96 + t];
}

// ---------------- mega kernel: init h0 + counters + pack W + pack bias ------
#define MEGA_IB 225000      // (NN*HD)/256
#define MEGA_PB 3888        // 18*55296/256
#define MEGA_BB 27
__global__ void k_mega(
    const float* __restrict__ x1, const float* __restrict__ x2, const float* __restrict__ x3,
    const float* __restrict__ W1, const float* __restrict__ wih1, const float* __restrict__ whh1,
    const float* __restrict__ W2, const float* __restrict__ wih2, const float* __restrict__ whh2,
    const float* __restrict__ W3, const float* __restrict__ wih3, const float* __restrict__ whh3,
    const float* __restrict__ bih1, const float* __restrict__ bhh1,
    const float* __restrict__ bih2, const float* __restrict__ bhh2,
    const float* __restrict__ bih3, const float* __restrict__ bhh3)
{
    int bid = blockIdx.x;
    int tid = threadIdx.x;
    if (bid < MEGA_IB){
        long long idx = (long long)bid*256 + tid;
        int n = (int)(idx / HD);
        int j = (int)(idx - (long long)n*HD);
        int c = n / NC;
        int ln = n - c*NC;
        const float* x = (c==0)?x1:((c==1)?x2:x3);
        g_h[idx] = (j < 32) ? x[(size_t)ln*32 + j] : 0.f;
        if (idx < NN){ g_deg[(int)idx] = 0; g_fill[(int)idx] = 0; }
    } else if (bid < MEGA_IB + MEGA_PB){
        int gid = (bid - MEGA_IB)*256 + tid;      // < 18*55296
        int cl = gid / 55296;
        int r  = gid - cl*55296;
        int p  = r / 27648;
        int r2 = r - p*27648;
        int chunk = r2 / 2304;
        int r3 = r2 - chunk*2304;
        int plane = r3 / 1152;
        int w  = r3 - plane*1152;
        int row = w >> 3, wk = w & 7;
        int c = cl / 6, l = cl % 6;
        const float* W   = (c==0)?W1:((c==1)?W2:W3);
        const float* wih = (c==0)?wih1:((c==1)?wih2:wih3);
        const float* whh = (c==0)?whh1:((c==1)?whh2:whh3);
        int gi = row / 48, rloc = row - gi*48;
        int nbase = (gi == 0) ? 0 : (gi == 1) ? 96 : ((chunk < 6) ? 192 : 288);
        int n = nbase + p*48 + rloc;
        int khalf = (wk >> 2) ^ ((row >> 2) & 1);
        int k = chunk*16 + (khalf*4 + (wk & 3))*2;
        float v0 = wval(W, wih, whh, l, k, n);
        float v1 = wval(W, wih, whh, l, k+1, n);
        unsigned hi, lo;
        pack2(v0, v1, hi, lo);
        g_Wp[(size_t)gid] = plane ? lo : hi;
    } else {
        int id = (bid - MEGA_IB - MEGA_PB)*256 + tid;
        if (id < 18*384){
            int cl = id / 384;
            int j = id - cl*384;
            int c = cl / 6;
            const float* bih = (c==0)?bih1:((c==1)?bih2:bih3);
            const float* bhh = (c==0)?bhh1:((c==1)?bhh2:bhh3);
            float v;
            if (j < 192)      v = bih[j] + bhh[j];
            else if (j < 288) v = bih[192 + (j-192)];
            else              v = bhh[192 + (j-288)];
            g_bias[cl*384 + j] = v;
        }
    }
}

// ---------------- CSR build -------------------------------------------------
__global__ void k_deg(const int* __restrict__ e1, const int* __restrict__ e2,
                      const int* __restrict__ e3){
    int e = blockIdx.x*blockDim.x + threadIdx.x;
    if (e >= EE) return;
    int c = e / EC, le = e - c*EC;
    const int* ei = (c==0)?e1:((c==1)?e2:e3);
    atomicAdd(&g_deg[c*NC + ei[EC + le]], 1);
}

__global__ void k_scan1(){
    __shared__ int sm[SCAN_BLK];
    int tid = threadIdx.x;
    int i = blockIdx.x*SCAN_BLK + tid;
    int v = (i < NN) ? g_deg[i] : 0;
    sm[tid] = v;
    __syncthreads();
    for (int off = 1; off < SCAN_BLK; off <<= 1){
        int t = 0;
        if (tid >= off) t = sm[tid - off];
        __syncthreads();
        sm[tid] += t;
        __syncthreads();
    }
    if (i < NN) g_off[i] = sm[tid] - v;
    if (tid == SCAN_BLK-1) g_part[blockIdx.x] = sm[tid];
}

__global__ void k_scan2(){
    __shared__ int sm[SCAN_BLK];
    int tid = threadIdx.x;
    int v = (tid < NPART) ? g_part[tid] : 0;
    sm[tid] = v;
    __syncthreads();
    for (int off = 1; off < SCAN_BLK; off <<= 1){
        int t = 0;
        if (tid >= off) t = sm[tid - off];
        __syncthreads();
        sm[tid] += t;
        __syncthreads();
    }
    if (tid < NPART) g_part[tid] = sm[tid] - v;
}

__global__ void k_fill(const int* __restrict__ e1, const int* __restrict__ e2,
                       const int* __restrict__ e3){
    int e = blockIdx.x*blockDim.x + threadIdx.x;
    if (e >= EE) return;
    int c = e / EC, le = e - c*EC;
    const int* ei = (c==0)?e1:((c==1)?e2:e3);
    int dst = ei[EC + le];
    int src = ei[le];
    int dg = c*NC + dst;
    int p = g_off[dg] + g_part[dg >> 10] + atomicAdd(&g_fill[dg], 1);
    g_esrc[p] = c*NC + src;
}

// ---------------- fused GRU layer: gather + mma.sync(ldmatrix) + gates -------
// 64 rows/block, 256 threads (8 warps = 4M x 2N), 2 CTAs/SM.
// W: two 3-chunk (27648 B) cp.async buffers, ping-pong, fills overlapped.
// Gather: wave-parallel edge processing (MLP ~8-16 instead of serial).
#define BIAS_OFF 0            // 1536 B
#define A_HI_OFF 1536         // 64 rows x 400 B = 25600
#define A_LO_OFF 27136
#define W_OFF    52736        // 2 bufs x 27648 B
#define W_BUF    27648
#define SMEM_GRU_TOTAL 108032

__device__ __forceinline__ void fill3(uint32_t smW, const unsigned* gsrc, int tid){
    #pragma unroll
    for (int q = 0; q < 7; q++){
        int idx = tid + 256*q;
        if (idx < 1728){
            CP_ASYNC16(smW + idx*16, (const void*)(gsrc + idx*4));
        }
    }
    CP_COMMIT();
}

template<int G2>
__device__ __forceinline__ void gru_chunk(uint32_t wchunk, uint32_t a_h, uint32_t a_l,
                                          int kglob, uint32_t b4off, uint32_t bt2off,
                                          uint32_t bx2off, float (&acc)[4][3][4]){
    unsigned afh[4], afl[4];
    LDSM_X4(afh[0], afh[1], afh[2], afh[3], a_h + kglob*32);
    LDSM_X4(afl[0], afl[1], afl[2], afl[3], a_l + kglob*32);
    #pragma unroll
    for (int plane = 0; plane < 2; plane++){
        uint32_t pb = wchunk + plane*4608;
        unsigned b[3][6];
        LDSM_X4(b[0][0], b[0][1], b[0][2], b[0][3], pb + b4off);
        LDSM_X4(b[1][0], b[1][1], b[1][2], b[1][3], pb + 1536 + b4off);
        LDSM_X4(b[2][0], b[2][1], b[2][2], b[2][3], pb + 3072 + b4off);
        LDSM_X4(b[0][4], b[0][5], b[1][4], b[1][5], pb + bt2off);
        LDSM_X2(b[2][4], b[2][5], pb + bx2off);
        #pragma unroll
        for (int gi = 0; gi < 3; gi++){
            const int ga = (gi < 2) ? gi : G2;
            #pragma unroll
            for (int t = 0; t < 3; t++){
                mma16816(acc[ga][t], afh, b[gi][2*t], b[gi][2*t+1]);
                if (plane == 0) mma16816(acc[ga][t], afl, b[gi][2*t], b[gi][2*t+1]);
            }
        }
    }
}

template<int G2>
__device__ __forceinline__ void compute3(uint32_t wbuf, uint32_t a_h, uint32_t a_l,
                                         int kbase, uint32_t b4off, uint32_t bt2off,
                                         uint32_t bx2off, float (&acc)[4][3][4]){
    #pragma unroll
    for (int c = 0; c < 3; c++)
        gru_chunk<G2>(wbuf + c*9216, a_h, a_l, kbase + c, b4off, bt2off, bx2off, acc);
}

__device__ __forceinline__ void gru_epilogue(
    int p, float (&acc)[4][3][4], const float* sb,
    const unsigned* Ahw, const unsigned* Alw, float* hout,
    int comp, int row0, int wm, int wn, int lr, int lq)
{
    #pragma unroll
    for (int t = 0; t < 3; t++){
        int f0 = p*48 + wn*24 + t*8 + 2*lq;
        float bR0 = sb[f0],       bR1 = sb[f0+1];
        float bZ0 = sb[96+f0],    bZ1 = sb[96+f0+1];
        float bI0 = sb[192+f0],   bI1 = sb[192+f0+1];
        float bN0 = sb[288+f0],   bN1 = sb[288+f0+1];
        #pragma unroll
        for (int half = 0; half < 2; half++){
            int row = wm*16 + lr + half*8;
            size_t base = (size_t)(comp*NC + row0 + row)*96;
            int wofs = row*100 + 48 + (f0 >> 1);
            unsigned hw = Ahw[wofs], lw = Alw[wofs];
            float hx = bflo(hw) + bflo(lw);
            float hy = bfhi(hw) + bfhi(lw);
            int ci = half*2;
            float xr0 = fminf(fmaxf((acc[0][t][ci]   + bR0)*L2E, -30.f), 30.f);
            float xr1 = fminf(fmaxf((acc[0][t][ci+1] + bR1)*L2E, -30.f), 30.f);
            float xz0 = fminf(fmaxf((acc[1][t][ci]   + bZ0)*L2E, -30.f), 30.f);
            float xz1 = fminf(fmaxf((acc[1][t][ci+1] + bZ1)*L2E, -30.f), 30.f);
            float er0 = ex2f(xr0), er1 = ex2f(xr1);
            float ez0 = ex2f(xz0), ez1 = ex2f(xz1);
            float d1 = er0 + 1.f, d2 = ez0 + 1.f, d3 = er1 + 1.f, d4 = ez1 + 1.f;
            float p12 = d1*d2, p34 = d3*d4;
            float rp = rcpf(p12*p34);
            float q12 = rp*p34, q34 = rp*p12;
            float rr0 = er0*(q12*d2), zz0 = ez0*(q12*d1);
            float rr1 = er1*(q34*d4), zz1 = ez1*(q34*d3);
            float t0 = fmaf(rr0, acc[3][t][ci]   + bN0, acc[2][t][ci]   + bI0);
            float t1 = fmaf(rr1, acc[3][t][ci+1] + bN1, acc[2][t][ci+1] + bI1);
            float lt0 = fminf(fmaxf(t0*(2.f*L2E), -30.f), 30.f);
            float lt1 = fminf(fmaxf(t1*(2.f*L2E), -30.f), 30.f);
            float e0 = ex2f(lt0), e1 = ex2f(lt1);
            float dt0 = e0 + 1.f, dt1 = e1 + 1.f;
            float rpt = rcpf(dt0*dt1);
            float nn0 = fmaf(-2.f, rpt*dt1, 1.f);
            float nn1 = fmaf(-2.f, rpt*dt0, 1.f);
            float o0 = fmaf(zz0, hx - nn0, nn0);
            float o1 = fmaf(zz1, hy - nn1, nn1);
            *(float2*)(hout + base + f0) = make_float2(o0, o1);
        }
    }
}

template<int WARM>
__global__ void __launch_bounds__(256, 2) k_gru(int layer){
    extern __shared__ char smc[];
    const uint32_t smb = smem_u32(smc);
    float* sb = (float*)(smc + BIAS_OFF);

    const int comp = blockIdx.y;
    const int cl = comp*6 + layer;
    const int row0 = blockIdx.x*64;
    const int tid = threadIdx.x;
    const int lane = tid & 31;
    const int wid = tid >> 5;
    const int wm = wid & 3;          // rows wm*16..+15
    const int wn = wid >> 2;         // 0..1
    const int lr = lane >> 2;        // 0..7
    const int lq = lane & 3;         // 0..3

    const unsigned* wsrc = g_Wp + (size_t)cl*55296;
    const uint32_t w0 = smb + W_OFF;
    const uint32_t w1 = w0 + W_BUF;

    // kick off W fills (overlap the gather)
    fill3(w0, wsrc, tid);
    fill3(w1, wsrc + 3*2304, tid);

    for (int i = tid; i < 384; i += 256) sb[i] = g_bias[cl*384 + i];

    const float* hin  = WARM ? g_h : ((layer & 1) ? g_s : g_h);
    float*       hout = WARM ? g_s : ((layer & 1) ? g_h : g_s);

    // ---- wave-parallel gather + stage A (bf16 hi/lo, 100-word stride) ----
    {
        unsigned* Ahw2 = (unsigned*)(smc + A_HI_OFF);
        unsigned* Alw2 = (unsigned*)(smc + A_LO_OFF);
        const int nd = comp*NC + row0 + wid*8;
        float2 s0[8], s1[8];
        #pragma unroll
        for (int r = 0; r < 8; r++){ s0[r] = make_float2(0.f,0.f); s1[r] = make_float2(0.f,0.f); }
        if (!WARM){
            int beg[8], end8[8];
            #pragma unroll
            for (int r = 0; r < 8; r++){
                int node = nd + r;
                beg[r] = __ldg(&g_off[node]) + __ldg(&g_part[node >> 10]);
            }
            #pragma unroll
            for (int r = 0; r < 8; r++){
                int n1 = nd + r + 1;
                end8[r] = (n1 == NN) ? EE : (__ldg(&g_off[n1]) + __ldg(&g_part[n1 >> 10]));
            }
            int md = 0;
            #pragma unroll
            for (int r = 0; r < 8; r++) md = max(md, end8[r] - beg[r]);
            for (int j = 0; j < md; j++){
                int sidx[8];
                #pragma unroll
                for (int r = 0; r < 8; r++)
                    sidx[r] = (j < end8[r] - beg[r]) ? __ldg(&g_esrc[beg[r] + j]) : -1;
                #pragma unroll
                for (int r = 0; r < 8; r++){
                    if (sidx[r] >= 0){
                        const float2* hp = (const float2*)(hin + (size_t)sidx[r]*96);
                        float2 v = __ldg(hp + lane);
                        s0[r].x += v.x; s0[r].y += v.y;
                        if (lane < 16){
                            float2 v1 = __ldg(hp + 32 + lane);
                            s1[r].x += v1.x; s1[r].y += v1.y;
                        }
                    }
                }
            }
        }
        // batch h-row loads (all independent)
        float2 h0v[8], h1v[8];
        #pragma unroll
        for (int r = 0; r < 8; r++){
            const float2* hr = (const float2*)(hin + (size_t)(nd + r)*96);
            h0v[r] = __ldg(hr + lane);
            if (lane < 16) h1v[r] = __ldg(hr + 32 + lane);
        }
        #pragma unroll
        for (int r = 0; r < 8; r++){
            int row = wid*8 + r;
            int wb = row*100;
            unsigned hi, lo;
            pack2(s0[r].x, s0[r].y, hi, lo);
            Ahw2[wb + lane] = hi;  Alw2[wb + lane] = lo;
            pack2(h0v[r].x, h0v[r].y, hi, lo);
            Ahw2[wb + 48 + lane] = hi;  Alw2[wb + 48 + lane] = lo;
            if (lane < 16){
                pack2(s1[r].x, s1[r].y, hi, lo);
                Ahw2[wb + 32 + lane] = hi;  Alw2[wb + 32 + lane] = lo;
                pack2(h1v[r].x, h1v[r].y, hi, lo);
                Ahw2[wb + 80 + lane] = hi;  Alw2[wb + 80 + lane] = lo;
            }
        }
    }

    // per-warp ldmatrix addresses
    const uint32_t a_h = smb + A_HI_OFF +
        ((wm*16 + (lane & 15))*100 + ((lane >> 4) << 2))*4;
    const uint32_t a_l = a_h + (A_LO_OFF - A_HI_OFF);
    const int hsel = (lane >> 3) & 1;
    const uint32_t b4off  = wn*768 + swzoff(((lane >> 4) << 3) + (lane & 7), hsel);
    const uint32_t bt2off = (lane >> 4)*1536 + wn*768 + swzoff(16 + (lane & 7), hsel);
    const uint32_t bx2off = 3072 + wn*768 + swzoff(16 + (lane & 7), hsel);

    const unsigned* Ahw = (const unsigned*)(smc + A_HI_OFF);
    const unsigned* Alw = (const unsigned*)(smc + A_LO_OFF);

    // boundary: all-done-X barrier, refill X, ensure Y ready+visible
    #define BOUNDARY(bufaddr, srcoff) do { \
        __syncthreads(); \
        fill3(bufaddr, wsrc + (srcoff)*2304, tid); \
        CP_WAITG(1); \
        __syncthreads(); \
    } while(0)

    float acc[4][3][4];
    #pragma unroll
    for (int g = 0; g < 4; g++)
        #pragma unroll
        for (int t = 0; t < 3; t++)
            #pragma unroll
            for (int i = 0; i < 4; i++) acc[g][t][i] = 0.f;

    CP_WAITG(1);
    __syncthreads();   // A staged + W0 ready

    compute3<2>(w0, a_h, a_l, 0, b4off, bt2off, bx2off, acc);
    BOUNDARY(w0, 6);
    compute3<2>(w1, a_h, a_l, 3, b4off, bt2off, bx2off, acc);
    BOUNDARY(w1, 9);
    compute3<3>(w0, a_h, a_l, 6, b4off, bt2off, bx2off, acc);
    BOUNDARY(w0, 12);
    compute3<3>(w1, a_h, a_l, 9, b4off, bt2off, bx2off, acc);
    BOUNDARY(w1, 15);
    gru_epilogue(0, acc, sb, Ahw, Alw, hout, comp, row0, wm, wn, lr, lq);

    #pragma unroll
    for (int g = 0; g < 4; g++)
        #pragma unroll
        for (int t = 0; t < 3; t++)
            #pragma unroll
            for (int i = 0; i < 4; i++) acc[g][t][i] = 0.f;

    compute3<2>(w0, a_h, a_l, 0, b4off, bt2off, bx2off, acc);
    BOUNDARY(w0, 18);
    compute3<2>(w1, a_h, a_l, 3, b4off, bt2off, bx2off, acc);
    BOUNDARY(w1, 21);
    compute3<3>(w0, a_h, a_l, 6, b4off, bt2off, bx2off, acc);
    __syncthreads();
    CP_WAITG(0);
    __syncthreads();
    compute3<3>(w1, a_h, a_l, 9, b4off, bt2off, bx2off, acc);
    gru_epilogue(1, acc, sb, Ahw, Alw, hout, comp, row0, wm, wn, lr, lq);
    #undef BOUNDARY
}

// ---------------- pooling: mean of relu(h) over sorted batch ranges ---------
__global__ void k_pool(const int* __restrict__ b1, const int* __restrict__ b2,
                       const int* __restrict__ b3){
    int b = blockIdx.x;
    int c = blockIdx.y;
    const int* batch = (c==0)?b1:((c==1)?b2:b3);
    int lo = 0, hi = NC;
    while (lo < hi){ int m = (lo+hi) >> 1; if (batch[m] < b) lo = m+1; else hi = m; }
    int s0 = lo;
    hi = NC;
    while (lo < hi){ int m = (lo+hi) >> 1; if (batch[m] < b+1) lo = m+1; else hi = m; }
    int e0 = lo;
    float denom = fmaxf((float)(e0 - s0), 1.f);
    int f = threadIdx.x;
    float sum = 0.f;
    for (int n = s0; n < e0; n++)
        sum += fmaxf(g_h[(size_t)(c*NC + n)*HD + f], 0.f);
    g_pool[((size_t)c*NB + b)*HD + f] = sum / denom;
}

// ---------------- feature assembly ------------------------------------------
__global__ void k_feat(){
    int idx = blockIdx.x*blockDim.x + threadIdx.x;
    if (idx >= NB*384) return;
    int b = idx / 384;
    int j = idx - b*384;
    float v;
    if (j < 96)       v = g_pool[(size_t)b*HD + j];
    else if (j < 192) v = g_pool[((size_t)NB + b)*HD + (j-96)];
    else if (j < 288) v = g_pool[((size_t)2*NB + b)*HD + (j-192)];
    else {
        int jj = j - 288;
        v = g_pool[(size_t)b*HD + jj]
          * g_pool[((size_t)NB + b)*HD + jj]
          * g_pool[((size_t)2*NB + b)*HD + jj];
    }
    g_feat[idx] = v;
}

// ---------------- MLP GEMM (f32x2 FFMA2, globals resolved in device code) ---
template<int MODE>
__global__ void __launch_bounds__(256) k_gemm(const float* __restrict__ B,
                                              const float* __restrict__ bias){
    const float* A = (MODE == 0) ? g_feat : g_t1;
    float*       C = (MODE == 0) ? g_t1   : g_t2;
    const int N = (MODE == 0) ? 1536 : 384;
    const int K = (MODE == 0) ? 384  : 1536;

    __shared__ float As[64*33];
    __shared__ __align__(16) float Bs[32*68];
    int txx = threadIdx.x & 15;
    int tyy = threadIdx.x >> 4;
    int m0 = blockIdx.y*64;
    int n0 = blockIdx.x*64;
    unsigned long long acc2[4][2];
    #pragma unroll
    for (int i = 0; i < 4; i++){ acc2[i][0] = 0ull; acc2[i][1] = 0ull; }

    for (int kc = 0; kc < K; kc += 32){
        __syncthreads();
        for (int i = threadIdx.x; i < 64*32; i += 256){
            int r = i >> 5, k = i & 31;
            As[r*33 + k] = A[(size_t)(m0 + r)*K + kc + k];
        }
        for (int i = threadIdx.x; i < 32*64; i += 256){
            int k = i >> 6, cc = i & 63;
            Bs[k*68 + cc] = B[(size_t)(kc + k)*N + n0 + cc];
        }
        __syncthreads();
        #pragma unroll 8
        for (int k = 0; k < 32; k++){
            unsigned long long b0 = *(const unsigned long long*)&Bs[k*68 + txx*4];
            unsigned long long b1 = *(const unsigned long long*)&Bs[k*68 + txx*4 + 2];
            #pragma unroll
            for (int i = 0; i < 4; i++){
                unsigned long long ai = dup2(As[(tyy*4 + i)*33 + k]);
                acc2[i][0] = ffma2(ai, b0, acc2[i][0]);
                acc2[i][1] = ffma2(ai, b1, acc2[i][1]);
            }
        }
    }
    #pragma unroll
    for (int i = 0; i < 4; i++){
        int row = m0 + tyy*4 + i;
        #pragma unroll
        for (int j2 = 0; j2 < 2; j2++){
            float2 v = unpk2(acc2[i][j2]);
            int col = n0 + txx*4 + j2*2;
            C[(size_t)row*N + col]     = fmaxf(v.x + bias[col], 0.f);
            C[(size_t)row*N + col + 1] = fmaxf(v.y + bias[col+1], 0.f);
        }
    }
}

// ---------------- fc3: [4096,384] @ [384,3] ---------------------------------
__global__ void k_fc3(const float* __restrict__ w, const float* __restrict__ b,
                      float* __restrict__ out){
    int gt = blockIdx.x*blockDim.x + threadIdx.x;
    int row = gt >> 5;
    int lane = gt & 31;
    if (row >= NB) return;
    float a0 = 0.f, a1 = 0.f, a2 = 0.f;
    for (int k = lane; k < 384; k += 32){
        float f = g_t2[(size_t)row*384 + k];
        a0 += f*w[k*3 + 0];
        a1 += f*w[k*3 + 1];
        a2 += f*w[k*3 + 2];
    }
    #pragma unroll
    for (int o = 16; o; o >>= 1){
        a0 += __shfl_down_sync(0xffffffffu, a0, o);
        a1 += __shfl_down_sync(0xffffffffu, a1, o);
        a2 += __shfl_down_sync(0xffffffffu, a2, o);
    }
    if (lane == 0){
        out[row*3 + 0] = a0 + b[0];
        out[row*3 + 1] = a1 + b[1];
        out[row*3 + 2] = a2 + b[2];
    }
}

// ---------------- launch ----------------------------------------------------
extern "C" void kernel_launch(void* const* d_in, const int* in_sizes, int n_in,
                              void* d_out, int out_size) {
    const float* xs[3]   = {0,0,0};
    const int*   es[3]   = {0,0,0};
    const int*   bs[3]   = {0,0,0};
    const float* Ws[3]   = {0,0,0};
    const float* wihs[3] = {0,0,0};
    const float* whhs[3] = {0,0,0};
    const float* bihs[3] = {0,0,0};
    const float* bhhs[3] = {0,0,0};
    const float* fcw[2]  = {0,0};
    const float* fc1b = 0; const float* fc2b = 0;
    const float* fc3w = 0; const float* fc3b = 0;
    int nx=0, ne=0, nb=0, nW=0, nwpair=0, nbpair=0, nfcw=0;
    for (int i = 0; i < n_in; i++){
        int s = in_sizes[i];
        const void* p = d_in[i];
        switch (s){
            case 6400000: if (nx < 3) xs[nx++] = (const float*)p; break;
            case 800000:  if (ne < 3) es[ne++] = (const int*)p;   break;
            case 200000:  if (nb < 3) bs[nb++] = (const int*)p;   break;
            case 55296:   if (nW < 3) Ws[nW++] = (const float*)p; break;
            case 27648:   { int c = nwpair/2;
                            if (c < 3){ if ((nwpair & 1) == 0) wihs[c] = (const float*)p;
                                        else                   whhs[c] = (const float*)p; }
                            nwpair++; } break;
            case 288:     { int c = nbpair/2;
                            if (c < 3){ if ((nbpair & 1) == 0) bihs[c] = (const float*)p;
                                        else                   bhhs[c] = (const float*)p; }
                            nbpair++; } break;
            case 589824:  if (nfcw < 2) fcw[nfcw++] = (const float*)p; break;
            case 1536:    fc1b = (const float*)p; break;
            case 384:     fc2b = (const float*)p; break;
            case 1152:    fc3w = (const float*)p; break;
            case 3:       fc3b = (const float*)p; break;
            default: break;
        }
    }
    const float* fc1w = fcw[0];
    const float* fc2w = fcw[1];
    float* out = (float*)d_out;

    cudaFuncSetAttribute(k_gru<0>, cudaFuncAttributeMaxDynamicSharedMemorySize, SMEM_GRU_TOTAL);
    cudaFuncSetAttribute(k_gru<1>, cudaFuncAttributeMaxDynamicSharedMemorySize, SMEM_GRU_TOTAL);

    // 1: mega init (h0 + counters + W prepack + bias pack)
    k_mega<<<MEGA_IB + MEGA_PB + MEGA_BB, 256>>>(
        xs[0], xs[1], xs[2],
        Ws[0], wihs[0], whhs[0], Ws[1], wihs[1], whhs[1], Ws[2], wihs[2], whhs[2],
        bihs[0], bhhs[0], bihs[1], bhhs[1], bihs[2], bhhs[2]);
    // 2-3: CSR histogram + block scan
    k_deg<<<(EE + 255)/256, 256>>>(es[0], es[1], es[2]);
    k_scan1<<<NPART, SCAN_BLK>>>();
    // 4: telemetry warmup GRU (no gather; writes g_s, overwritten by layer 0)
    k_gru<1><<<dim3(200, 3), 256, SMEM_GRU_TOTAL>>>(0);
    // 5-6: finish CSR
    k_scan2<<<1, SCAN_BLK>>>();
    k_fill<<<(EE + 255)/256, 256>>>(es[0], es[1], es[2]);

    const int gruBlocks = NC/64;   // 3125
    for (int l = 0; l < 6; l++)
        k_gru<0><<<dim3(gruBlocks, 3), 256, SMEM_GRU_TOTAL>>>(l);

    k_pool<<<dim3(NB, 3), 96>>>(bs[0], bs[1], bs[2]);
    k_feat<<<(NB*384 + 255)/256, 256>>>();
    k_gemm<0><<<dim3(1536/64, NB/64), 256>>>(fc1w, fc1b);
    k_gemm<1><<<dim3(384/64,  NB/64), 256>>>(fc2w, fc2b);
    k_fc3<<<(NB*32 + 255)/256, 256>>>(fc3w, fc3b, out);
}